// round 3
// baseline (speedup 1.0000x reference)
#include <cuda_runtime.h>
#include <math.h>
#include <float.h>

#define NPTS   8192
#define NDOWN  2048
#define KNN    16
#define CHUNKS 16

// ----------------------------------------------------------------------------
// Scratch arenas (no cudaMalloc allowed).
// ----------------------------------------------------------------------------
__device__ float g_f[40200000];
__device__ int   g_i[2400000];

static const size_t O_A1  = 0;
static const size_t O_B1  = O_A1  + (size_t)8192*64;
static const size_t O_X1  = O_B1  + (size_t)8192*64;
static const size_t O_A2  = O_X1  + (size_t)8192*64;
static const size_t O_B2  = O_A2  + (size_t)8192*128;
static const size_t O_X2  = O_B2  + (size_t)8192*128;
static const size_t O_Q1  = O_X2  + (size_t)8192*128;
static const size_t O_K1  = O_Q1  + (size_t)8192*256;
static const size_t O_V1  = O_K1  + (size_t)8192*256;
static const size_t O_X3  = O_V1  + (size_t)8192*256;
static const size_t O_Q2  = O_X3  + (size_t)8192*256;
static const size_t O_K2  = O_Q2  + (size_t)8192*512;
static const size_t O_V2  = O_K2  + (size_t)8192*512;
static const size_t O_X4  = O_V2  + (size_t)8192*512;
static const size_t O_PX  = O_X4  + (size_t)8192*512;
static const size_t O_PM  = O_PX  + (size_t)8192*512;
static const size_t O_XD  = O_PM  + (size_t)2048*512;
static const size_t O_XU  = O_XD  + (size_t)2048*512;
static const size_t O_H   = O_XU  + (size_t)2048*256;
static const size_t O_GS  = O_H   + (size_t)2048*128;
static const size_t O_BE  = O_GS  + 512;
static const size_t O_B2E = O_BE  + 256;
static const size_t O_WD1 = O_B2E + 128;
static const size_t O_WD2 = O_WD1 + 192;
static const size_t O_P4  = O_WD2 + 8192;
static const size_t O_S1D = O_P4  + (size_t)8192*4;      // 8192*256 floats

static const size_t OI_IDX  = 0;                          // 8192*16
static const size_t OI_IDXD = (size_t)8192*16;            // 2048*16
static const size_t OI_S1I  = OI_IDXD + (size_t)2048*16;  // 8192*256

// ----------------------------------------------------------------------------
// f32x2 helpers
// ----------------------------------------------------------------------------
typedef unsigned long long ull;

__device__ __forceinline__ ull pk2(float lo, float hi) {
    ull r; asm("mov.b64 %0,{%1,%2};" : "=l"(r) : "f"(lo), "f"(hi)); return r;
}
__device__ __forceinline__ ull fma2(ull a, ull b, ull c) {
    ull d; asm("fma.rn.f32x2 %0,%1,%2,%3;" : "=l"(d) : "l"(a), "l"(b), "l"(c)); return d;
}
__device__ __forceinline__ void upk2(ull v, float& lo, float& hi) {
    asm("mov.b64 {%0,%1},%2;" : "=f"(lo), "=f"(hi) : "l"(v));
}

// ----------------------------------------------------------------------------
// kNN
// ----------------------------------------------------------------------------
__device__ __forceinline__ void replace_rescan(float s, int j, float (&d)[KNN], int (&id)[KNN],
                                               float& wval, int& wpos) {
#pragma unroll
    for (int t = 0; t < KNN; ++t) if (t == wpos) { d[t] = s; id[t] = j; }
    wval = d[0]; wpos = 0;
#pragma unroll
    for (int t = 1; t < KNN; ++t) if (d[t] > wval) { wval = d[t]; wpos = t; }
}

__global__ void prep_p4_kernel(const float* __restrict__ p, float4* __restrict__ p4) {
    int i = blockIdx.x * blockDim.x + threadIdx.x;
    if (i < NPTS) {
        float x = p[3 * i], y = p[3 * i + 1], z = p[3 * i + 2];
        p4[i] = make_float4(x, y, z, x * x + y * y + z * z);
    }
}

// grid (nq/128, CHUNKS), block 128. One 512-candidate tile per chunk.
__global__ void knn_stage1_kernel(const float4* __restrict__ p4, int qstride,
                                  float* __restrict__ s1d, int* __restrict__ s1i) {
    const int CH = NPTS / CHUNKS;  // 512
    int q  = blockIdx.x * blockDim.x + threadIdx.x;
    int c0 = blockIdx.y * CH;

    float4 qp = p4[q * qstride];
    float qx = -2.f * qp.x, qy = -2.f * qp.y, qz = -2.f * qp.z;

    __shared__ float4 tile[512];
#pragma unroll
    for (int l = 0; l < 4; ++l) tile[threadIdx.x + l * 128] = p4[c0 + threadIdx.x + l * 128];
    __syncthreads();

    float d[KNN]; int id[KNN];
#pragma unroll
    for (int t = 0; t < KNN; ++t) {
        float4 c = tile[t];
        d[t] = fmaf(qx, c.x, fmaf(qy, c.y, fmaf(qz, c.z, c.w)));
        id[t] = c0 + t;
    }
    float wval = d[0]; int wpos = 0;
#pragma unroll
    for (int t = 1; t < KNN; ++t) if (d[t] > wval) { wval = d[t]; wpos = t; }

    float bs0 = 0.f, bs1 = 0.f, bs2 = 0.f, bs3 = 0.f;
    int   bj0 = 0, bj1 = 0, bj2 = 0, bj3 = 0, cnt = 0;

    for (int i = KNN; i < CH; ++i) {
        float4 c = tile[i];
        float s = fmaf(qx, c.x, fmaf(qy, c.y, fmaf(qz, c.z, c.w)));
        if (s < wval) {
            int j = c0 + i;
            if (cnt == 0)      { bs0 = s; bj0 = j; }
            else if (cnt == 1) { bs1 = s; bj1 = j; }
            else if (cnt == 2) { bs2 = s; bj2 = j; }
            else               { bs3 = s; bj3 = j; }
            cnt++;
        }
        if (__any_sync(0xffffffffu, cnt == 4)) {
            if (cnt > 0 && bs0 < wval) replace_rescan(bs0, bj0, d, id, wval, wpos);
            if (cnt > 1 && bs1 < wval) replace_rescan(bs1, bj1, d, id, wval, wpos);
            if (cnt > 2 && bs2 < wval) replace_rescan(bs2, bj2, d, id, wval, wpos);
            if (cnt > 3 && bs3 < wval) replace_rescan(bs3, bj3, d, id, wval, wpos);
            cnt = 0;
        }
    }
    if (cnt > 0 && bs0 < wval) replace_rescan(bs0, bj0, d, id, wval, wpos);
    if (cnt > 1 && bs1 < wval) replace_rescan(bs1, bj1, d, id, wval, wpos);
    if (cnt > 2 && bs2 < wval) replace_rescan(bs2, bj2, d, id, wval, wpos);
    if (cnt > 3 && bs3 < wval) replace_rescan(bs3, bj3, d, id, wval, wpos);

    size_t o = ((size_t)q * CHUNKS + blockIdx.y) * KNN;
#pragma unroll
    for (int t = 0; t < KNN; ++t) { s1d[o + t] = d[t]; s1i[o + t] = id[t]; }
}

__global__ void knn_stage2_kernel(const float* __restrict__ s1d, const int* __restrict__ s1i,
                                  int nq, int* __restrict__ outidx) {
    int q = blockIdx.x * blockDim.x + threadIdx.x;
    if (q >= nq) return;
    size_t base = (size_t)q * (CHUNKS * KNN);
    float d[KNN]; int id[KNN];
#pragma unroll
    for (int t = 0; t < KNN; ++t) { d[t] = s1d[base + t]; id[t] = s1i[base + t]; }
    float wval = d[0]; int wpos = 0;
#pragma unroll
    for (int t = 1; t < KNN; ++t) if (d[t] > wval) { wval = d[t]; wpos = t; }
    for (int c = KNN; c < CHUNKS * KNN; ++c) {
        float s = s1d[base + c];
        if (s < wval) replace_rescan(s, s1i[base + c], d, id, wval, wpos);
    }
#pragma unroll
    for (int t = 0; t < KNN; ++t) outidx[q * KNN + t] = id[t];
}

// ----------------------------------------------------------------------------
// Batched GEMM: C[M,N] = A[M,K] @ B[K,N]; B/C selected by blockIdx.z.
// MODE 0: store. MODE 2: C = relu(acc*s + b) per-col.
// MODE 3: C = acc + px*W3[0,c] + py*W3[1,c] + pz*W3[2,c]  (row ld = ldc)
// ----------------------------------------------------------------------------
template <int BM, int BN, int MODE>
__global__ __launch_bounds__(256)
void gemm_kernel(const float* __restrict__ A, int lda,
                 const float* __restrict__ Bp0, const float* __restrict__ Bp1,
                 const float* __restrict__ Bp2, int ldb,
                 float* __restrict__ Cp0, float* __restrict__ Cp1,
                 float* __restrict__ Cp2, int ldc, int K,
                 const float* __restrict__ scv, const float* __restrict__ biv,
                 const float4* __restrict__ p4r, int rstride,
                 const float* __restrict__ W3) {
    constexpr int TM = BM / 16;
    constexpr int TN = BN / 16;
    constexpr int RP = TM / 2;
    constexpr int NA = BM / 64;
    constexpr int NB = BN / 64;
    constexpr int F4R = BN / 4;
    constexpr int BROW = 256 / F4R;

    __shared__ __align__(16) float As[16][BM + 4];
    __shared__ __align__(16) float Bs[16][BN];

    const float* B = (blockIdx.z == 0) ? Bp0 : (blockIdx.z == 1) ? Bp1 : Bp2;
    float*       C = (blockIdx.z == 0) ? Cp0 : (blockIdx.z == 1) ? Cp1 : Cp2;

    int tid = threadIdx.x;
    int bm = blockIdx.y * BM, bn = blockIdx.x * BN;

    int ar = tid >> 2, ac4 = tid & 3;
    int bk = tid / F4R, bc = tid % F4R;

    const float* Ap = A + (size_t)(bm + ar) * lda + ac4 * 4;
    const float* Bq = B + (size_t)bk * ldb + bn + bc * 4;

    float4 pa[NA], pb[NB];
#pragma unroll
    for (int l = 0; l < NA; ++l) pa[l] = *(const float4*)(Ap + (size_t)(64 * l) * lda);
#pragma unroll
    for (int l = 0; l < NB; ++l) pb[l] = *(const float4*)(Bq + (size_t)(BROW * l) * ldb);
    Ap += 16;
    Bq += (size_t)16 * ldb;

    int tr = (tid >> 4) * TM;
    int tc = (tid & 15) * TN;

    ull acc[RP][TN];
#pragma unroll
    for (int rp = 0; rp < RP; ++rp)
#pragma unroll
        for (int c = 0; c < TN; ++c) acc[rp][c] = 0ull;

    int ktiles = K >> 4;
    for (int t = 0; t < ktiles; ++t) {
#pragma unroll
        for (int l = 0; l < NA; ++l) {
            int r = ar + 64 * l;
            As[ac4 * 4 + 0][r] = pa[l].x;
            As[ac4 * 4 + 1][r] = pa[l].y;
            As[ac4 * 4 + 2][r] = pa[l].z;
            As[ac4 * 4 + 3][r] = pa[l].w;
        }
#pragma unroll
        for (int l = 0; l < NB; ++l)
            *(float4*)&Bs[bk + BROW * l][bc * 4] = pb[l];
        __syncthreads();

        if (t + 1 < ktiles) {
#pragma unroll
            for (int l = 0; l < NA; ++l) pa[l] = *(const float4*)(Ap + (size_t)(64 * l) * lda);
#pragma unroll
            for (int l = 0; l < NB; ++l) pb[l] = *(const float4*)(Bq + (size_t)(BROW * l) * ldb);
            Ap += 16;
            Bq += (size_t)16 * ldb;
        }

#pragma unroll
        for (int k = 0; k < 16; ++k) {
            float4 av[TM / 4], bv[TN / 4];
#pragma unroll
            for (int v = 0; v < TM / 4; ++v) av[v] = *(const float4*)&As[k][tr + 4 * v];
#pragma unroll
            for (int v = 0; v < TN / 4; ++v) bv[v] = *(const float4*)&Bs[k][tc + 4 * v];
            ull apk[RP];
#pragma unroll
            for (int v = 0; v < TM / 4; ++v) {
                apk[2 * v + 0] = pk2(av[v].x, av[v].y);
                apk[2 * v + 1] = pk2(av[v].z, av[v].w);
            }
#pragma unroll
            for (int v = 0; v < TN / 4; ++v) {
                {
                    ull bb = pk2(bv[v].x, bv[v].x);
#pragma unroll
                    for (int rp = 0; rp < RP; ++rp) acc[rp][4 * v + 0] = fma2(apk[rp], bb, acc[rp][4 * v + 0]);
                }
                {
                    ull bb = pk2(bv[v].y, bv[v].y);
#pragma unroll
                    for (int rp = 0; rp < RP; ++rp) acc[rp][4 * v + 1] = fma2(apk[rp], bb, acc[rp][4 * v + 1]);
                }
                {
                    ull bb = pk2(bv[v].z, bv[v].z);
#pragma unroll
                    for (int rp = 0; rp < RP; ++rp) acc[rp][4 * v + 2] = fma2(apk[rp], bb, acc[rp][4 * v + 2]);
                }
                {
                    ull bb = pk2(bv[v].w, bv[v].w);
#pragma unroll
                    for (int rp = 0; rp < RP; ++rp) acc[rp][4 * v + 3] = fma2(apk[rp], bb, acc[rp][4 * v + 3]);
                }
            }
        }
        __syncthreads();
    }

    float sc8[TN], bi8[TN];
    if (MODE == 2) {
#pragma unroll
        for (int c = 0; c < TN; ++c) { sc8[c] = scv[bn + tc + c]; bi8[c] = biv[bn + tc + c]; }
    }
    float w30[TN], w31[TN], w32[TN];
    if (MODE == 3) {
#pragma unroll
        for (int c = 0; c < TN; ++c) {
            int gc = bn + tc + c;
            w30[c] = W3[gc]; w31[c] = W3[ldc + gc]; w32[c] = W3[2 * ldc + gc];
        }
    }
#pragma unroll
    for (int rp = 0; rp < RP; ++rp) {
        int r0 = bm + tr + 2 * rp, r1 = r0 + 1;
        float o0[TN], o1[TN];
#pragma unroll
        for (int c = 0; c < TN; ++c) upk2(acc[rp][c], o0[c], o1[c]);
        if (MODE == 2) {
#pragma unroll
            for (int c = 0; c < TN; ++c) {
                o0[c] = fmaxf(fmaf(o0[c], sc8[c], bi8[c]), 0.f);
                o1[c] = fmaxf(fmaf(o1[c], sc8[c], bi8[c]), 0.f);
            }
        }
        if (MODE == 3) {
            float4 p0 = p4r[(size_t)r0 * rstride];
            float4 p1 = p4r[(size_t)r1 * rstride];
#pragma unroll
            for (int c = 0; c < TN; ++c) {
                o0[c] += fmaf(p0.x, w30[c], fmaf(p0.y, w31[c], p0.z * w32[c]));
                o1[c] += fmaf(p1.x, w30[c], fmaf(p1.y, w31[c], p1.z * w32[c]));
            }
        }
#pragma unroll
        for (int v = 0; v < TN / 4; ++v) {
            *(float4*)&C[(size_t)r0 * ldc + bn + tc + 4 * v] =
                make_float4(o0[4 * v], o0[4 * v + 1], o0[4 * v + 2], o0[4 * v + 3]);
            *(float4*)&C[(size_t)r1 * ldc + bn + tc + 4 * v] =
                make_float4(o1[4 * v], o1[4 * v + 1], o1[4 * v + 2], o1[4 * v + 3]);
        }
    }
}

// ----------------------------------------------------------------------------
// edge_conv1 fused (K=3, C=64)
// ----------------------------------------------------------------------------
__global__ void edge1_kernel(const float4* __restrict__ p4,
                             const float* __restrict__ Wd, const float* __restrict__ Wb,
                             const int* __restrict__ idx,
                             const float* __restrict__ s, const float* __restrict__ b,
                             float* __restrict__ out) {
    __shared__ float4 pj[KNN];
    int i = blockIdx.x, c = threadIdx.x;  // block 64
    if (c < KNN) pj[c] = p4[idx[i * KNN + c]];
    __syncthreads();
    float4 pi = p4[i];
    float w0 = Wd[c], w1 = Wd[64 + c], w2 = Wd[128 + c];
    float u0 = Wb[c], u1 = Wb[64 + c], u2 = Wb[128 + c];
    float a = fmaf(pi.x, w0, fmaf(pi.y, w1, pi.z * w2));
    float sc = s[c], bv = b[c];
    float m = 0.f;
#pragma unroll
    for (int k = 0; k < KNN; ++k) {
        float4 pp = pj[k];
        float e = fmaf(pp.x, u0, fmaf(pp.y, u1, fmaf(pp.z, u2, a)));
        m = fmaxf(m, fmaf(e, sc, bv));
    }
    out[(size_t)i * 64 + c] = m;
}

// ----------------------------------------------------------------------------
// edge_conv2 gather-max, float4-wide: block = C/4 threads.
// ----------------------------------------------------------------------------
__global__ void gathermax_kernel(const float4* __restrict__ Aa, const float4* __restrict__ Bb,
                                 const int* __restrict__ idx,
                                 const float4* __restrict__ s, const float4* __restrict__ b,
                                 float4* __restrict__ out, int C4) {
    int i = blockIdx.x, c = threadIdx.x;
    __shared__ int js[KNN];
    if (c < KNN) js[c] = idx[i * KNN + c];
    __syncthreads();
    float4 a = Aa[(size_t)i * C4 + c];
    float4 sc = s[c], bv = b[c];
    float4 m = make_float4(0.f, 0.f, 0.f, 0.f);
#pragma unroll
    for (int k = 0; k < KNN; ++k) {
        float4 bj = Bb[(size_t)js[k] * C4 + c];
        m.x = fmaxf(m.x, fmaf(a.x + bj.x, sc.x, bv.x));
        m.y = fmaxf(m.y, fmaf(a.y + bj.y, sc.y, bv.y));
        m.z = fmaxf(m.z, fmaf(a.z + bj.z, sc.z, bv.z));
        m.w = fmaxf(m.w, fmaf(a.w + bj.w, sc.w, bv.w));
    }
    out[(size_t)i * C4 + c] = m;
}

// ----------------------------------------------------------------------------
// graph attention, float4-wide: block = D/4 threads.
// ----------------------------------------------------------------------------
template <int D>
__global__ void attn_kernel(const float4* __restrict__ q, const float4* __restrict__ kk,
                            const float4* __restrict__ v, const int* __restrict__ idx,
                            const float4* __restrict__ s, const float4* __restrict__ b,
                            float4* __restrict__ out) {
    constexpr int D4 = D / 4;
    int i = blockIdx.x;
    int tid = threadIdx.x;
    __shared__ float4 qs[D4];
    __shared__ float lg[KNN];
    __shared__ float aw[KNN];
    __shared__ int js[KNN];
    qs[tid] = q[(size_t)i * D4 + tid];
    if (tid < KNN) js[tid] = idx[i * KNN + tid];
    __syncthreads();

    constexpr int NW = D4 / 32;
    int w = tid >> 5, lane = tid & 31;
    for (int k = w; k < KNN; k += NW) {
        const float4* kr = kk + (size_t)js[k] * D4;
        float sum = 0.f;
#pragma unroll
        for (int m = lane; m < D4; m += 32) {
            float4 a = qs[m], c = kr[m];
            sum = fmaf(a.x, c.x, fmaf(a.y, c.y, fmaf(a.z, c.z, fmaf(a.w, c.w, sum))));
        }
#pragma unroll
        for (int o = 16; o; o >>= 1) sum += __shfl_xor_sync(0xffffffffu, sum, o);
        if (lane == 0) lg[k] = sum * (1.f / sqrtf((float)D));
    }
    __syncthreads();
    if (tid < 32) {
        float l = (lane < KNN) ? lg[lane] : -FLT_MAX;
        float mx = l;
#pragma unroll
        for (int o = 16; o; o >>= 1) mx = fmaxf(mx, __shfl_xor_sync(0xffffffffu, mx, o));
        float e = (lane < KNN) ? expf(l - mx) : 0.f;
        float se = e;
#pragma unroll
        for (int o = 16; o; o >>= 1) se += __shfl_xor_sync(0xffffffffu, se, o);
        if (lane < KNN) aw[lane] = e / se;
    }
    __syncthreads();
    float4 y = make_float4(0.f, 0.f, 0.f, 0.f);
#pragma unroll
    for (int k = 0; k < KNN; ++k) {
        float a = aw[k];
        float4 vv = v[(size_t)js[k] * D4 + tid];
        y.x = fmaf(a, vv.x, y.x); y.y = fmaf(a, vv.y, y.y);
        y.z = fmaf(a, vv.z, y.z); y.w = fmaf(a, vv.w, y.w);
    }
    float4 sc = s[tid], bv = b[tid];
    float4 r;
    r.x = fmaxf(fmaf(y.x, sc.x, bv.x), 0.f);
    r.y = fmaxf(fmaf(y.y, sc.y, bv.y), 0.f);
    r.z = fmaxf(fmaf(y.z, sc.z, bv.z), 0.f);
    r.w = fmaxf(fmaf(y.w, sc.w, bv.w), 0.f);
    out[(size_t)i * D4 + tid] = r;
}

// ----------------------------------------------------------------------------
// K=3 row transform (PM only, 2048 rows)
// ----------------------------------------------------------------------------
__global__ void rows3_kernel(const float4* __restrict__ p4, int rstride,
                             const float* __restrict__ W, float* __restrict__ out, int ncols) {
    int i = blockIdx.x;
    int c = blockIdx.y * blockDim.x + threadIdx.x;
    float4 p = p4[(size_t)i * rstride];
    out[(size_t)i * ncols + c] = fmaf(p.x, W[c], fmaf(p.y, W[ncols + c], p.z * W[2 * ncols + c]));
}

// ----------------------------------------------------------------------------
// downsample gather-max, float4-wide: block = 128 threads (512/4)
// ----------------------------------------------------------------------------
__global__ void downgather_kernel(const float4* __restrict__ PX, const float4* __restrict__ Pm,
                                  const int* __restrict__ idxd,
                                  const float4* __restrict__ s, const float4* __restrict__ b,
                                  float4* __restrict__ out) {
    int i = blockIdx.x, c = threadIdx.x;
    __shared__ int js[KNN];
    if (c < KNN) js[c] = idxd[i * KNN + c];
    __syncthreads();
    float4 pm = Pm[(size_t)i * 128 + c];
    float4 sc = s[c], bv = b[c];
    float4 m = make_float4(0.f, 0.f, 0.f, 0.f);
#pragma unroll
    for (int k = 0; k < KNN; ++k) {
        float4 px = PX[(size_t)js[k] * 128 + c];
        m.x = fmaxf(m.x, fmaf(px.x - pm.x, sc.x, bv.x));
        m.y = fmaxf(m.y, fmaf(px.y - pm.y, sc.y, bv.y));
        m.z = fmaxf(m.z, fmaf(px.z - pm.z, sc.z, bv.z));
        m.w = fmaxf(m.w, fmaf(px.w - pm.w, sc.w, bv.w));
    }
    out[(size_t)i * 128 + c] = m;
}

__global__ void colsum_kernel(const float* __restrict__ xd, float* __restrict__ gsum) {
    int c = blockIdx.x * blockDim.x + threadIdx.x;
    if (c >= 512) return;
    float s = 0.f;
    for (int r = 0; r < NDOWN; ++r) s += xd[(size_t)r * 512 + c];
    gsum[c] = s;
}

__global__ void beff_kernel(const float* __restrict__ gsum, const float* __restrict__ Wu2,
                            const float* __restrict__ su2, const float* __restrict__ bu1,
                            const float* __restrict__ bu2, float* __restrict__ be) {
    int c = threadIdx.x;
    float acc = 0.f;
    for (int d = 0; d < 512; ++d) acc = fmaf(gsum[d], Wu2[(size_t)d * 256 + c], acc);
    be[c] = bu1[c] + bu2[c] + su2[c] * (acc * (1.f / 2048.f));
}

__global__ void b2eff_kernel(const float* __restrict__ bc1, const float* __restrict__ scv,
                             const float* __restrict__ bcv, float* __restrict__ o) {
    int c = threadIdx.x;
    o[c] = fmaf(bc1[c], scv[c], bcv[c]);
}

__global__ void wdiff_kernel(const float* __restrict__ W, int half, float* __restrict__ Wd) {
    int t = blockIdx.x * blockDim.x + threadIdx.x;
    if (t < half) Wd[t] = W[t] - W[half + t];
}

__global__ void final_kernel(const float* __restrict__ h, const float* __restrict__ Wc2,
                             const float* __restrict__ bc2, float* __restrict__ out) {
    int t = blockIdx.x * blockDim.x + threadIdx.x;
    if (t >= NDOWN * 6) return;
    int i = t / 6, c = t % 6;
    float acc = bc2[c];
    for (int d = 0; d < 128; ++d) acc = fmaf(h[(size_t)i * 128 + d], Wc2[d * 6 + c], acc);
    out[t] = acc;
}

// ----------------------------------------------------------------------------
// launch
// ----------------------------------------------------------------------------
extern "C" void kernel_launch(void* const* d_in, const int* in_sizes, int n_in,
                              void* d_out, int out_size) {
    const float* points = (const float*)d_in[0];
    const float* We1 = (const float*)d_in[1];
    const float* se1 = (const float*)d_in[2];
    const float* be1 = (const float*)d_in[3];
    const float* We2 = (const float*)d_in[4];
    const float* se2 = (const float*)d_in[5];
    const float* be2 = (const float*)d_in[6];
    const float* Wq1 = (const float*)d_in[7];
    const float* Wk1 = (const float*)d_in[8];
    const float* Wv1 = (const float*)d_in[9];
    const float* sa1 = (const float*)d_in[10];
    const float* ba1 = (const float*)d_in[11];
    const float* Wq2 = (const float*)d_in[12];
    const float* Wk2 = (const float*)d_in[13];
    const float* Wv2 = (const float*)d_in[14];
    const float* sa2 = (const float*)d_in[15];
    const float* ba2 = (const float*)d_in[16];
    const float* Wtd = (const float*)d_in[17];
    const float* sd  = (const float*)d_in[18];
    const float* bd  = (const float*)d_in[19];
    const float* Wu1 = (const float*)d_in[20];
    const float* su1 = (const float*)d_in[21];
    const float* bu1 = (const float*)d_in[22];
    const float* Wu2 = (const float*)d_in[23];
    const float* su2 = (const float*)d_in[24];
    const float* bu2 = (const float*)d_in[25];
    const float* Wc1 = (const float*)d_in[26];
    const float* bc1 = (const float*)d_in[27];
    const float* scv = (const float*)d_in[28];
    const float* bcv = (const float*)d_in[29];
    const float* Wc2 = (const float*)d_in[30];
    const float* bc2 = (const float*)d_in[31];

    float* F = nullptr;
    int*   I = nullptr;
    cudaGetSymbolAddress((void**)&F, g_f);
    cudaGetSymbolAddress((void**)&I, g_i);

    float4* p4  = (float4*)(F + O_P4);
    float*  s1d = F + O_S1D;
    int*    s1i = I + OI_S1I;
    int*    idx = I + OI_IDX;
    int*    idxd = I + OI_IDXD;

    // --- kNN (full + downsampled) ---
    prep_p4_kernel<<<64, 128>>>(points, p4);
    {
        dim3 g1(NPTS / 128, CHUNKS);
        knn_stage1_kernel<<<g1, 128>>>(p4, 1, s1d, s1i);
        knn_stage2_kernel<<<NPTS / 128, 128>>>(s1d, s1i, NPTS, idx);
        dim3 g2(NDOWN / 128, CHUNKS);
        knn_stage1_kernel<<<g2, 128>>>(p4, 4, s1d, s1i);
        knn_stage2_kernel<<<NDOWN / 128, 128>>>(s1d, s1i, NDOWN, idxd);
    }

    // --- edge_conv 1 (fused, K=3, C=64) ---
    wdiff_kernel<<<2, 128>>>(We1, 192, F + O_WD1);
    edge1_kernel<<<NPTS, 64>>>(p4, F + O_WD1, We1 + 192, idx, se1, be1, F + O_X1);

    // --- edge_conv 2: C=128, batched A/B halves ---
    wdiff_kernel<<<64, 128>>>(We2, 8192, F + O_WD2);
    gemm_kernel<128, 128, 0><<<dim3(1, 64, 2), 256>>>(
        F + O_X1, 64, F + O_WD2, We2 + 8192, nullptr, 128,
        F + O_A2, F + O_B2, nullptr, 128, 64, nullptr, nullptr, nullptr, 0, nullptr);
    gathermax_kernel<<<NPTS, 32>>>((const float4*)(F + O_A2), (const float4*)(F + O_B2), idx,
                                   (const float4*)se2, (const float4*)be2,
                                   (float4*)(F + O_X2), 32);

    // --- graph_attn 1: D=256, q/k/v batched ---
    gemm_kernel<128, 128, 0><<<dim3(2, 64, 3), 256>>>(
        F + O_X2, 128, Wq1, Wk1, Wv1, 256,
        F + O_Q1, F + O_K1, F + O_V1, 256, 128, nullptr, nullptr, nullptr, 0, nullptr);
    attn_kernel<256><<<NPTS, 64>>>((const float4*)(F + O_Q1), (const float4*)(F + O_K1),
                                   (const float4*)(F + O_V1), idx,
                                   (const float4*)sa1, (const float4*)ba1,
                                   (float4*)(F + O_X3));

    // --- graph_attn 2: D=512, q/k/v batched ---
    gemm_kernel<128, 128, 0><<<dim3(4, 64, 3), 256>>>(
        F + O_X3, 256, Wq2, Wk2, Wv2, 512,
        F + O_Q2, F + O_K2, F + O_V2, 512, 256, nullptr, nullptr, nullptr, 0, nullptr);
    attn_kernel<512><<<NPTS, 128>>>((const float4*)(F + O_Q2), (const float4*)(F + O_K2),
                                    (const float4*)(F + O_V2), idx,
                                    (const float4*)sa2, (const float4*)ba2,
                                    (float4*)(F + O_X4));

    // --- downsample: PX = x4@Wtd[3:] + p@Wtd[0:3] (fused epilogue) ---
    gemm_kernel<128, 128, 3><<<dim3(4, 64, 1), 256>>>(
        F + O_X4, 512, Wtd + 3 * 512, nullptr, nullptr, 512,
        F + O_PX, nullptr, nullptr, 512, 512, nullptr, nullptr, p4, 1, Wtd);
    rows3_kernel<<<dim3(NDOWN, 4), 128>>>(p4, 4, Wtd, F + O_PM, 512);
    downgather_kernel<<<NDOWN, 128>>>((const float4*)(F + O_PX), (const float4*)(F + O_PM), idxd,
                                      (const float4*)sd, (const float4*)bd,
                                      (float4*)(F + O_XD));

    // --- global mean folded into bias; xu = relu(xd@Wu1*su1 + beff) ---
    colsum_kernel<<<4, 128>>>(F + O_XD, F + O_GS);
    beff_kernel<<<1, 256>>>(F + O_GS, Wu2, su2, bu1, bu2, F + O_BE);
    gemm_kernel<64, 64, 2><<<dim3(4, 32, 1), 256>>>(
        F + O_XD, 512, Wu1, nullptr, nullptr, 256,
        F + O_XU, nullptr, nullptr, 256, 512, su1, F + O_BE, nullptr, 0, nullptr);

    // --- h = relu((xu@Wc1)*sc + (bc1*sc+bc)) ---
    b2eff_kernel<<<1, 128>>>(bc1, scv, bcv, F + O_B2E);
    gemm_kernel<64, 64, 2><<<dim3(2, 32, 1), 256>>>(
        F + O_XU, 256, Wc1, nullptr, nullptr, 128,
        F + O_H, nullptr, nullptr, 128, 256, scv, F + O_B2E, nullptr, 0, nullptr);

    // --- out = h@Wc2 + bc2 ---
    final_kernel<<<96, 128>>>(F + O_H, Wc2, bc2, (float*)d_out);
}

// round 4
// speedup vs baseline: 1.3066x; 1.3066x over previous
#include <cuda_runtime.h>
#include <math.h>
#include <float.h>

#define NPTS   8192
#define NDOWN  2048
#define KNN    16
#define CHUNKS 16

// ----------------------------------------------------------------------------
// Scratch arenas (no cudaMalloc allowed).
// ----------------------------------------------------------------------------
__device__ float g_f[40200000];
__device__ int   g_i[2400000];

static const size_t O_A1  = 0;
static const size_t O_B1  = O_A1  + (size_t)8192*64;
static const size_t O_X1  = O_B1  + (size_t)8192*64;
static const size_t O_A2  = O_X1  + (size_t)8192*64;
static const size_t O_B2  = O_A2  + (size_t)8192*128;
static const size_t O_X2  = O_B2  + (size_t)8192*128;
static const size_t O_Q1  = O_X2  + (size_t)8192*128;
static const size_t O_K1  = O_Q1  + (size_t)8192*256;
static const size_t O_V1  = O_K1  + (size_t)8192*256;
static const size_t O_X3  = O_V1  + (size_t)8192*256;
static const size_t O_Q2  = O_X3  + (size_t)8192*256;
static const size_t O_K2  = O_Q2  + (size_t)8192*512;
static const size_t O_V2  = O_K2  + (size_t)8192*512;
static const size_t O_X4  = O_V2  + (size_t)8192*512;
static const size_t O_PX  = O_X4  + (size_t)8192*512;
static const size_t O_PM  = O_PX  + (size_t)8192*512;
static const size_t O_XD  = O_PM  + (size_t)2048*512;
static const size_t O_XU  = O_XD  + (size_t)2048*512;
static const size_t O_H   = O_XU  + (size_t)2048*256;
static const size_t O_GS  = O_H   + (size_t)2048*128;
static const size_t O_BE  = O_GS  + 512;
static const size_t O_B2E = O_BE  + 256;
static const size_t O_WD1 = O_B2E + 128;
static const size_t O_WD2 = O_WD1 + 192;
static const size_t O_P4  = O_WD2 + 8192;
static const size_t O_S1D = O_P4  + (size_t)8192*4;      // 8192*256 floats

static const size_t OI_IDX  = 0;                          // 8192*16
static const size_t OI_S1I  = (size_t)8192*16;            // 8192*256

// ----------------------------------------------------------------------------
// f32x2 helpers
// ----------------------------------------------------------------------------
typedef unsigned long long ull;

__device__ __forceinline__ ull pk2(float lo, float hi) {
    ull r; asm("mov.b64 %0,{%1,%2};" : "=l"(r) : "f"(lo), "f"(hi)); return r;
}
__device__ __forceinline__ ull fma2(ull a, ull b, ull c) {
    ull d; asm("fma.rn.f32x2 %0,%1,%2,%3;" : "=l"(d) : "l"(a), "l"(b), "l"(c)); return d;
}
__device__ __forceinline__ void upk2(ull v, float& lo, float& hi) {
    asm("mov.b64 {%0,%1},%2;" : "=f"(lo), "=f"(hi) : "l"(v));
}

// ----------------------------------------------------------------------------
// kNN (single pass over full query set; downsampled result is idx at stride 4)
// ----------------------------------------------------------------------------
__device__ __forceinline__ void replace_rescan(float s, int j, float (&d)[KNN], int (&id)[KNN],
                                               float& wval, int& wpos) {
#pragma unroll
    for (int t = 0; t < KNN; ++t) if (t == wpos) { d[t] = s; id[t] = j; }
    wval = d[0]; wpos = 0;
#pragma unroll
    for (int t = 1; t < KNN; ++t) if (d[t] > wval) { wval = d[t]; wpos = t; }
}

__global__ void prep_p4_kernel(const float* __restrict__ p, float4* __restrict__ p4) {
    int i = blockIdx.x * blockDim.x + threadIdx.x;
    if (i < NPTS) {
        float x = p[3 * i], y = p[3 * i + 1], z = p[3 * i + 2];
        p4[i] = make_float4(x, y, z, x * x + y * y + z * z);
    }
}

// grid (NPTS/128, CHUNKS), block 128. One 512-candidate tile per chunk.
__global__ void knn_stage1_kernel(const float4* __restrict__ p4,
                                  float* __restrict__ s1d, int* __restrict__ s1i) {
    const int CH = NPTS / CHUNKS;  // 512
    int q  = blockIdx.x * blockDim.x + threadIdx.x;
    int c0 = blockIdx.y * CH;

    float4 qp = p4[q];
    float qx = -2.f * qp.x, qy = -2.f * qp.y, qz = -2.f * qp.z;

    __shared__ float4 tile[512];
#pragma unroll
    for (int l = 0; l < 4; ++l) tile[threadIdx.x + l * 128] = p4[c0 + threadIdx.x + l * 128];
    __syncthreads();

    float d[KNN]; int id[KNN];
#pragma unroll
    for (int t = 0; t < KNN; ++t) {
        float4 c = tile[t];
        d[t] = fmaf(qx, c.x, fmaf(qy, c.y, fmaf(qz, c.z, c.w)));
        id[t] = c0 + t;
    }
    float wval = d[0]; int wpos = 0;
#pragma unroll
    for (int t = 1; t < KNN; ++t) if (d[t] > wval) { wval = d[t]; wpos = t; }

    float bs0 = 0.f, bs1 = 0.f, bs2 = 0.f, bs3 = 0.f;
    int   bj0 = 0, bj1 = 0, bj2 = 0, bj3 = 0, cnt = 0;

    for (int i = KNN; i < CH; ++i) {
        float4 c = tile[i];
        float s = fmaf(qx, c.x, fmaf(qy, c.y, fmaf(qz, c.z, c.w)));
        if (s < wval) {
            int j = c0 + i;
            if (cnt == 0)      { bs0 = s; bj0 = j; }
            else if (cnt == 1) { bs1 = s; bj1 = j; }
            else if (cnt == 2) { bs2 = s; bj2 = j; }
            else               { bs3 = s; bj3 = j; }
            cnt++;
        }
        if (__any_sync(0xffffffffu, cnt == 4)) {
            if (cnt > 0 && bs0 < wval) replace_rescan(bs0, bj0, d, id, wval, wpos);
            if (cnt > 1 && bs1 < wval) replace_rescan(bs1, bj1, d, id, wval, wpos);
            if (cnt > 2 && bs2 < wval) replace_rescan(bs2, bj2, d, id, wval, wpos);
            if (cnt > 3 && bs3 < wval) replace_rescan(bs3, bj3, d, id, wval, wpos);
            cnt = 0;
        }
    }
    if (cnt > 0 && bs0 < wval) replace_rescan(bs0, bj0, d, id, wval, wpos);
    if (cnt > 1 && bs1 < wval) replace_rescan(bs1, bj1, d, id, wval, wpos);
    if (cnt > 2 && bs2 < wval) replace_rescan(bs2, bj2, d, id, wval, wpos);
    if (cnt > 3 && bs3 < wval) replace_rescan(bs3, bj3, d, id, wval, wpos);

    size_t o = ((size_t)q * CHUNKS + blockIdx.y) * KNN;
#pragma unroll
    for (int t = 0; t < KNN; ++t) { s1d[o + t] = d[t]; s1i[o + t] = id[t]; }
}

__global__ void knn_stage2_kernel(const float* __restrict__ s1d, const int* __restrict__ s1i,
                                  int* __restrict__ outidx) {
    int q = blockIdx.x * blockDim.x + threadIdx.x;
    size_t base = (size_t)q * (CHUNKS * KNN);
    float d[KNN]; int id[KNN];
#pragma unroll
    for (int t = 0; t < KNN; ++t) { d[t] = s1d[base + t]; id[t] = s1i[base + t]; }
    float wval = d[0]; int wpos = 0;
#pragma unroll
    for (int t = 1; t < KNN; ++t) if (d[t] > wval) { wval = d[t]; wpos = t; }
    for (int c = KNN; c < CHUNKS * KNN; ++c) {
        float s = s1d[base + c];
        if (s < wval) replace_rescan(s, s1i[base + c], d, id, wval, wpos);
    }
#pragma unroll
    for (int t = 0; t < KNN; ++t) outidx[q * KNN + t] = id[t];
}

// ----------------------------------------------------------------------------
// Batched GEMM: C[M,N] = A[M,K] @ B[K,N]; B/C selected by blockIdx.z.
// MODE 0: store. MODE 2: relu(acc*s+b). MODE 3: acc + p@W3 rows (ld = ldc).
// ----------------------------------------------------------------------------
template <int BM, int BN, int MODE>
__global__ __launch_bounds__(256)
void gemm_kernel(const float* __restrict__ A, int lda,
                 const float* __restrict__ Bp0, const float* __restrict__ Bp1,
                 const float* __restrict__ Bp2, int ldb,
                 float* __restrict__ Cp0, float* __restrict__ Cp1,
                 float* __restrict__ Cp2, int ldc, int K,
                 const float* __restrict__ scv, const float* __restrict__ biv,
                 const float4* __restrict__ p4r, int rstride,
                 const float* __restrict__ W3) {
    constexpr int TM = BM / 16;
    constexpr int TN = BN / 16;
    constexpr int RP = TM / 2;
    constexpr int NA = BM / 64;
    constexpr int NB = BN / 64;
    constexpr int F4R = BN / 4;
    constexpr int BROW = 256 / F4R;

    __shared__ __align__(16) float As[16][BM + 4];
    __shared__ __align__(16) float Bs[16][BN];

    const float* B = (blockIdx.z == 0) ? Bp0 : (blockIdx.z == 1) ? Bp1 : Bp2;
    float*       C = (blockIdx.z == 0) ? Cp0 : (blockIdx.z == 1) ? Cp1 : Cp2;

    int tid = threadIdx.x;
    int bm = blockIdx.y * BM, bn = blockIdx.x * BN;

    int ar = tid >> 2, ac4 = tid & 3;
    int bk = tid / F4R, bc = tid % F4R;

    const float* Ap = A + (size_t)(bm + ar) * lda + ac4 * 4;
    const float* Bq = B + (size_t)bk * ldb + bn + bc * 4;

    float4 pa[NA], pb[NB];
#pragma unroll
    for (int l = 0; l < NA; ++l) pa[l] = *(const float4*)(Ap + (size_t)(64 * l) * lda);
#pragma unroll
    for (int l = 0; l < NB; ++l) pb[l] = *(const float4*)(Bq + (size_t)(BROW * l) * ldb);
    Ap += 16;
    Bq += (size_t)16 * ldb;

    int tr = (tid >> 4) * TM;
    int tc = (tid & 15) * TN;

    ull acc[RP][TN];
#pragma unroll
    for (int rp = 0; rp < RP; ++rp)
#pragma unroll
        for (int c = 0; c < TN; ++c) acc[rp][c] = 0ull;

    int ktiles = K >> 4;
    for (int t = 0; t < ktiles; ++t) {
#pragma unroll
        for (int l = 0; l < NA; ++l) {
            int r = ar + 64 * l;
            As[ac4 * 4 + 0][r] = pa[l].x;
            As[ac4 * 4 + 1][r] = pa[l].y;
            As[ac4 * 4 + 2][r] = pa[l].z;
            As[ac4 * 4 + 3][r] = pa[l].w;
        }
#pragma unroll
        for (int l = 0; l < NB; ++l)
            *(float4*)&Bs[bk + BROW * l][bc * 4] = pb[l];
        __syncthreads();

        if (t + 1 < ktiles) {
#pragma unroll
            for (int l = 0; l < NA; ++l) pa[l] = *(const float4*)(Ap + (size_t)(64 * l) * lda);
#pragma unroll
            for (int l = 0; l < NB; ++l) pb[l] = *(const float4*)(Bq + (size_t)(BROW * l) * ldb);
            Ap += 16;
            Bq += (size_t)16 * ldb;
        }

#pragma unroll
        for (int k = 0; k < 16; ++k) {
            float4 av[TM / 4], bv[TN / 4];
#pragma unroll
            for (int v = 0; v < TM / 4; ++v) av[v] = *(const float4*)&As[k][tr + 4 * v];
#pragma unroll
            for (int v = 0; v < TN / 4; ++v) bv[v] = *(const float4*)&Bs[k][tc + 4 * v];
            ull apk[RP];
#pragma unroll
            for (int v = 0; v < TM / 4; ++v) {
                apk[2 * v + 0] = pk2(av[v].x, av[v].y);
                apk[2 * v + 1] = pk2(av[v].z, av[v].w);
            }
#pragma unroll
            for (int v = 0; v < TN / 4; ++v) {
                {
                    ull bb = pk2(bv[v].x, bv[v].x);
#pragma unroll
                    for (int rp = 0; rp < RP; ++rp) acc[rp][4 * v + 0] = fma2(apk[rp], bb, acc[rp][4 * v + 0]);
                }
                {
                    ull bb = pk2(bv[v].y, bv[v].y);
#pragma unroll
                    for (int rp = 0; rp < RP; ++rp) acc[rp][4 * v + 1] = fma2(apk[rp], bb, acc[rp][4 * v + 1]);
                }
                {
                    ull bb = pk2(bv[v].z, bv[v].z);
#pragma unroll
                    for (int rp = 0; rp < RP; ++rp) acc[rp][4 * v + 2] = fma2(apk[rp], bb, acc[rp][4 * v + 2]);
                }
                {
                    ull bb = pk2(bv[v].w, bv[v].w);
#pragma unroll
                    for (int rp = 0; rp < RP; ++rp) acc[rp][4 * v + 3] = fma2(apk[rp], bb, acc[rp][4 * v + 3]);
                }
            }
        }
        __syncthreads();
    }

    float sc8[TN], bi8[TN];
    if (MODE == 2) {
#pragma unroll
        for (int c = 0; c < TN; ++c) { sc8[c] = scv[bn + tc + c]; bi8[c] = biv[bn + tc + c]; }
    }
    float w30[TN], w31[TN], w32[TN];
    if (MODE == 3) {
#pragma unroll
        for (int c = 0; c < TN; ++c) {
            int gc = bn + tc + c;
            w30[c] = W3[gc]; w31[c] = W3[ldc + gc]; w32[c] = W3[2 * ldc + gc];
        }
    }
#pragma unroll
    for (int rp = 0; rp < RP; ++rp) {
        int r0 = bm + tr + 2 * rp, r1 = r0 + 1;
        float o0[TN], o1[TN];
#pragma unroll
        for (int c = 0; c < TN; ++c) upk2(acc[rp][c], o0[c], o1[c]);
        if (MODE == 2) {
#pragma unroll
            for (int c = 0; c < TN; ++c) {
                o0[c] = fmaxf(fmaf(o0[c], sc8[c], bi8[c]), 0.f);
                o1[c] = fmaxf(fmaf(o1[c], sc8[c], bi8[c]), 0.f);
            }
        }
        if (MODE == 3) {
            float4 p0 = p4r[(size_t)r0 * rstride];
            float4 p1 = p4r[(size_t)r1 * rstride];
#pragma unroll
            for (int c = 0; c < TN; ++c) {
                o0[c] += fmaf(p0.x, w30[c], fmaf(p0.y, w31[c], p0.z * w32[c]));
                o1[c] += fmaf(p1.x, w30[c], fmaf(p1.y, w31[c], p1.z * w32[c]));
            }
        }
#pragma unroll
        for (int v = 0; v < TN / 4; ++v) {
            *(float4*)&C[(size_t)r0 * ldc + bn + tc + 4 * v] =
                make_float4(o0[4 * v], o0[4 * v + 1], o0[4 * v + 2], o0[4 * v + 3]);
            *(float4*)&C[(size_t)r1 * ldc + bn + tc + 4 * v] =
                make_float4(o1[4 * v], o1[4 * v + 1], o1[4 * v + 2], o1[4 * v + 3]);
        }
    }
}

// ----------------------------------------------------------------------------
// edge_conv1 fused (K=3, C=64). 4 points/block, 256 threads.
// ----------------------------------------------------------------------------
__global__ void edge1_kernel(const float4* __restrict__ p4,
                             const float* __restrict__ Wd, const float* __restrict__ Wb,
                             const int* __restrict__ idx,
                             const float* __restrict__ s, const float* __restrict__ b,
                             float* __restrict__ out) {
    __shared__ float4 pj[4][KNN];
    int g = threadIdx.x >> 6, c = threadIdx.x & 63;
    int i = blockIdx.x * 4 + g;
    if (c < KNN) pj[g][c] = p4[idx[i * KNN + c]];
    __syncthreads();
    float4 pi = p4[i];
    float w0 = Wd[c], w1 = Wd[64 + c], w2 = Wd[128 + c];
    float u0 = Wb[c], u1 = Wb[64 + c], u2 = Wb[128 + c];
    float a = fmaf(pi.x, w0, fmaf(pi.y, w1, pi.z * w2));
    float sc = s[c], bv = b[c];
    float m = 0.f;
#pragma unroll
    for (int k = 0; k < KNN; ++k) {
        float4 pp = pj[g][k];
        float e = fmaf(pp.x, u0, fmaf(pp.y, u1, fmaf(pp.z, u2, a)));
        m = fmaxf(m, fmaf(e, sc, bv));
    }
    out[(size_t)i * 64 + c] = m;
}

// ----------------------------------------------------------------------------
// edge_conv2 gather-max (C=128, float4): 4 points/block, 128 threads.
// ----------------------------------------------------------------------------
__global__ void gathermax_kernel(const float4* __restrict__ Aa, const float4* __restrict__ Bb,
                                 const int* __restrict__ idx,
                                 const float4* __restrict__ s, const float4* __restrict__ b,
                                 float4* __restrict__ out) {
    const int C4 = 32;
    __shared__ int js[4][KNN];
    int g = threadIdx.x >> 5, c = threadIdx.x & 31;
    int i = blockIdx.x * 4 + g;
    if (c < KNN) js[g][c] = idx[i * KNN + c];
    __syncthreads();
    float4 a = Aa[(size_t)i * C4 + c];
    float4 sc = s[c], bv = b[c];
    float4 m = make_float4(0.f, 0.f, 0.f, 0.f);
#pragma unroll
    for (int k = 0; k < KNN; ++k) {
        float4 bj = Bb[(size_t)js[g][k] * C4 + c];
        m.x = fmaxf(m.x, fmaf(a.x + bj.x, sc.x, bv.x));
        m.y = fmaxf(m.y, fmaf(a.y + bj.y, sc.y, bv.y));
        m.z = fmaxf(m.z, fmaf(a.z + bj.z, sc.z, bv.z));
        m.w = fmaxf(m.w, fmaf(a.w + bj.w, sc.w, bv.w));
    }
    out[(size_t)i * C4 + c] = m;
}

// ----------------------------------------------------------------------------
// graph attention, float4; NP points per block, D4 threads per point.
// ----------------------------------------------------------------------------
template <int D, int NP>
__global__ void attn_kernel(const float4* __restrict__ q, const float4* __restrict__ kk,
                            const float4* __restrict__ v, const int* __restrict__ idx,
                            const float4* __restrict__ s, const float4* __restrict__ b,
                            float4* __restrict__ out) {
    constexpr int D4 = D / 4;
    int tid = threadIdx.x;
    int g = tid / D4, t = tid % D4;
    int i = blockIdx.x * NP + g;
    __shared__ float4 qs[NP][D4];
    __shared__ float lg[NP][KNN];
    __shared__ float aw[NP][KNN];
    __shared__ int js[NP][KNN];
    qs[g][t] = q[(size_t)i * D4 + t];
    if (t < KNN) js[g][t] = idx[i * KNN + t];
    __syncthreads();

    constexpr int NW = D4 / 32;
    int w = t >> 5, lane = t & 31;
    for (int k = w; k < KNN; k += NW) {
        const float4* kr = kk + (size_t)js[g][k] * D4;
        float sum = 0.f;
#pragma unroll
        for (int m = lane; m < D4; m += 32) {
            float4 a = qs[g][m], c = kr[m];
            sum = fmaf(a.x, c.x, fmaf(a.y, c.y, fmaf(a.z, c.z, fmaf(a.w, c.w, sum))));
        }
#pragma unroll
        for (int o = 16; o; o >>= 1) sum += __shfl_xor_sync(0xffffffffu, sum, o);
        if (lane == 0) lg[g][k] = sum * (1.f / sqrtf((float)D));
    }
    __syncthreads();
    if (t < 32) {
        float l = (lane < KNN) ? lg[g][lane] : -FLT_MAX;
        float mx = l;
#pragma unroll
        for (int o = 16; o; o >>= 1) mx = fmaxf(mx, __shfl_xor_sync(0xffffffffu, mx, o));
        float e = (lane < KNN) ? expf(l - mx) : 0.f;
        float se = e;
#pragma unroll
        for (int o = 16; o; o >>= 1) se += __shfl_xor_sync(0xffffffffu, se, o);
        if (lane < KNN) aw[g][lane] = e / se;
    }
    __syncthreads();
    float4 y = make_float4(0.f, 0.f, 0.f, 0.f);
#pragma unroll
    for (int k = 0; k < KNN; ++k) {
        float a = aw[g][k];
        float4 vv = v[(size_t)js[g][k] * D4 + t];
        y.x = fmaf(a, vv.x, y.x); y.y = fmaf(a, vv.y, y.y);
        y.z = fmaf(a, vv.z, y.z); y.w = fmaf(a, vv.w, y.w);
    }
    float4 sc = s[t], bv = b[t];
    float4 r;
    r.x = fmaxf(fmaf(y.x, sc.x, bv.x), 0.f);
    r.y = fmaxf(fmaf(y.y, sc.y, bv.y), 0.f);
    r.z = fmaxf(fmaf(y.z, sc.z, bv.z), 0.f);
    r.w = fmaxf(fmaf(y.w, sc.w, bv.w), 0.f);
    out[(size_t)i * D4 + t] = r;
}

// ----------------------------------------------------------------------------
// K=3 row transform (PM: 2048 rows, stride-4 points)
// ----------------------------------------------------------------------------
__global__ void rows3_kernel(const float4* __restrict__ p4, int rstride,
                             const float* __restrict__ W, float* __restrict__ out, int ncols) {
    int i = blockIdx.x;
    int c = blockIdx.y * blockDim.x + threadIdx.x;
    float4 p = p4[(size_t)i * rstride];
    out[(size_t)i * ncols + c] = fmaf(p.x, W[c], fmaf(p.y, W[ncols + c], p.z * W[2 * ncols + c]));
}

// ----------------------------------------------------------------------------
// downsample gather-max (float4): 2 points/block, 256 threads. Neighbor rows
// come from the FULL kNN index at stride 4 (idx_d[i] == idx[4*i]).
// ----------------------------------------------------------------------------
__global__ void downgather_kernel(const float4* __restrict__ PX, const float4* __restrict__ Pm,
                                  const int* __restrict__ idx,
                                  const float4* __restrict__ s, const float4* __restrict__ b,
                                  float4* __restrict__ out) {
    __shared__ int js[2][KNN];
    int g = threadIdx.x >> 7, c = threadIdx.x & 127;
    int i = blockIdx.x * 2 + g;
    if (c < KNN) js[g][c] = idx[(4 * i) * KNN + c];
    __syncthreads();
    float4 pm = Pm[(size_t)i * 128 + c];
    float4 sc = s[c], bv = b[c];
    float4 m = make_float4(0.f, 0.f, 0.f, 0.f);
#pragma unroll
    for (int k = 0; k < KNN; ++k) {
        float4 px = PX[(size_t)js[g][k] * 128 + c];
        m.x = fmaxf(m.x, fmaf(px.x - pm.x, sc.x, bv.x));
        m.y = fmaxf(m.y, fmaf(px.y - pm.y, sc.y, bv.y));
        m.z = fmaxf(m.z, fmaf(px.z - pm.z, sc.z, bv.z));
        m.w = fmaxf(m.w, fmaf(px.w - pm.w, sc.w, bv.w));
    }
    out[(size_t)i * 128 + c] = m;
}

__global__ void colsum_kernel(const float* __restrict__ xd, float* __restrict__ gsum) {
    int c = blockIdx.x * blockDim.x + threadIdx.x;
    if (c >= 512) return;
    float s = 0.f;
    for (int r = 0; r < NDOWN; ++r) s += xd[(size_t)r * 512 + c];
    gsum[c] = s;
}

__global__ void beff_kernel(const float* __restrict__ gsum, const float* __restrict__ Wu2,
                            const float* __restrict__ su2, const float* __restrict__ bu1,
                            const float* __restrict__ bu2, float* __restrict__ be) {
    int c = threadIdx.x;
    float acc = 0.f;
    for (int d = 0; d < 512; ++d) acc = fmaf(gsum[d], Wu2[(size_t)d * 256 + c], acc);
    be[c] = bu1[c] + bu2[c] + su2[c] * (acc * (1.f / 2048.f));
}

__global__ void b2eff_kernel(const float* __restrict__ bc1, const float* __restrict__ scv,
                             const float* __restrict__ bcv, float* __restrict__ o) {
    int c = threadIdx.x;
    o[c] = fmaf(bc1[c], scv[c], bcv[c]);
}

__global__ void wdiff_kernel(const float* __restrict__ W, int half, float* __restrict__ Wd) {
    int t = blockIdx.x * blockDim.x + threadIdx.x;
    if (t < half) Wd[t] = W[t] - W[half + t];
}

__global__ void final_kernel(const float* __restrict__ h, const float* __restrict__ Wc2,
                             const float* __restrict__ bc2, float* __restrict__ out) {
    int t = blockIdx.x * blockDim.x + threadIdx.x;
    if (t >= NDOWN * 6) return;
    int i = t / 6, c = t % 6;
    float acc = bc2[c];
    for (int d = 0; d < 128; ++d) acc = fmaf(h[(size_t)i * 128 + d], Wc2[d * 6 + c], acc);
    out[t] = acc;
}

// ----------------------------------------------------------------------------
// launch
// ----------------------------------------------------------------------------
extern "C" void kernel_launch(void* const* d_in, const int* in_sizes, int n_in,
                              void* d_out, int out_size) {
    const float* points = (const float*)d_in[0];
    const float* We1 = (const float*)d_in[1];
    const float* se1 = (const float*)d_in[2];
    const float* be1 = (const float*)d_in[3];
    const float* We2 = (const float*)d_in[4];
    const float* se2 = (const float*)d_in[5];
    const float* be2 = (const float*)d_in[6];
    const float* Wq1 = (const float*)d_in[7];
    const float* Wk1 = (const float*)d_in[8];
    const float* Wv1 = (const float*)d_in[9];
    const float* sa1 = (const float*)d_in[10];
    const float* ba1 = (const float*)d_in[11];
    const float* Wq2 = (const float*)d_in[12];
    const float* Wk2 = (const float*)d_in[13];
    const float* Wv2 = (const float*)d_in[14];
    const float* sa2 = (const float*)d_in[15];
    const float* ba2 = (const float*)d_in[16];
    const float* Wtd = (const float*)d_in[17];
    const float* sd  = (const float*)d_in[18];
    const float* bd  = (const float*)d_in[19];
    const float* Wu1 = (const float*)d_in[20];
    const float* su1 = (const float*)d_in[21];
    const float* bu1 = (const float*)d_in[22];
    const float* Wu2 = (const float*)d_in[23];
    const float* su2 = (const float*)d_in[24];
    const float* bu2 = (const float*)d_in[25];
    const float* Wc1 = (const float*)d_in[26];
    const float* bc1 = (const float*)d_in[27];
    const float* scv = (const float*)d_in[28];
    const float* bcv = (const float*)d_in[29];
    const float* Wc2 = (const float*)d_in[30];
    const float* bc2 = (const float*)d_in[31];

    float* F = nullptr;
    int*   I = nullptr;
    cudaGetSymbolAddress((void**)&F, g_f);
    cudaGetSymbolAddress((void**)&I, g_i);

    float4* p4  = (float4*)(F + O_P4);
    float*  s1d = F + O_S1D;
    int*    s1i = I + OI_S1I;
    int*    idx = I + OI_IDX;

    // --- kNN (single full pass; downsampled rows are idx at stride 4) ---
    prep_p4_kernel<<<64, 128>>>(points, p4);
    knn_stage1_kernel<<<dim3(NPTS / 128, CHUNKS), 128>>>(p4, s1d, s1i);
    knn_stage2_kernel<<<NPTS / 128, 128>>>(s1d, s1i, idx);

    // --- edge_conv 1 (fused, K=3, C=64) ---
    wdiff_kernel<<<2, 128>>>(We1, 192, F + O_WD1);
    edge1_kernel<<<NPTS / 4, 256>>>(p4, F + O_WD1, We1 + 192, idx, se1, be1, F + O_X1);

    // --- edge_conv 2: C=128, batched A/B halves ---
    wdiff_kernel<<<64, 128>>>(We2, 8192, F + O_WD2);
    gemm_kernel<128, 128, 0><<<dim3(1, 64, 2), 256>>>(
        F + O_X1, 64, F + O_WD2, We2 + 8192, nullptr, 128,
        F + O_A2, F + O_B2, nullptr, 128, 64, nullptr, nullptr, nullptr, 0, nullptr);
    gathermax_kernel<<<NPTS / 4, 128>>>((const float4*)(F + O_A2), (const float4*)(F + O_B2), idx,
                                        (const float4*)se2, (const float4*)be2,
                                        (float4*)(F + O_X2));

    // --- graph_attn 1: D=256, q/k/v batched ---
    gemm_kernel<128, 128, 0><<<dim3(2, 64, 3), 256>>>(
        F + O_X2, 128, Wq1, Wk1, Wv1, 256,
        F + O_Q1, F + O_K1, F + O_V1, 256, 128, nullptr, nullptr, nullptr, 0, nullptr);
    attn_kernel<256, 4><<<NPTS / 4, 256>>>((const float4*)(F + O_Q1), (const float4*)(F + O_K1),
                                           (const float4*)(F + O_V1), idx,
                                           (const float4*)sa1, (const float4*)ba1,
                                           (float4*)(F + O_X3));

    // --- graph_attn 2: D=512, q/k/v batched ---
    gemm_kernel<128, 128, 0><<<dim3(4, 64, 3), 256>>>(
        F + O_X3, 256, Wq2, Wk2, Wv2, 512,
        F + O_Q2, F + O_K2, F + O_V2, 512, 256, nullptr, nullptr, nullptr, 0, nullptr);
    attn_kernel<512, 2><<<NPTS / 2, 256>>>((const float4*)(F + O_Q2), (const float4*)(F + O_K2),
                                           (const float4*)(F + O_V2), idx,
                                           (const float4*)sa2, (const float4*)ba2,
                                           (float4*)(F + O_X4));

    // --- downsample: PX = x4@Wtd[3:] + p@Wtd[0:3] (fused epilogue) ---
    gemm_kernel<128, 128, 3><<<dim3(4, 64, 1), 256>>>(
        F + O_X4, 512, Wtd + 3 * 512, nullptr, nullptr, 512,
        F + O_PX, nullptr, nullptr, 512, 512, nullptr, nullptr, p4, 1, Wtd);
    rows3_kernel<<<dim3(NDOWN, 4), 128>>>(p4, 4, Wtd, F + O_PM, 512);
    downgather_kernel<<<NDOWN / 2, 256>>>((const float4*)(F + O_PX), (const float4*)(F + O_PM), idx,
                                          (const float4*)sd, (const float4*)bd,
                                          (float4*)(F + O_XD));

    // --- global mean folded into bias; xu = relu(xd@Wu1*su1 + beff) ---
    colsum_kernel<<<4, 128>>>(F + O_XD, F + O_GS);
    beff_kernel<<<1, 256>>>(F + O_GS, Wu2, su2, bu1, bu2, F + O_BE);
    gemm_kernel<64, 64, 2><<<dim3(4, 32, 1), 256>>>(
        F + O_XD, 512, Wu1, nullptr, nullptr, 256,
        F + O_XU, nullptr, nullptr, 256, 512, su1, F + O_BE, nullptr, 0, nullptr);

    // --- h = relu((xu@Wc1)*sc + (bc1*sc+bc)) ---
    b2eff_kernel<<<1, 128>>>(bc1, scv, bcv, F + O_B2E);
    gemm_kernel<64, 64, 2><<<dim3(2, 32, 1), 256>>>(
        F + O_XU, 256, Wc1, nullptr, nullptr, 128,
        F + O_H, nullptr, nullptr, 128, 256, scv, F + O_B2E, nullptr, 0, nullptr);

    // --- out = h@Wc2 + bc2 ---
    final_kernel<<<96, 128>>>(F + O_H, Wc2, bc2, (float*)d_out);
}

// round 5
// speedup vs baseline: 1.4038x; 1.0744x over previous
#include <cuda_runtime.h>
#include <math.h>
#include <float.h>

#define NPTS   8192
#define NDOWN  2048
#define KNN    16
#define CHUNKS 16

// ----------------------------------------------------------------------------
// Scratch arenas (no cudaMalloc allowed).
// ----------------------------------------------------------------------------
__device__ float g_f[40200000];
__device__ int   g_i[2400000];

static const size_t O_A1  = 0;
static const size_t O_B1  = O_A1  + (size_t)8192*64;
static const size_t O_X1  = O_B1  + (size_t)8192*64;
static const size_t O_A2  = O_X1  + (size_t)8192*64;
static const size_t O_B2  = O_A2  + (size_t)8192*128;
static const size_t O_X2  = O_B2  + (size_t)8192*128;
static const size_t O_Q1  = O_X2  + (size_t)8192*128;
static const size_t O_K1  = O_Q1  + (size_t)8192*256;
static const size_t O_V1  = O_K1  + (size_t)8192*256;
static const size_t O_X3  = O_V1  + (size_t)8192*256;
static const size_t O_Q2  = O_X3  + (size_t)8192*256;
static const size_t O_K2  = O_Q2  + (size_t)8192*512;
static const size_t O_V2  = O_K2  + (size_t)8192*512;
static const size_t O_X4  = O_V2  + (size_t)8192*512;
static const size_t O_PX  = O_X4  + (size_t)8192*512;
static const size_t O_PM  = O_PX  + (size_t)8192*512;
static const size_t O_XD  = O_PM  + (size_t)2048*512;
static const size_t O_XU  = O_XD  + (size_t)2048*512;
static const size_t O_H   = O_XU  + (size_t)2048*256;
static const size_t O_GS  = O_H   + (size_t)2048*128;   // 512
static const size_t O_BE  = O_GS  + 512;                // 256
static const size_t O_B2E = O_BE  + 256;                // 128
static const size_t O_WD1 = O_B2E + 128;                // 192
static const size_t O_WD2 = O_WD1 + 192;                // 8192
static const size_t O_P4  = O_WD2 + 8192;               // 8192*4
static const size_t O_S1D = O_P4  + (size_t)8192*4;     // 8192*256
static const size_t O_GS2 = O_S1D + (size_t)8192*256;   // 4096

static const size_t OI_IDX  = 0;                          // 8192*16
static const size_t OI_S1I  = (size_t)8192*16;            // 8192*256

// ----------------------------------------------------------------------------
// f32x2 helpers
// ----------------------------------------------------------------------------
typedef unsigned long long ull;

__device__ __forceinline__ ull pk2(float lo, float hi) {
    ull r; asm("mov.b64 %0,{%1,%2};" : "=l"(r) : "f"(lo), "f"(hi)); return r;
}
__device__ __forceinline__ ull fma2(ull a, ull b, ull c) {
    ull d; asm("fma.rn.f32x2 %0,%1,%2,%3;" : "=l"(d) : "l"(a), "l"(b), "l"(c)); return d;
}
__device__ __forceinline__ void upk2(ull v, float& lo, float& hi) {
    asm("mov.b64 {%0,%1},%2;" : "=f"(lo), "=f"(hi) : "l"(v));
}

// ----------------------------------------------------------------------------
// kNN (single pass; downsampled rows are idx at stride 4)
// ----------------------------------------------------------------------------
__device__ __forceinline__ void replace_rescan(float s, int j, float (&d)[KNN], int (&id)[KNN],
                                               float& wval, int& wpos) {
#pragma unroll
    for (int t = 0; t < KNN; ++t) if (t == wpos) { d[t] = s; id[t] = j; }
    wval = d[0]; wpos = 0;
#pragma unroll
    for (int t = 1; t < KNN; ++t) if (d[t] > wval) { wval = d[t]; wpos = t; }
}

__global__ void prep_p4_kernel(const float* __restrict__ p, float4* __restrict__ p4, int base) {
    int i = base + blockIdx.x * blockDim.x + threadIdx.x;
    if (i < NPTS) {
        float x = p[3 * i], y = p[3 * i + 1], z = p[3 * i + 2];
        p4[i] = make_float4(x, y, z, x * x + y * y + z * z);
    }
}

// grid (NPTS/128, CHUNKS), block 128. One 512-candidate tile per chunk.
__global__ void knn_stage1_kernel(const float4* __restrict__ p4,
                                  float* __restrict__ s1d, int* __restrict__ s1i) {
    const int CH = NPTS / CHUNKS;  // 512
    int q  = blockIdx.x * blockDim.x + threadIdx.x;
    int c0 = blockIdx.y * CH;

    float4 qp = p4[q];
    float qx = -2.f * qp.x, qy = -2.f * qp.y, qz = -2.f * qp.z;

    __shared__ float4 tile[512];
#pragma unroll
    for (int l = 0; l < 4; ++l) tile[threadIdx.x + l * 128] = p4[c0 + threadIdx.x + l * 128];
    __syncthreads();

    float d[KNN]; int id[KNN];
#pragma unroll
    for (int t = 0; t < KNN; ++t) {
        float4 c = tile[t];
        d[t] = fmaf(qx, c.x, fmaf(qy, c.y, fmaf(qz, c.z, c.w)));
        id[t] = c0 + t;
    }
    float wval = d[0]; int wpos = 0;
#pragma unroll
    for (int t = 1; t < KNN; ++t) if (d[t] > wval) { wval = d[t]; wpos = t; }

    float bs0 = 0.f, bs1 = 0.f, bs2 = 0.f, bs3 = 0.f;
    int   bj0 = 0, bj1 = 0, bj2 = 0, bj3 = 0, cnt = 0;

    for (int i = KNN; i < CH; ++i) {
        float4 c = tile[i];
        float s = fmaf(qx, c.x, fmaf(qy, c.y, fmaf(qz, c.z, c.w)));
        if (s < wval) {
            int j = c0 + i;
            if (cnt == 0)      { bs0 = s; bj0 = j; }
            else if (cnt == 1) { bs1 = s; bj1 = j; }
            else if (cnt == 2) { bs2 = s; bj2 = j; }
            else               { bs3 = s; bj3 = j; }
            cnt++;
        }
        if (__any_sync(0xffffffffu, cnt == 4)) {
            if (cnt > 0 && bs0 < wval) replace_rescan(bs0, bj0, d, id, wval, wpos);
            if (cnt > 1 && bs1 < wval) replace_rescan(bs1, bj1, d, id, wval, wpos);
            if (cnt > 2 && bs2 < wval) replace_rescan(bs2, bj2, d, id, wval, wpos);
            if (cnt > 3 && bs3 < wval) replace_rescan(bs3, bj3, d, id, wval, wpos);
            cnt = 0;
        }
    }
    if (cnt > 0 && bs0 < wval) replace_rescan(bs0, bj0, d, id, wval, wpos);
    if (cnt > 1 && bs1 < wval) replace_rescan(bs1, bj1, d, id, wval, wpos);
    if (cnt > 2 && bs2 < wval) replace_rescan(bs2, bj2, d, id, wval, wpos);
    if (cnt > 3 && bs3 < wval) replace_rescan(bs3, bj3, d, id, wval, wpos);

    size_t o = ((size_t)q * CHUNKS + blockIdx.y) * KNN;
#pragma unroll
    for (int t = 0; t < KNN; ++t) { s1d[o + t] = d[t]; s1i[o + t] = id[t]; }
}

__global__ void knn_stage2_kernel(const float* __restrict__ s1d, const int* __restrict__ s1i,
                                  int* __restrict__ outidx) {
    int q = blockIdx.x * blockDim.x + threadIdx.x;
    size_t base = (size_t)q * (CHUNKS * KNN);
    float d[KNN]; int id[KNN];
#pragma unroll
    for (int t = 0; t < KNN; ++t) { d[t] = s1d[base + t]; id[t] = s1i[base + t]; }
    float wval = d[0]; int wpos = 0;
#pragma unroll
    for (int t = 1; t < KNN; ++t) if (d[t] > wval) { wval = d[t]; wpos = t; }
    for (int c = KNN; c < CHUNKS * KNN; ++c) {
        float s = s1d[base + c];
        if (s < wval) replace_rescan(s, s1i[base + c], d, id, wval, wpos);
    }
#pragma unroll
    for (int t = 0; t < KNN; ++t) outidx[q * KNN + t] = id[t];
}

// ----------------------------------------------------------------------------
// Batched GEMM, double-buffered smem: C[M,N] = A[M,K] @ B[K,N].
// One __syncthreads per k-tile; load(t+1)->compute(t)->store(t+1)->sync.
// MODE 0: store. MODE 2: relu(acc*s+b). MODE 3: acc + p@W3 rows (ld = ldc).
// ----------------------------------------------------------------------------
template <int BM, int BN, int MODE>
__global__ __launch_bounds__(256, 2)
void gemm_kernel(const float* __restrict__ A, int lda,
                 const float* __restrict__ Bp0, const float* __restrict__ Bp1,
                 const float* __restrict__ Bp2, int ldb,
                 float* __restrict__ Cp0, float* __restrict__ Cp1,
                 float* __restrict__ Cp2, int ldc, int K,
                 const float* __restrict__ scv, const float* __restrict__ biv,
                 const float4* __restrict__ p4r, int rstride,
                 const float* __restrict__ W3) {
    constexpr int TM = BM / 16;
    constexpr int TN = BN / 16;
    constexpr int RP = TM / 2;
    constexpr int NA = BM / 64;
    constexpr int NB = BN / 64;
    constexpr int F4R = BN / 4;
    constexpr int BROW = 256 / F4R;

    __shared__ __align__(16) float As[2][16][BM + 4];
    __shared__ __align__(16) float Bs[2][16][BN];

    const float* B = (blockIdx.z == 0) ? Bp0 : (blockIdx.z == 1) ? Bp1 : Bp2;
    float*       C = (blockIdx.z == 0) ? Cp0 : (blockIdx.z == 1) ? Cp1 : Cp2;

    int tid = threadIdx.x;
    int bm = blockIdx.y * BM, bn = blockIdx.x * BN;

    int ar = tid >> 2, ac4 = tid & 3;
    int bk = tid / F4R, bc = tid % F4R;

    const float* Ap = A + (size_t)(bm + ar) * lda + ac4 * 4;
    const float* Bq = B + (size_t)bk * ldb + bn + bc * 4;

    float4 pa[NA], pb[NB];
#pragma unroll
    for (int l = 0; l < NA; ++l) pa[l] = *(const float4*)(Ap + (size_t)(64 * l) * lda);
#pragma unroll
    for (int l = 0; l < NB; ++l) pb[l] = *(const float4*)(Bq + (size_t)(BROW * l) * ldb);
    Ap += 16;
    Bq += (size_t)16 * ldb;

    // stage tile 0 into buffer 0
#pragma unroll
    for (int l = 0; l < NA; ++l) {
        int r = ar + 64 * l;
        As[0][ac4 * 4 + 0][r] = pa[l].x;
        As[0][ac4 * 4 + 1][r] = pa[l].y;
        As[0][ac4 * 4 + 2][r] = pa[l].z;
        As[0][ac4 * 4 + 3][r] = pa[l].w;
    }
#pragma unroll
    for (int l = 0; l < NB; ++l)
        *(float4*)&Bs[0][bk + BROW * l][bc * 4] = pb[l];
    __syncthreads();

    int tr = (tid >> 4) * TM;
    int tc = (tid & 15) * TN;

    ull acc[RP][TN];
#pragma unroll
    for (int rp = 0; rp < RP; ++rp)
#pragma unroll
        for (int c = 0; c < TN; ++c) acc[rp][c] = 0ull;

    int ktiles = K >> 4;
    for (int t = 0; t < ktiles; ++t) {
        bool more = (t + 1 < ktiles);
        if (more) {
#pragma unroll
            for (int l = 0; l < NA; ++l) pa[l] = *(const float4*)(Ap + (size_t)(64 * l) * lda);
#pragma unroll
            for (int l = 0; l < NB; ++l) pb[l] = *(const float4*)(Bq + (size_t)(BROW * l) * ldb);
            Ap += 16;
            Bq += (size_t)16 * ldb;
        }

        int cb = t & 1;
#pragma unroll
        for (int k = 0; k < 16; ++k) {
            float4 av[TM / 4], bv[TN / 4];
#pragma unroll
            for (int v = 0; v < TM / 4; ++v) av[v] = *(const float4*)&As[cb][k][tr + 4 * v];
#pragma unroll
            for (int v = 0; v < TN / 4; ++v) bv[v] = *(const float4*)&Bs[cb][k][tc + 4 * v];
            ull apk[RP];
#pragma unroll
            for (int v = 0; v < TM / 4; ++v) {
                apk[2 * v + 0] = pk2(av[v].x, av[v].y);
                apk[2 * v + 1] = pk2(av[v].z, av[v].w);
            }
#pragma unroll
            for (int v = 0; v < TN / 4; ++v) {
                {
                    ull bb = pk2(bv[v].x, bv[v].x);
#pragma unroll
                    for (int rp = 0; rp < RP; ++rp) acc[rp][4 * v + 0] = fma2(apk[rp], bb, acc[rp][4 * v + 0]);
                }
                {
                    ull bb = pk2(bv[v].y, bv[v].y);
#pragma unroll
                    for (int rp = 0; rp < RP; ++rp) acc[rp][4 * v + 1] = fma2(apk[rp], bb, acc[rp][4 * v + 1]);
                }
                {
                    ull bb = pk2(bv[v].z, bv[v].z);
#pragma unroll
                    for (int rp = 0; rp < RP; ++rp) acc[rp][4 * v + 2] = fma2(apk[rp], bb, acc[rp][4 * v + 2]);
                }
                {
                    ull bb = pk2(bv[v].w, bv[v].w);
#pragma unroll
                    for (int rp = 0; rp < RP; ++rp) acc[rp][4 * v + 3] = fma2(apk[rp], bb, acc[rp][4 * v + 3]);
                }
            }
        }

        if (more) {
            int nb = (t + 1) & 1;
#pragma unroll
            for (int l = 0; l < NA; ++l) {
                int r = ar + 64 * l;
                As[nb][ac4 * 4 + 0][r] = pa[l].x;
                As[nb][ac4 * 4 + 1][r] = pa[l].y;
                As[nb][ac4 * 4 + 2][r] = pa[l].z;
                As[nb][ac4 * 4 + 3][r] = pa[l].w;
            }
#pragma unroll
            for (int l = 0; l < NB; ++l)
                *(float4*)&Bs[nb][bk + BROW * l][bc * 4] = pb[l];
        }
        __syncthreads();
    }

    float sc8[TN], bi8[TN];
    if (MODE == 2) {
#pragma unroll
        for (int c = 0; c < TN; ++c) { sc8[c] = scv[bn + tc + c]; bi8[c] = biv[bn + tc + c]; }
    }
    float w30[TN], w31[TN], w32[TN];
    if (MODE == 3) {
#pragma unroll
        for (int c = 0; c < TN; ++c) {
            int gc = bn + tc + c;
            w30[c] = W3[gc]; w31[c] = W3[ldc + gc]; w32[c] = W3[2 * ldc + gc];
        }
    }
#pragma unroll
    for (int rp = 0; rp < RP; ++rp) {
        int r0 = bm + tr + 2 * rp, r1 = r0 + 1;
        float o0[TN], o1[TN];
#pragma unroll
        for (int c = 0; c < TN; ++c) upk2(acc[rp][c], o0[c], o1[c]);
        if (MODE == 2) {
#pragma unroll
            for (int c = 0; c < TN; ++c) {
                o0[c] = fmaxf(fmaf(o0[c], sc8[c], bi8[c]), 0.f);
                o1[c] = fmaxf(fmaf(o1[c], sc8[c], bi8[c]), 0.f);
            }
        }
        if (MODE == 3) {
            float4 p0 = p4r[(size_t)r0 * rstride];
            float4 p1 = p4r[(size_t)r1 * rstride];
#pragma unroll
            for (int c = 0; c < TN; ++c) {
                o0[c] += fmaf(p0.x, w30[c], fmaf(p0.y, w31[c], p0.z * w32[c]));
                o1[c] += fmaf(p1.x, w30[c], fmaf(p1.y, w31[c], p1.z * w32[c]));
            }
        }
#pragma unroll
        for (int v = 0; v < TN / 4; ++v) {
            *(float4*)&C[(size_t)r0 * ldc + bn + tc + 4 * v] =
                make_float4(o0[4 * v], o0[4 * v + 1], o0[4 * v + 2], o0[4 * v + 3]);
            *(float4*)&C[(size_t)r1 * ldc + bn + tc + 4 * v] =
                make_float4(o1[4 * v], o1[4 * v + 1], o1[4 * v + 2], o1[4 * v + 3]);
        }
    }
}

// ----------------------------------------------------------------------------
// edge_conv1 fused (K=3, C=64). 4 points/block, 256 threads.
// ----------------------------------------------------------------------------
__global__ void edge1_kernel(const float4* __restrict__ p4,
                             const float* __restrict__ Wd, const float* __restrict__ Wb,
                             const int* __restrict__ idx,
                             const float* __restrict__ s, const float* __restrict__ b,
                             float* __restrict__ out) {
    __shared__ float4 pj[4][KNN];
    int g = threadIdx.x >> 6, c = threadIdx.x & 63;
    int i = blockIdx.x * 4 + g;
    if (c < KNN) pj[g][c] = p4[idx[i * KNN + c]];
    __syncthreads();
    float4 pi = p4[i];
    float w0 = Wd[c], w1 = Wd[64 + c], w2 = Wd[128 + c];
    float u0 = Wb[c], u1 = Wb[64 + c], u2 = Wb[128 + c];
    float a = fmaf(pi.x, w0, fmaf(pi.y, w1, pi.z * w2));
    float sc = s[c], bv = b[c];
    float m = 0.f;
#pragma unroll
    for (int k = 0; k < KNN; ++k) {
        float4 pp = pj[g][k];
        float e = fmaf(pp.x, u0, fmaf(pp.y, u1, fmaf(pp.z, u2, a)));
        m = fmaxf(m, fmaf(e, sc, bv));
    }
    out[(size_t)i * 64 + c] = m;
}

// ----------------------------------------------------------------------------
// edge_conv2 gather-max (C=128, float4): 4 points/block, 128 threads.
// ----------------------------------------------------------------------------
__global__ void gathermax_kernel(const float4* __restrict__ Aa, const float4* __restrict__ Bb,
                                 const int* __restrict__ idx,
                                 const float4* __restrict__ s, const float4* __restrict__ b,
                                 float4* __restrict__ out) {
    const int C4 = 32;
    __shared__ int js[4][KNN];
    int g = threadIdx.x >> 5, c = threadIdx.x & 31;
    int i = blockIdx.x * 4 + g;
    if (c < KNN) js[g][c] = idx[i * KNN + c];
    __syncthreads();
    float4 a = Aa[(size_t)i * C4 + c];
    float4 sc = s[c], bv = b[c];
    float4 m = make_float4(0.f, 0.f, 0.f, 0.f);
#pragma unroll
    for (int k = 0; k < KNN; ++k) {
        float4 bj = Bb[(size_t)js[g][k] * C4 + c];
        m.x = fmaxf(m.x, fmaf(a.x + bj.x, sc.x, bv.x));
        m.y = fmaxf(m.y, fmaf(a.y + bj.y, sc.y, bv.y));
        m.z = fmaxf(m.z, fmaf(a.z + bj.z, sc.z, bv.z));
        m.w = fmaxf(m.w, fmaf(a.w + bj.w, sc.w, bv.w));
    }
    out[(size_t)i * C4 + c] = m;
}

// ----------------------------------------------------------------------------
// graph attention, float4; NP points per block, D4 threads per point.
// ----------------------------------------------------------------------------
template <int D, int NP>
__global__ void attn_kernel(const float4* __restrict__ q, const float4* __restrict__ kk,
                            const float4* __restrict__ v, const int* __restrict__ idx,
                            const float4* __restrict__ s, const float4* __restrict__ b,
                            float4* __restrict__ out) {
    constexpr int D4 = D / 4;
    int tid = threadIdx.x;
    int g = tid / D4, t = tid % D4;
    int i = blockIdx.x * NP + g;
    __shared__ float4 qs[NP][D4];
    __shared__ float lg[NP][KNN];
    __shared__ float aw[NP][KNN];
    __shared__ int js[NP][KNN];
    qs[g][t] = q[(size_t)i * D4 + t];
    if (t < KNN) js[g][t] = idx[i * KNN + t];
    __syncthreads();

    constexpr int NW = D4 / 32;
    int w = t >> 5, lane = t & 31;
    for (int k = w; k < KNN; k += NW) {
        const float4* kr = kk + (size_t)js[g][k] * D4;
        float sum = 0.f;
#pragma unroll
        for (int m = lane; m < D4; m += 32) {
            float4 a = qs[g][m], c = kr[m];
            sum = fmaf(a.x, c.x, fmaf(a.y, c.y, fmaf(a.z, c.z, fmaf(a.w, c.w, sum))));
        }
#pragma unroll
        for (int o = 16; o; o >>= 1) sum += __shfl_xor_sync(0xffffffffu, sum, o);
        if (lane == 0) lg[g][k] = sum * (1.f / sqrtf((float)D));
    }
    __syncthreads();
    if (t < 32) {
        float l = (lane < KNN) ? lg[g][lane] : -FLT_MAX;
        float mx = l;
#pragma unroll
        for (int o = 16; o; o >>= 1) mx = fmaxf(mx, __shfl_xor_sync(0xffffffffu, mx, o));
        float e = (lane < KNN) ? expf(l - mx) : 0.f;
        float se = e;
#pragma unroll
        for (int o = 16; o; o >>= 1) se += __shfl_xor_sync(0xffffffffu, se, o);
        if (lane < KNN) aw[g][lane] = e / se;
    }
    __syncthreads();
    float4 y = make_float4(0.f, 0.f, 0.f, 0.f);
#pragma unroll
    for (int k = 0; k < KNN; ++k) {
        float a = aw[g][k];
        float4 vv = v[(size_t)js[g][k] * D4 + t];
        y.x = fmaf(a, vv.x, y.x); y.y = fmaf(a, vv.y, y.y);
        y.z = fmaf(a, vv.z, y.z); y.w = fmaf(a, vv.w, y.w);
    }
    float4 sc = s[t], bv = b[t];
    float4 r;
    r.x = fmaxf(fmaf(y.x, sc.x, bv.x), 0.f);
    r.y = fmaxf(fmaf(y.y, sc.y, bv.y), 0.f);
    r.z = fmaxf(fmaf(y.z, sc.z, bv.z), 0.f);
    r.w = fmaxf(fmaf(y.w, sc.w, bv.w), 0.f);
    out[(size_t)i * D4 + t] = r;
}

// ----------------------------------------------------------------------------
// K=3 row transform (PM: 2048 rows, stride-4 points)
// ----------------------------------------------------------------------------
__global__ void rows3_kernel(const float4* __restrict__ p4, int rstride,
                             const float* __restrict__ W, float* __restrict__ out, int ncols) {
    int i = blockIdx.x;
    int c = blockIdx.y * blockDim.x + threadIdx.x;
    float4 p = p4[(size_t)i * rstride];
    out[(size_t)i * ncols + c] = fmaf(p.x, W[c], fmaf(p.y, W[ncols + c], p.z * W[2 * ncols + c]));
}

// ----------------------------------------------------------------------------
// downsample gather-max (float4): 2 points/block, 256 threads; idx at stride 4.
// ----------------------------------------------------------------------------
__global__ void downgather_kernel(const float4* __restrict__ PX, const float4* __restrict__ Pm,
                                  const int* __restrict__ idx,
                                  const float4* __restrict__ s, const float4* __restrict__ b,
                                  float4* __restrict__ out) {
    __shared__ int js[2][KNN];
    int g = threadIdx.x >> 7, c = threadIdx.x & 127;
    int i = blockIdx.x * 2 + g;
    if (c < KNN) js[g][c] = idx[(4 * i) * KNN + c];
    __syncthreads();
    float4 pm = Pm[(size_t)i * 128 + c];
    float4 sc = s[c], bv = b[c];
    float4 m = make_float4(0.f, 0.f, 0.f, 0.f);
#pragma unroll
    for (int k = 0; k < KNN; ++k) {
        float4 px = PX[(size_t)js[g][k] * 128 + c];
        m.x = fmaxf(m.x, fmaf(px.x - pm.x, sc.x, bv.x));
        m.y = fmaxf(m.y, fmaf(px.y - pm.y, sc.y, bv.y));
        m.z = fmaxf(m.z, fmaf(px.z - pm.z, sc.z, bv.z));
        m.w = fmaxf(m.w, fmaf(px.w - pm.w, sc.w, bv.w));
    }
    out[(size_t)i * 128 + c] = m;
}

// column partial sums of xd [2048,512]: grid (4, 8), block 128.
__global__ void colsum_part_kernel(const float* __restrict__ xd, float* __restrict__ gs2) {
    int c = blockIdx.x * blockDim.x + threadIdx.x;
    int g = blockIdx.y;
    float s = 0.f;
    for (int r = g * 256; r < (g + 1) * 256; ++r) s += xd[(size_t)r * 512 + c];
    gs2[g * 512 + c] = s;
}

__global__ void colsum_reduce_kernel(const float* __restrict__ gs2, float* __restrict__ gsum) {
    int c = blockIdx.x * blockDim.x + threadIdx.x;
    float s = 0.f;
#pragma unroll
    for (int g = 0; g < 8; ++g) s += gs2[g * 512 + c];
    gsum[c] = s;
}

__global__ void beff_kernel(const float* __restrict__ gsum, const float* __restrict__ Wu2,
                            const float* __restrict__ su2, const float* __restrict__ bu1,
                            const float* __restrict__ bu2, float* __restrict__ be) {
    int c = threadIdx.x;
    float acc = 0.f;
    for (int d = 0; d < 512; ++d) acc = fmaf(gsum[d], Wu2[(size_t)d * 256 + c], acc);
    be[c] = bu1[c] + bu2[c] + su2[c] * (acc * (1.f / 2048.f));
}

__global__ void b2eff_kernel(const float* __restrict__ bc1, const float* __restrict__ scv,
                             const float* __restrict__ bcv, float* __restrict__ o) {
    int c = threadIdx.x;
    o[c] = fmaf(bc1[c], scv[c], bcv[c]);
}

__global__ void wdiff_kernel(const float* __restrict__ W, int half, float* __restrict__ Wd) {
    int t = blockIdx.x * blockDim.x + threadIdx.x;
    if (t < half) Wd[t] = W[t] - W[half + t];
}

__global__ void final_kernel(const float* __restrict__ h, const float* __restrict__ Wc2,
                             const float* __restrict__ bc2, float* __restrict__ out) {
    int t = blockIdx.x * blockDim.x + threadIdx.x;
    if (t >= NDOWN * 6) return;
    int i = t / 6, c = t % 6;
    float acc = bc2[c];
    for (int d = 0; d < 128; ++d) acc = fmaf(h[(size_t)i * 128 + d], Wc2[d * 6 + c], acc);
    out[t] = acc;
}

// ----------------------------------------------------------------------------
// launch
// ----------------------------------------------------------------------------
extern "C" void kernel_launch(void* const* d_in, const int* in_sizes, int n_in,
                              void* d_out, int out_size) {
    const float* points = (const float*)d_in[0];
    const float* We1 = (const float*)d_in[1];
    const float* se1 = (const float*)d_in[2];
    const float* be1 = (const float*)d_in[3];
    const float* We2 = (const float*)d_in[4];
    const float* se2 = (const float*)d_in[5];
    const float* be2 = (const float*)d_in[6];
    const float* Wq1 = (const float*)d_in[7];
    const float* Wk1 = (const float*)d_in[8];
    const float* Wv1 = (const float*)d_in[9];
    const float* sa1 = (const float*)d_in[10];
    const float* ba1 = (const float*)d_in[11];
    const float* Wq2 = (const float*)d_in[12];
    const float* Wk2 = (const float*)d_in[13];
    const float* Wv2 = (const float*)d_in[14];
    const float* sa2 = (const float*)d_in[15];
    const float* ba2 = (const float*)d_in[16];
    const float* Wtd = (const float*)d_in[17];
    const float* sd  = (const float*)d_in[18];
    const float* bd  = (const float*)d_in[19];
    const float* Wu1 = (const float*)d_in[20];
    const float* su1 = (const float*)d_in[21];
    const float* bu1 = (const float*)d_in[22];
    const float* Wu2 = (const float*)d_in[23];
    const float* su2 = (const float*)d_in[24];
    const float* bu2 = (const float*)d_in[25];
    const float* Wc1 = (const float*)d_in[26];
    const float* bc1 = (const float*)d_in[27];
    const float* scv = (const float*)d_in[28];
    const float* bcv = (const float*)d_in[29];
    const float* Wc2 = (const float*)d_in[30];
    const float* bc2 = (const float*)d_in[31];

    float* F = nullptr;
    int*   I = nullptr;
    cudaGetSymbolAddress((void**)&F, g_f);
    cudaGetSymbolAddress((void**)&I, g_i);

    float4* p4  = (float4*)(F + O_P4);
    float*  s1d = F + O_S1D;
    int*    s1i = I + OI_S1I;
    int*    idx = I + OI_IDX;

    // --- independent prologue (ordered so profiled slot 5 = knn_stage1) ---
    prep_p4_kernel<<<32, 128>>>(points, p4, 0);        // 0
    prep_p4_kernel<<<32, 128>>>(points, p4, 4096);     // 1
    wdiff_kernel<<<2, 128>>>(We1, 192, F + O_WD1);     // 2
    wdiff_kernel<<<64, 128>>>(We2, 8192, F + O_WD2);   // 3
    b2eff_kernel<<<1, 128>>>(bc1, scv, bcv, F + O_B2E);// 4

    // --- kNN (single full pass; downsampled rows are idx at stride 4) ---
    knn_stage1_kernel<<<dim3(NPTS / 128, CHUNKS), 128>>>(p4, s1d, s1i);  // 5 (profiled)
    knn_stage2_kernel<<<NPTS / 128, 128>>>(s1d, s1i, idx);

    // --- edge_conv 1 (fused, K=3, C=64) ---
    edge1_kernel<<<NPTS / 4, 256>>>(p4, F + O_WD1, We1 + 192, idx, se1, be1, F + O_X1);

    // --- edge_conv 2: C=128, batched A/B halves ---
    gemm_kernel<128, 128, 0><<<dim3(1, 64, 2), 256>>>(
        F + O_X1, 64, F + O_WD2, We2 + 8192, nullptr, 128,
        F + O_A2, F + O_B2, nullptr, 128, 64, nullptr, nullptr, nullptr, 0, nullptr);
    gathermax_kernel<<<NPTS / 4, 128>>>((const float4*)(F + O_A2), (const float4*)(F + O_B2), idx,
                                        (const float4*)se2, (const float4*)be2,
                                        (float4*)(F + O_X2));

    // --- graph_attn 1: D=256, q/k/v batched ---
    gemm_kernel<128, 128, 0><<<dim3(2, 64, 3), 256>>>(
        F + O_X2, 128, Wq1, Wk1, Wv1, 256,
        F + O_Q1, F + O_K1, F + O_V1, 256, 128, nullptr, nullptr, nullptr, 0, nullptr);
    attn_kernel<256, 4><<<NPTS / 4, 256>>>((const float4*)(F + O_Q1), (const float4*)(F + O_K1),
                                           (const float4*)(F + O_V1), idx,
                                           (const float4*)sa1, (const float4*)ba1,
                                           (float4*)(F + O_X3));

    // --- graph_attn 2: D=512, q/k/v batched ---
    gemm_kernel<128, 128, 0><<<dim3(4, 64, 3), 256>>>(
        F + O_X3, 256, Wq2, Wk2, Wv2, 512,
        F + O_Q2, F + O_K2, F + O_V2, 512, 256, nullptr, nullptr, nullptr, 0, nullptr);
    attn_kernel<512, 2><<<NPTS / 2, 256>>>((const float4*)(F + O_Q2), (const float4*)(F + O_K2),
                                           (const float4*)(F + O_V2), idx,
                                           (const float4*)sa2, (const float4*)ba2,
                                           (float4*)(F + O_X4));

    // --- downsample: PX = x4@Wtd[3:] + p@Wtd[0:3] (fused epilogue) ---
    gemm_kernel<128, 128, 3><<<dim3(4, 64, 1), 256>>>(
        F + O_X4, 512, Wtd + 3 * 512, nullptr, nullptr, 512,
        F + O_PX, nullptr, nullptr, 512, 512, nullptr, nullptr, p4, 1, Wtd);
    rows3_kernel<<<dim3(NDOWN, 4), 128>>>(p4, 4, Wtd, F + O_PM, 512);
    downgather_kernel<<<NDOWN / 2, 256>>>((const float4*)(F + O_PX), (const float4*)(F + O_PM), idx,
                                          (const float4*)sd, (const float4*)bd,
                                          (float4*)(F + O_XD));

    // --- global mean folded into bias; xu = relu(xd@Wu1*su1 + beff) ---
    colsum_part_kernel<<<dim3(4, 8), 128>>>(F + O_XD, F + O_GS2);
    colsum_reduce_kernel<<<4, 128>>>(F + O_GS2, F + O_GS);
    beff_kernel<<<1, 256>>>(F + O_GS, Wu2, su2, bu1, bu2, F + O_BE);
    gemm_kernel<64, 64, 2><<<dim3(4, 32, 1), 256>>>(
        F + O_XD, 512, Wu1, nullptr, nullptr, 256,
        F + O_XU, nullptr, nullptr, 256, 512, su1, F + O_BE, nullptr, 0, nullptr);

    // --- h = relu((xu@Wc1)*sc + (bc1*sc+bc)) ---
    gemm_kernel<64, 64, 2><<<dim3(2, 32, 1), 256>>>(
        F + O_XU, 256, Wc1, nullptr, nullptr, 128,
        F + O_H, nullptr, nullptr, 128, 256, scv, F + O_B2E, nullptr, 0, nullptr);

    // --- out = h@Wc2 + bc2 ---
    final_kernel<<<96, 128>>>(F + O_H, Wc2, bc2, (float*)d_out);
}

// round 6
// speedup vs baseline: 1.7098x; 1.2180x over previous
#include <cuda_runtime.h>
#include <math.h>
#include <float.h>

#define NPTS   8192
#define NDOWN  2048
#define KNN    16
#define CHUNKS 16

// ----------------------------------------------------------------------------
// Scratch arenas (no cudaMalloc allowed).
// ----------------------------------------------------------------------------
__device__ float g_f[40200000];
__device__ int   g_i[2400000];

static const size_t O_A1  = 0;
static const size_t O_B1  = O_A1  + (size_t)8192*64;
static const size_t O_X1  = O_B1  + (size_t)8192*64;
static const size_t O_A2  = O_X1  + (size_t)8192*64;
static const size_t O_B2  = O_A2  + (size_t)8192*128;
static const size_t O_X2  = O_B2  + (size_t)8192*128;
static const size_t O_Q1  = O_X2  + (size_t)8192*128;
static const size_t O_K1  = O_Q1  + (size_t)8192*256;
static const size_t O_V1  = O_K1  + (size_t)8192*256;
static const size_t O_X3  = O_V1  + (size_t)8192*256;
static const size_t O_Q2  = O_X3  + (size_t)8192*256;
static const size_t O_K2  = O_Q2  + (size_t)8192*512;
static const size_t O_V2  = O_K2  + (size_t)8192*512;
static const size_t O_X4  = O_V2  + (size_t)8192*512;
static const size_t O_PX  = O_X4  + (size_t)8192*512;
static const size_t O_PM  = O_PX  + (size_t)8192*512;
static const size_t O_XD  = O_PM  + (size_t)2048*512;
static const size_t O_XU  = O_XD  + (size_t)2048*512;
static const size_t O_H   = O_XU  + (size_t)2048*256;
static const size_t O_GS  = O_H   + (size_t)2048*128;   // 512
static const size_t O_BE  = O_GS  + 512;                // 256
static const size_t O_B2E = O_BE  + 256;                // 128
static const size_t O_WD1 = O_B2E + 128;                // 192
static const size_t O_WD2 = O_WD1 + 192;                // 8192
static const size_t O_P4  = O_WD2 + 8192;               // 8192*4
static const size_t O_S1D = O_P4  + (size_t)8192*4;     // 8192*256
static const size_t O_GS2 = O_S1D + (size_t)8192*256;   // 4096

static const size_t OI_IDX  = 0;                          // 8192*16
static const size_t OI_S1I  = (size_t)8192*16;            // 8192*256

// ----------------------------------------------------------------------------
// f32x2 helpers (for the small 64x64 GEMMs)
// ----------------------------------------------------------------------------
typedef unsigned long long ull;

__device__ __forceinline__ ull pk2(float lo, float hi) {
    ull r; asm("mov.b64 %0,{%1,%2};" : "=l"(r) : "f"(lo), "f"(hi)); return r;
}
__device__ __forceinline__ ull fma2(ull a, ull b, ull c) {
    ull d; asm("fma.rn.f32x2 %0,%1,%2,%3;" : "=l"(d) : "l"(a), "l"(b), "l"(c)); return d;
}
__device__ __forceinline__ void upk2(ull v, float& lo, float& hi) {
    asm("mov.b64 {%0,%1},%2;" : "=f"(lo), "=f"(hi) : "l"(v));
}

__device__ __forceinline__ unsigned tf32cvt(float f) {
    unsigned r; asm("cvt.rna.tf32.f32 %0,%1;" : "=r"(r) : "f"(f)); return r;
}

// ----------------------------------------------------------------------------
// kNN (single pass; downsampled rows are idx at stride 4)
// ----------------------------------------------------------------------------
__device__ __forceinline__ void replace_rescan(float s, int j, float (&d)[KNN], int (&id)[KNN],
                                               float& wval, int& wpos) {
#pragma unroll
    for (int t = 0; t < KNN; ++t) if (t == wpos) { d[t] = s; id[t] = j; }
    wval = d[0]; wpos = 0;
#pragma unroll
    for (int t = 1; t < KNN; ++t) if (d[t] > wval) { wval = d[t]; wpos = t; }
}

__global__ void prep_p4_kernel(const float* __restrict__ p, float4* __restrict__ p4, int base) {
    int i = base + blockIdx.x * blockDim.x + threadIdx.x;
    if (i < NPTS) {
        float x = p[3 * i], y = p[3 * i + 1], z = p[3 * i + 2];
        p4[i] = make_float4(x, y, z, x * x + y * y + z * z);
    }
}

__global__ void knn_stage1_kernel(const float4* __restrict__ p4,
                                  float* __restrict__ s1d, int* __restrict__ s1i) {
    const int CH = NPTS / CHUNKS;  // 512
    int q  = blockIdx.x * blockDim.x + threadIdx.x;
    int c0 = blockIdx.y * CH;

    float4 qp = p4[q];
    float qx = -2.f * qp.x, qy = -2.f * qp.y, qz = -2.f * qp.z;

    __shared__ float4 tile[512];
#pragma unroll
    for (int l = 0; l < 4; ++l) tile[threadIdx.x + l * 128] = p4[c0 + threadIdx.x + l * 128];
    __syncthreads();

    float d[KNN]; int id[KNN];
#pragma unroll
    for (int t = 0; t < KNN; ++t) {
        float4 c = tile[t];
        d[t] = fmaf(qx, c.x, fmaf(qy, c.y, fmaf(qz, c.z, c.w)));
        id[t] = c0 + t;
    }
    float wval = d[0]; int wpos = 0;
#pragma unroll
    for (int t = 1; t < KNN; ++t) if (d[t] > wval) { wval = d[t]; wpos = t; }

    float bs0 = 0.f, bs1 = 0.f, bs2 = 0.f, bs3 = 0.f;
    int   bj0 = 0, bj1 = 0, bj2 = 0, bj3 = 0, cnt = 0;

    for (int i = KNN; i < CH; ++i) {
        float4 c = tile[i];
        float s = fmaf(qx, c.x, fmaf(qy, c.y, fmaf(qz, c.z, c.w)));
        if (s < wval) {
            int j = c0 + i;
            if (cnt == 0)      { bs0 = s; bj0 = j; }
            else if (cnt == 1) { bs1 = s; bj1 = j; }
            else if (cnt == 2) { bs2 = s; bj2 = j; }
            else               { bs3 = s; bj3 = j; }
            cnt++;
        }
        if (__any_sync(0xffffffffu, cnt == 4)) {
            if (cnt > 0 && bs0 < wval) replace_rescan(bs0, bj0, d, id, wval, wpos);
            if (cnt > 1 && bs1 < wval) replace_rescan(bs1, bj1, d, id, wval, wpos);
            if (cnt > 2 && bs2 < wval) replace_rescan(bs2, bj2, d, id, wval, wpos);
            if (cnt > 3 && bs3 < wval) replace_rescan(bs3, bj3, d, id, wval, wpos);
            cnt = 0;
        }
    }
    if (cnt > 0 && bs0 < wval) replace_rescan(bs0, bj0, d, id, wval, wpos);
    if (cnt > 1 && bs1 < wval) replace_rescan(bs1, bj1, d, id, wval, wpos);
    if (cnt > 2 && bs2 < wval) replace_rescan(bs2, bj2, d, id, wval, wpos);
    if (cnt > 3 && bs3 < wval) replace_rescan(bs3, bj3, d, id, wval, wpos);

    size_t o = ((size_t)q * CHUNKS + blockIdx.y) * KNN;
#pragma unroll
    for (int t = 0; t < KNN; ++t) { s1d[o + t] = d[t]; s1i[o + t] = id[t]; }
}

__global__ void knn_stage2_kernel(const float* __restrict__ s1d, const int* __restrict__ s1i,
                                  int* __restrict__ outidx) {
    int q = blockIdx.x * blockDim.x + threadIdx.x;
    size_t base = (size_t)q * (CHUNKS * KNN);
    float d[KNN]; int id[KNN];
#pragma unroll
    for (int t = 0; t < KNN; ++t) { d[t] = s1d[base + t]; id[t] = s1i[base + t]; }
    float wval = d[0]; int wpos = 0;
#pragma unroll
    for (int t = 1; t < KNN; ++t) if (d[t] > wval) { wval = d[t]; wpos = t; }
    for (int c = KNN; c < CHUNKS * KNN; ++c) {
        float s = s1d[base + c];
        if (s < wval) replace_rescan(s, s1i[base + c], d, id, wval, wpos);
    }
#pragma unroll
    for (int t = 0; t < KNN; ++t) outidx[q * KNN + t] = id[t];
}

// ----------------------------------------------------------------------------
// Tensor-core GEMM (tf32 mma.sync.m16n8k8): C[M,N] = A[M,K] @ B[K,N].
// 128x128x16 tiles, 256 thr = 8 warps (2m x 4n), warp = 64x32.
// A/B staged in smem pre-converted to tf32, double-buffered.
// MODE 0: store. MODE 3: acc + p@W3 rows (row ld = ldc).
// M%128==0, N%128==0, K%16==0 required.
// ----------------------------------------------------------------------------
#define SP 132  // smem row pad (floats)

template <int MODE>
__global__ __launch_bounds__(256, 2)
void mma_gemm_kernel(const float* __restrict__ A, int lda,
                     const float* __restrict__ Bp0, const float* __restrict__ Bp1,
                     const float* __restrict__ Bp2, int ldb,
                     float* __restrict__ Cp0, float* __restrict__ Cp1,
                     float* __restrict__ Cp2, int ldc, int K,
                     const float* __restrict__ scv, const float* __restrict__ biv,
                     const float4* __restrict__ p4r, int rstride,
                     const float* __restrict__ W3) {
    __shared__ __align__(16) unsigned As[2][16][SP];
    __shared__ __align__(16) unsigned Bs[2][16][SP];

    const float* B = (blockIdx.z == 0) ? Bp0 : (blockIdx.z == 1) ? Bp1 : Bp2;
    float*       C = (blockIdx.z == 0) ? Cp0 : (blockIdx.z == 1) ? Cp1 : Cp2;

    int tid = threadIdx.x;
    int bm = blockIdx.y * 128, bn = blockIdx.x * 128;

    // loaders
    int ar = tid >> 2, ac4 = tid & 3;          // A: rows ar, ar+64; cols ac4*4..+3
    int bk = tid >> 5, bc = tid & 31;          // B: k-rows bk, bk+8; col group bc
    const float* Ap = A + (size_t)(bm + ar) * lda + ac4 * 4;
    const float* Bq = B + (size_t)bk * ldb + bn + bc * 4;

    float4 pa0, pa1, pb0, pb1;
    pa0 = *(const float4*)Ap;
    pa1 = *(const float4*)(Ap + (size_t)64 * lda);
    pb0 = *(const float4*)Bq;
    pb1 = *(const float4*)(Bq + (size_t)8 * ldb);
    Ap += 16;
    Bq += (size_t)16 * ldb;

    // stage tile 0
    {
        As[0][ac4 * 4 + 0][ar] = tf32cvt(pa0.x);
        As[0][ac4 * 4 + 1][ar] = tf32cvt(pa0.y);
        As[0][ac4 * 4 + 2][ar] = tf32cvt(pa0.z);
        As[0][ac4 * 4 + 3][ar] = tf32cvt(pa0.w);
        As[0][ac4 * 4 + 0][ar + 64] = tf32cvt(pa1.x);
        As[0][ac4 * 4 + 1][ar + 64] = tf32cvt(pa1.y);
        As[0][ac4 * 4 + 2][ar + 64] = tf32cvt(pa1.z);
        As[0][ac4 * 4 + 3][ar + 64] = tf32cvt(pa1.w);
        uint4 t0 = make_uint4(tf32cvt(pb0.x), tf32cvt(pb0.y), tf32cvt(pb0.z), tf32cvt(pb0.w));
        uint4 t1 = make_uint4(tf32cvt(pb1.x), tf32cvt(pb1.y), tf32cvt(pb1.z), tf32cvt(pb1.w));
        *(uint4*)&Bs[0][bk][bc * 4] = t0;
        *(uint4*)&Bs[0][bk + 8][bc * 4] = t1;
    }
    __syncthreads();

    int lane = tid & 31, wid = tid >> 5;
    int wm = (wid & 1) * 64;       // warp m offset
    int wn = (wid >> 1) * 32;      // warp n offset
    int grp = lane >> 2, qid = lane & 3;

    float acc[4][4][4];
#pragma unroll
    for (int tm = 0; tm < 4; ++tm)
#pragma unroll
        for (int tn = 0; tn < 4; ++tn)
#pragma unroll
            for (int c = 0; c < 4; ++c) acc[tm][tn][c] = 0.f;

    int ktiles = K >> 4;
    for (int t = 0; t < ktiles; ++t) {
        bool more = (t + 1 < ktiles);
        if (more) {
            pa0 = *(const float4*)Ap;
            pa1 = *(const float4*)(Ap + (size_t)64 * lda);
            pb0 = *(const float4*)Bq;
            pb1 = *(const float4*)(Bq + (size_t)8 * ldb);
            Ap += 16;
            Bq += (size_t)16 * ldb;
        }

        int cb = t & 1;
#pragma unroll
        for (int kh = 0; kh < 2; ++kh) {
            int k0 = kh * 8;
            unsigned af[4][4], bf[4][2];
#pragma unroll
            for (int tm = 0; tm < 4; ++tm) {
                int m0 = wm + tm * 16 + grp;
                af[tm][0] = As[cb][k0 + qid][m0];
                af[tm][1] = As[cb][k0 + qid][m0 + 8];
                af[tm][2] = As[cb][k0 + qid + 4][m0];
                af[tm][3] = As[cb][k0 + qid + 4][m0 + 8];
            }
#pragma unroll
            for (int tn = 0; tn < 4; ++tn) {
                int n0 = wn + tn * 8 + grp;
                bf[tn][0] = Bs[cb][k0 + qid][n0];
                bf[tn][1] = Bs[cb][k0 + qid + 4][n0];
            }
#pragma unroll
            for (int tm = 0; tm < 4; ++tm)
#pragma unroll
                for (int tn = 0; tn < 4; ++tn) {
                    asm volatile(
                        "mma.sync.aligned.m16n8k8.row.col.f32.tf32.tf32.f32 "
                        "{%0,%1,%2,%3},{%4,%5,%6,%7},{%8,%9},{%0,%1,%2,%3};"
                        : "+f"(acc[tm][tn][0]), "+f"(acc[tm][tn][1]),
                          "+f"(acc[tm][tn][2]), "+f"(acc[tm][tn][3])
                        : "r"(af[tm][0]), "r"(af[tm][1]), "r"(af[tm][2]), "r"(af[tm][3]),
                          "r"(bf[tn][0]), "r"(bf[tn][1]));
                }
        }

        if (more) {
            int nb = (t + 1) & 1;
            As[nb][ac4 * 4 + 0][ar] = tf32cvt(pa0.x);
            As[nb][ac4 * 4 + 1][ar] = tf32cvt(pa0.y);
            As[nb][ac4 * 4 + 2][ar] = tf32cvt(pa0.z);
            As[nb][ac4 * 4 + 3][ar] = tf32cvt(pa0.w);
            As[nb][ac4 * 4 + 0][ar + 64] = tf32cvt(pa1.x);
            As[nb][ac4 * 4 + 1][ar + 64] = tf32cvt(pa1.y);
            As[nb][ac4 * 4 + 2][ar + 64] = tf32cvt(pa1.z);
            As[nb][ac4 * 4 + 3][ar + 64] = tf32cvt(pa1.w);
            uint4 t0 = make_uint4(tf32cvt(pb0.x), tf32cvt(pb0.y), tf32cvt(pb0.z), tf32cvt(pb0.w));
            uint4 t1 = make_uint4(tf32cvt(pb1.x), tf32cvt(pb1.y), tf32cvt(pb1.z), tf32cvt(pb1.w));
            *(uint4*)&Bs[nb][bk][bc * 4] = t0;
            *(uint4*)&Bs[nb][bk + 8][bc * 4] = t1;
        }
        __syncthreads();
    }

    // epilogue
#pragma unroll
    for (int tm = 0; tm < 4; ++tm) {
        int r0 = bm + wm + tm * 16 + grp;
        int r1 = r0 + 8;
        float px0 = 0.f, px1 = 0.f;   // per-row p@W3 lazily per column below
        float4 p0, p1;
        if (MODE == 3) {
            p0 = p4r[(size_t)r0 * rstride];
            p1 = p4r[(size_t)r1 * rstride];
        }
#pragma unroll
        for (int tn = 0; tn < 4; ++tn) {
            int col = bn + wn + tn * 8 + 2 * qid;
            float c0 = acc[tm][tn][0], c1 = acc[tm][tn][1];
            float c2 = acc[tm][tn][2], c3 = acc[tm][tn][3];
            if (MODE == 3) {
                float wa0 = W3[col],           wa1 = W3[col + 1];
                float wb0 = W3[ldc + col],     wb1 = W3[ldc + col + 1];
                float wc0 = W3[2 * ldc + col], wc1 = W3[2 * ldc + col + 1];
                c0 += fmaf(p0.x, wa0, fmaf(p0.y, wb0, p0.z * wc0));
                c1 += fmaf(p0.x, wa1, fmaf(p0.y, wb1, p0.z * wc1));
                c2 += fmaf(p1.x, wa0, fmaf(p1.y, wb0, p1.z * wc0));
                c3 += fmaf(p1.x, wa1, fmaf(p1.y, wb1, p1.z * wc1));
            }
            *(float2*)&C[(size_t)r0 * ldc + col] = make_float2(c0, c1);
            *(float2*)&C[(size_t)r1 * ldc + col] = make_float2(c2, c3);
        }
        (void)px0; (void)px1;
    }
}

// ----------------------------------------------------------------------------
// f32x2 GEMM for the small 64x64-tile layers (MODE 2: relu(acc*s+b)).
// ----------------------------------------------------------------------------
template <int BM, int BN, int MODE>
__global__ __launch_bounds__(256, 2)
void gemm_kernel(const float* __restrict__ A, int lda,
                 const float* __restrict__ Bp0, int ldb,
                 float* __restrict__ Cp0, int ldc, int K,
                 const float* __restrict__ scv, const float* __restrict__ biv) {
    constexpr int TM = BM / 16;
    constexpr int TN = BN / 16;
    constexpr int RP = TM / 2;
    constexpr int NA = BM / 64;
    constexpr int NB = BN / 64;
    constexpr int F4R = BN / 4;
    constexpr int BROW = 256 / F4R;

    __shared__ __align__(16) float As[2][16][BM + 4];
    __shared__ __align__(16) float Bs[2][16][BN];

    const float* B = Bp0;
    float*       C = Cp0;

    int tid = threadIdx.x;
    int bm = blockIdx.y * BM, bn = blockIdx.x * BN;

    int ar = tid >> 2, ac4 = tid & 3;
    int bk = tid / F4R, bc = tid % F4R;

    const float* Ap = A + (size_t)(bm + ar) * lda + ac4 * 4;
    const float* Bq = B + (size_t)bk * ldb + bn + bc * 4;

    float4 pa[NA], pb[NB];
#pragma unroll
    for (int l = 0; l < NA; ++l) pa[l] = *(const float4*)(Ap + (size_t)(64 * l) * lda);
#pragma unroll
    for (int l = 0; l < NB; ++l) pb[l] = *(const float4*)(Bq + (size_t)(BROW * l) * ldb);
    Ap += 16;
    Bq += (size_t)16 * ldb;

#pragma unroll
    for (int l = 0; l < NA; ++l) {
        int r = ar + 64 * l;
        As[0][ac4 * 4 + 0][r] = pa[l].x;
        As[0][ac4 * 4 + 1][r] = pa[l].y;
        As[0][ac4 * 4 + 2][r] = pa[l].z;
        As[0][ac4 * 4 + 3][r] = pa[l].w;
    }
#pragma unroll
    for (int l = 0; l < NB; ++l)
        *(float4*)&Bs[0][bk + BROW * l][bc * 4] = pb[l];
    __syncthreads();

    int tr = (tid >> 4) * TM;
    int tc = (tid & 15) * TN;

    ull acc[RP][TN];
#pragma unroll
    for (int rp = 0; rp < RP; ++rp)
#pragma unroll
        for (int c = 0; c < TN; ++c) acc[rp][c] = 0ull;

    int ktiles = K >> 4;
    for (int t = 0; t < ktiles; ++t) {
        bool more = (t + 1 < ktiles);
        if (more) {
#pragma unroll
            for (int l = 0; l < NA; ++l) pa[l] = *(const float4*)(Ap + (size_t)(64 * l) * lda);
#pragma unroll
            for (int l = 0; l < NB; ++l) pb[l] = *(const float4*)(Bq + (size_t)(BROW * l) * ldb);
            Ap += 16;
            Bq += (size_t)16 * ldb;
        }

        int cb = t & 1;
#pragma unroll
        for (int k = 0; k < 16; ++k) {
            float4 av[TM / 4], bv[TN / 4];
#pragma unroll
            for (int v = 0; v < TM / 4; ++v) av[v] = *(const float4*)&As[cb][k][tr + 4 * v];
#pragma unroll
            for (int v = 0; v < TN / 4; ++v) bv[v] = *(const float4*)&Bs[cb][k][tc + 4 * v];
            ull apk[RP];
#pragma unroll
            for (int v = 0; v < TM / 4; ++v) {
                apk[2 * v + 0] = pk2(av[v].x, av[v].y);
                apk[2 * v + 1] = pk2(av[v].z, av[v].w);
            }
#pragma unroll
            for (int v = 0; v < TN / 4; ++v) {
                {
                    ull bb = pk2(bv[v].x, bv[v].x);
#pragma unroll
                    for (int rp = 0; rp < RP; ++rp) acc[rp][4 * v + 0] = fma2(apk[rp], bb, acc[rp][4 * v + 0]);
                }
                {
                    ull bb = pk2(bv[v].y, bv[v].y);
#pragma unroll
                    for (int rp = 0; rp < RP; ++rp) acc[rp][4 * v + 1] = fma2(apk[rp], bb, acc[rp][4 * v + 1]);
                }
                {
                    ull bb = pk2(bv[v].z, bv[v].z);
#pragma unroll
                    for (int rp = 0; rp < RP; ++rp) acc[rp][4 * v + 2] = fma2(apk[rp], bb, acc[rp][4 * v + 2]);
                }
                {
                    ull bb = pk2(bv[v].w, bv[v].w);
#pragma unroll
                    for (int rp = 0; rp < RP; ++rp) acc[rp][4 * v + 3] = fma2(apk[rp], bb, acc[rp][4 * v + 3]);
                }
            }
        }

        if (more) {
            int nb = (t + 1) & 1;
#pragma unroll
            for (int l = 0; l < NA; ++l) {
                int r = ar + 64 * l;
                As[nb][ac4 * 4 + 0][r] = pa[l].x;
                As[nb][ac4 * 4 + 1][r] = pa[l].y;
                As[nb][ac4 * 4 + 2][r] = pa[l].z;
                As[nb][ac4 * 4 + 3][r] = pa[l].w;
            }
#pragma unroll
            for (int l = 0; l < NB; ++l)
                *(float4*)&Bs[nb][bk + BROW * l][bc * 4] = pb[l];
        }
        __syncthreads();
    }

    float sc8[TN], bi8[TN];
    if (MODE == 2) {
#pragma unroll
        for (int c = 0; c < TN; ++c) { sc8[c] = scv[bn + tc + c]; bi8[c] = biv[bn + tc + c]; }
    }
#pragma unroll
    for (int rp = 0; rp < RP; ++rp) {
        int r0 = bm + tr + 2 * rp, r1 = r0 + 1;
        float o0[TN], o1[TN];
#pragma unroll
        for (int c = 0; c < TN; ++c) upk2(acc[rp][c], o0[c], o1[c]);
        if (MODE == 2) {
#pragma unroll
            for (int c = 0; c < TN; ++c) {
                o0[c] = fmaxf(fmaf(o0[c], sc8[c], bi8[c]), 0.f);
                o1[c] = fmaxf(fmaf(o1[c], sc8[c], bi8[c]), 0.f);
            }
        }
#pragma unroll
        for (int v = 0; v < TN / 4; ++v) {
            *(float4*)&C[(size_t)r0 * ldc + bn + tc + 4 * v] =
                make_float4(o0[4 * v], o0[4 * v + 1], o0[4 * v + 2], o0[4 * v + 3]);
            *(float4*)&C[(size_t)r1 * ldc + bn + tc + 4 * v] =
                make_float4(o1[4 * v], o1[4 * v + 1], o1[4 * v + 2], o1[4 * v + 3]);
        }
    }
}

// ----------------------------------------------------------------------------
// edge_conv1 fused (K=3, C=64). 4 points/block, 256 threads.
// ----------------------------------------------------------------------------
__global__ void edge1_kernel(const float4* __restrict__ p4,
                             const float* __restrict__ Wd, const float* __restrict__ Wb,
                             const int* __restrict__ idx,
                             const float* __restrict__ s, const float* __restrict__ b,
                             float* __restrict__ out) {
    __shared__ float4 pj[4][KNN];
    int g = threadIdx.x >> 6, c = threadIdx.x & 63;
    int i = blockIdx.x * 4 + g;
    if (c < KNN) pj[g][c] = p4[idx[i * KNN + c]];
    __syncthreads();
    float4 pi = p4[i];
    float w0 = Wd[c], w1 = Wd[64 + c], w2 = Wd[128 + c];
    float u0 = Wb[c], u1 = Wb[64 + c], u2 = Wb[128 + c];
    float a = fmaf(pi.x, w0, fmaf(pi.y, w1, pi.z * w2));
    float sc = s[c], bv = b[c];
    float m = 0.f;
#pragma unroll
    for (int k = 0; k < KNN; ++k) {
        float4 pp = pj[g][k];
        float e = fmaf(pp.x, u0, fmaf(pp.y, u1, fmaf(pp.z, u2, a)));
        m = fmaxf(m, fmaf(e, sc, bv));
    }
    out[(size_t)i * 64 + c] = m;
}

// ----------------------------------------------------------------------------
// edge_conv2 gather-max (C=128, float4): 4 points/block, 128 threads.
// ----------------------------------------------------------------------------
__global__ void gathermax_kernel(const float4* __restrict__ Aa, const float4* __restrict__ Bb,
                                 const int* __restrict__ idx,
                                 const float4* __restrict__ s, const float4* __restrict__ b,
                                 float4* __restrict__ out) {
    const int C4 = 32;
    __shared__ int js[4][KNN];
    int g = threadIdx.x >> 5, c = threadIdx.x & 31;
    int i = blockIdx.x * 4 + g;
    if (c < KNN) js[g][c] = idx[i * KNN + c];
    __syncthreads();
    float4 a = Aa[(size_t)i * C4 + c];
    float4 sc = s[c], bv = b[c];
    float4 m = make_float4(0.f, 0.f, 0.f, 0.f);
#pragma unroll
    for (int k = 0; k < KNN; ++k) {
        float4 bj = Bb[(size_t)js[g][k] * C4 + c];
        m.x = fmaxf(m.x, fmaf(a.x + bj.x, sc.x, bv.x));
        m.y = fmaxf(m.y, fmaf(a.y + bj.y, sc.y, bv.y));
        m.z = fmaxf(m.z, fmaf(a.z + bj.z, sc.z, bv.z));
        m.w = fmaxf(m.w, fmaf(a.w + bj.w, sc.w, bv.w));
    }
    out[(size_t)i * C4 + c] = m;
}

// ----------------------------------------------------------------------------
// graph attention, float4; NP points per block, D4 threads per point.
// ----------------------------------------------------------------------------
template <int D, int NP>
__global__ void attn_kernel(const float4* __restrict__ q, const float4* __restrict__ kk,
                            const float4* __restrict__ v, const int* __restrict__ idx,
                            const float4* __restrict__ s, const float4* __restrict__ b,
                            float4* __restrict__ out) {
    constexpr int D4 = D / 4;
    int tid = threadIdx.x;
    int g = tid / D4, t = tid % D4;
    int i = blockIdx.x * NP + g;
    __shared__ float4 qs[NP][D4];
    __shared__ float lg[NP][KNN];
    __shared__ float aw[NP][KNN];
    __shared__ int js[NP][KNN];
    qs[g][t] = q[(size_t)i * D4 + t];
    if (t < KNN) js[g][t] = idx[i * KNN + t];
    __syncthreads();

    constexpr int NW = D4 / 32;
    int w = t >> 5, lane = t & 31;
    for (int k = w; k < KNN; k += NW) {
        const float4* kr = kk + (size_t)js[g][k] * D4;
        float sum = 0.f;
#pragma unroll
        for (int m = lane; m < D4; m += 32) {
            float4 a = qs[g][m], c = kr[m];
            sum = fmaf(a.x, c.x, fmaf(a.y, c.y, fmaf(a.z, c.z, fmaf(a.w, c.w, sum))));
        }
#pragma unroll
        for (int o = 16; o; o >>= 1) sum += __shfl_xor_sync(0xffffffffu, sum, o);
        if (lane == 0) lg[g][k] = sum * (1.f / sqrtf((float)D));
    }
    __syncthreads();
    if (t < 32) {
        float l = (lane < KNN) ? lg[g][lane] : -FLT_MAX;
        float mx = l;
#pragma unroll
        for (int o = 16; o; o >>= 1) mx = fmaxf(mx, __shfl_xor_sync(0xffffffffu, mx, o));
        float e = (lane < KNN) ? expf(l - mx) : 0.f;
        float se = e;
#pragma unroll
        for (int o = 16; o; o >>= 1) se += __shfl_xor_sync(0xffffffffu, se, o);
        if (lane < KNN) aw[g][lane] = e / se;
    }
    __syncthreads();
    float4 y = make_float4(0.f, 0.f, 0.f, 0.f);
#pragma unroll
    for (int k = 0; k < KNN; ++k) {
        float a = aw[g][k];
        float4 vv = v[(size_t)js[g][k] * D4 + t];
        y.x = fmaf(a, vv.x, y.x); y.y = fmaf(a, vv.y, y.y);
        y.z = fmaf(a, vv.z, y.z); y.w = fmaf(a, vv.w, y.w);
    }
    float4 sc = s[t], bv = b[t];
    float4 r;
    r.x = fmaxf(fmaf(y.x, sc.x, bv.x), 0.f);
    r.y = fmaxf(fmaf(y.y, sc.y, bv.y), 0.f);
    r.z = fmaxf(fmaf(y.z, sc.z, bv.z), 0.f);
    r.w = fmaxf(fmaf(y.w, sc.w, bv.w), 0.f);
    out[(size_t)i * D4 + t] = r;
}

// ----------------------------------------------------------------------------
// K=3 row transform (PM: 2048 rows, stride-4 points)
// ----------------------------------------------------------------------------
__global__ void rows3_kernel(const float4* __restrict__ p4, int rstride,
                             const float* __restrict__ W, float* __restrict__ out, int ncols) {
    int i = blockIdx.x;
    int c = blockIdx.y * blockDim.x + threadIdx.x;
    float4 p = p4[(size_t)i * rstride];
    out[(size_t)i * ncols + c] = fmaf(p.x, W[c], fmaf(p.y, W[ncols + c], p.z * W[2 * ncols + c]));
}

// ----------------------------------------------------------------------------
// downsample gather-max (float4): 2 points/block, 256 threads; idx at stride 4.
// ----------------------------------------------------------------------------
__global__ void downgather_kernel(const float4* __restrict__ PX, const float4* __restrict__ Pm,
                                  const int* __restrict__ idx,
                                  const float4* __restrict__ s, const float4* __restrict__ b,
                                  float4* __restrict__ out) {
    __shared__ int js[2][KNN];
    int g = threadIdx.x >> 7, c = threadIdx.x & 127;
    int i = blockIdx.x * 2 + g;
    if (c < KNN) js[g][c] = idx[(4 * i) * KNN + c];
    __syncthreads();
    float4 pm = Pm[(size_t)i * 128 + c];
    float4 sc = s[c], bv = b[c];
    float4 m = make_float4(0.f, 0.f, 0.f, 0.f);
#pragma unroll
    for (int k = 0; k < KNN; ++k) {
        float4 px = PX[(size_t)js[g][k] * 128 + c];
        m.x = fmaxf(m.x, fmaf(px.x - pm.x, sc.x, bv.x));
        m.y = fmaxf(m.y, fmaf(px.y - pm.y, sc.y, bv.y));
        m.z = fmaxf(m.z, fmaf(px.z - pm.z, sc.z, bv.z));
        m.w = fmaxf(m.w, fmaf(px.w - pm.w, sc.w, bv.w));
    }
    out[(size_t)i * 128 + c] = m;
}

__global__ void colsum_part_kernel(const float* __restrict__ xd, float* __restrict__ gs2) {
    int c = blockIdx.x * blockDim.x + threadIdx.x;
    int g = blockIdx.y;
    float s = 0.f;
    for (int r = g * 256; r < (g + 1) * 256; ++r) s += xd[(size_t)r * 512 + c];
    gs2[g * 512 + c] = s;
}

__global__ void colsum_reduce_kernel(const float* __restrict__ gs2, float* __restrict__ gsum) {
    int c = blockIdx.x * blockDim.x + threadIdx.x;
    float s = 0.f;
#pragma unroll
    for (int g = 0; g < 8; ++g) s += gs2[g * 512 + c];
    gsum[c] = s;
}

__global__ void beff_kernel(const float* __restrict__ gsum, const float* __restrict__ Wu2,
                            const float* __restrict__ su2, const float* __restrict__ bu1,
                            const float* __restrict__ bu2, float* __restrict__ be) {
    int c = threadIdx.x;
    float acc = 0.f;
    for (int d = 0; d < 512; ++d) acc = fmaf(gsum[d], Wu2[(size_t)d * 256 + c], acc);
    be[c] = bu1[c] + bu2[c] + su2[c] * (acc * (1.f / 2048.f));
}

__global__ void b2eff_kernel(const float* __restrict__ bc1, const float* __restrict__ scv,
                             const float* __restrict__ bcv, float* __restrict__ o) {
    int c = threadIdx.x;
    o[c] = fmaf(bc1[c], scv[c], bcv[c]);
}

__global__ void wdiff_kernel(const float* __restrict__ W, int half, float* __restrict__ Wd) {
    int t = blockIdx.x * blockDim.x + threadIdx.x;
    if (t < half) Wd[t] = W[t] - W[half + t];
}

__global__ void final_kernel(const float* __restrict__ h, const float* __restrict__ Wc2,
                             const float* __restrict__ bc2, float* __restrict__ out) {
    int t = blockIdx.x * blockDim.x + threadIdx.x;
    if (t >= NDOWN * 6) return;
    int i = t / 6, c = t % 6;
    float acc = bc2[c];
    for (int d = 0; d < 128; ++d) acc = fmaf(h[(size_t)i * 128 + d], Wc2[d * 6 + c], acc);
    out[t] = acc;
}

// ----------------------------------------------------------------------------
// launch
// ----------------------------------------------------------------------------
extern "C" void kernel_launch(void* const* d_in, const int* in_sizes, int n_in,
                              void* d_out, int out_size) {
    const float* points = (const float*)d_in[0];
    const float* We1 = (const float*)d_in[1];
    const float* se1 = (const float*)d_in[2];
    const float* be1 = (const float*)d_in[3];
    const float* We2 = (const float*)d_in[4];
    const float* se2 = (const float*)d_in[5];
    const float* be2 = (const float*)d_in[6];
    const float* Wq1 = (const float*)d_in[7];
    const float* Wk1 = (const float*)d_in[8];
    const float* Wv1 = (const float*)d_in[9];
    const float* sa1 = (const float*)d_in[10];
    const float* ba1 = (const float*)d_in[11];
    const float* Wq2 = (const float*)d_in[12];
    const float* Wk2 = (const float*)d_in[13];
    const float* Wv2 = (const float*)d_in[14];
    const float* sa2 = (const float*)d_in[15];
    const float* ba2 = (const float*)d_in[16];
    const float* Wtd = (const float*)d_in[17];
    const float* sd  = (const float*)d_in[18];
    const float* bd  = (const float*)d_in[19];
    const float* Wu1 = (const float*)d_in[20];
    const float* su1 = (const float*)d_in[21];
    const float* bu1 = (const float*)d_in[22];
    const float* Wu2 = (const float*)d_in[23];
    const float* su2 = (const float*)d_in[24];
    const float* bu2 = (const float*)d_in[25];
    const float* Wc1 = (const float*)d_in[26];
    const float* bc1 = (const float*)d_in[27];
    const float* scv = (const float*)d_in[28];
    const float* bcv = (const float*)d_in[29];
    const float* Wc2 = (const float*)d_in[30];
    const float* bc2 = (const float*)d_in[31];

    float* F = nullptr;
    int*   I = nullptr;
    cudaGetSymbolAddress((void**)&F, g_f);
    cudaGetSymbolAddress((void**)&I, g_i);

    float4* p4  = (float4*)(F + O_P4);
    float*  s1d = F + O_S1D;
    int*    s1i = I + OI_S1I;
    int*    idx = I + OI_IDX;

    // --- independent prologue ---
    prep_p4_kernel<<<32, 128>>>(points, p4, 0);
    prep_p4_kernel<<<32, 128>>>(points, p4, 4096);
    wdiff_kernel<<<2, 128>>>(We1, 192, F + O_WD1);
    wdiff_kernel<<<64, 128>>>(We2, 8192, F + O_WD2);
    b2eff_kernel<<<1, 128>>>(bc1, scv, bcv, F + O_B2E);

    // --- kNN (single full pass; downsampled rows are idx at stride 4) ---
    knn_stage1_kernel<<<dim3(NPTS / 128, CHUNKS), 128>>>(p4, s1d, s1i);
    knn_stage2_kernel<<<NPTS / 128, 128>>>(s1d, s1i, idx);

    // --- edge_conv 1 (fused, K=3, C=64) ---
    edge1_kernel<<<NPTS / 4, 256>>>(p4, F + O_WD1, We1 + 192, idx, se1, be1, F + O_X1);

    // --- edge_conv 2: C=128, batched A/B halves (tf32 tensor cores) ---
    mma_gemm_kernel<0><<<dim3(1, 64, 2), 256>>>(
        F + O_X1, 64, F + O_WD2, We2 + 8192, nullptr, 128,
        F + O_A2, F + O_B2, nullptr, 128, 64, nullptr, nullptr, nullptr, 0, nullptr);
    gathermax_kernel<<<NPTS / 4, 128>>>((const float4*)(F + O_A2), (const float4*)(F + O_B2), idx,
                                        (const float4*)se2, (const float4*)be2,
                                        (float4*)(F + O_X2));

    // --- graph_attn 1: D=256, q/k/v batched (tf32) ---
    mma_gemm_kernel<0><<<dim3(2, 64, 3), 256>>>(
        F + O_X2, 128, Wq1, Wk1, Wv1, 256,
        F + O_Q1, F + O_K1, F + O_V1, 256, 128, nullptr, nullptr, nullptr, 0, nullptr);
    attn_kernel<256, 4><<<NPTS / 4, 256>>>((const float4*)(F + O_Q1), (const float4*)(F + O_K1),
                                           (const float4*)(F + O_V1), idx,
                                           (const float4*)sa1, (const float4*)ba1,
                                           (float4*)(F + O_X3));

    // --- graph_attn 2: D=512, q/k/v batched (tf32) ---
    mma_gemm_kernel<0><<<dim3(4, 64, 3), 256>>>(
        F + O_X3, 256, Wq2, Wk2, Wv2, 512,
        F + O_Q2, F + O_K2, F + O_V2, 512, 256, nullptr, nullptr, nullptr, 0, nullptr);
    attn_kernel<512, 2><<<NPTS / 2, 256>>>((const float4*)(F + O_Q2), (const float4*)(F + O_K2),
                                           (const float4*)(F + O_V2), idx,
                                           (const float4*)sa2, (const float4*)ba2,
                                           (float4*)(F + O_X4));

    // --- downsample: PX = x4@Wtd[3:] + p@Wtd[0:3] (tf32, fused epilogue) ---
    mma_gemm_kernel<3><<<dim3(4, 64, 1), 256>>>(
        F + O_X4, 512, Wtd + 3 * 512, nullptr, nullptr, 512,
        F + O_PX, nullptr, nullptr, 512, 512, nullptr, nullptr, p4, 1, Wtd);
    rows3_kernel<<<dim3(NDOWN, 4), 128>>>(p4, 4, Wtd, F + O_PM, 512);
    downgather_kernel<<<NDOWN / 2, 256>>>((const float4*)(F + O_PX), (const float4*)(F + O_PM), idx,
                                          (const float4*)sd, (const float4*)bd,
                                          (float4*)(F + O_XD));

    // --- global mean folded into bias; xu = relu(xd@Wu1*su1 + beff) ---
    colsum_part_kernel<<<dim3(4, 8), 128>>>(F + O_XD, F + O_GS2);
    colsum_reduce_kernel<<<4, 128>>>(F + O_GS2, F + O_GS);
    beff_kernel<<<1, 256>>>(F + O_GS, Wu2, su2, bu1, bu2, F + O_BE);
    gemm_kernel<64, 64, 2><<<dim3(4, 32, 1), 256>>>(
        F + O_XD, 512, Wu1, 256, F + O_XU, 256, 512, su1, F + O_BE);

    // --- h = relu((xu@Wc1)*sc + (bc1*sc+bc)) ---
    gemm_kernel<64, 64, 2><<<dim3(2, 32, 1), 256>>>(
        F + O_XU, 256, Wc1, 128, F + O_H, 128, 256, scv, F + O_B2E);

    // --- out = h@Wc2 + bc2 ---
    final_kernel<<<96, 128>>>(F + O_H, Wc2, bc2, (float*)d_out);
}

// round 7
// speedup vs baseline: 1.7969x; 1.0509x over previous
#include <cuda_runtime.h>
#include <math.h>
#include <float.h>

#define NPTS   8192
#define NDOWN  2048
#define KNN    16
#define CHUNKS 16

// ----------------------------------------------------------------------------
// Scratch arenas (no cudaMalloc allowed).
// ----------------------------------------------------------------------------
__device__ float g_f[40200000];
__device__ int   g_i[2400000];

static const size_t O_A1  = 0;
static const size_t O_B1  = O_A1  + (size_t)8192*64;
static const size_t O_X1  = O_B1  + (size_t)8192*64;
static const size_t O_A2  = O_X1  + (size_t)8192*64;
static const size_t O_B2  = O_A2  + (size_t)8192*128;
static const size_t O_X2  = O_B2  + (size_t)8192*128;
static const size_t O_Q1  = O_X2  + (size_t)8192*128;   // y1 [8192,128]
static const size_t O_K1  = O_Q1  + (size_t)8192*256;   // region reused below
static const size_t O_V1  = O_K1  + (size_t)8192*256;
static const size_t O_X3  = O_V1  + (size_t)8192*256;
static const size_t O_Q2  = O_X3  + (size_t)8192*256;   // y2 [8192,256]
static const size_t O_K2  = O_Q2  + (size_t)8192*512;   // unused
static const size_t O_V2  = O_K2  + (size_t)8192*512;
static const size_t O_X4  = O_V2  + (size_t)8192*512;
static const size_t O_PX  = O_X4  + (size_t)8192*512;
static const size_t O_PM  = O_PX  + (size_t)8192*512;   // unused now
static const size_t O_XD  = O_PM  + (size_t)2048*512;
static const size_t O_XU  = O_XD  + (size_t)2048*512;
static const size_t O_H   = O_XU  + (size_t)2048*256;
static const size_t O_GS  = O_H   + (size_t)2048*128;   // 512 (unused)
static const size_t O_BE  = O_GS  + 512;                // 256
static const size_t O_B2E = O_BE  + 256;                // 128
static const size_t O_WD1 = O_B2E + 128;                // 192
static const size_t O_WD2 = O_WD1 + 192;                // 8192
static const size_t O_P4  = O_WD2 + 8192;               // 8192*4
static const size_t O_S1D = O_P4  + (size_t)8192*4;     // 8192*256
static const size_t O_GS2 = O_S1D + (size_t)8192*256;   // 4096

// precompute area inside the (free) O_K1 region
static const size_t O_WKT1 = O_K1;            // 256*128 = 32768
static const size_t O_M1   = O_K1 + 32768;    // 128*128 = 16384
static const size_t O_WKT2 = O_K1 + 65536;    // 512*256 = 131072
static const size_t O_M2   = O_K1 + 262144;   // 256*256 = 65536

static const size_t OI_IDX  = 0;                          // 8192*16
static const size_t OI_S1I  = (size_t)8192*16;            // 8192*256

// ----------------------------------------------------------------------------
// f32x2 helpers (for the small 64x64 GEMMs)
// ----------------------------------------------------------------------------
typedef unsigned long long ull;

__device__ __forceinline__ ull pk2(float lo, float hi) {
    ull r; asm("mov.b64 %0,{%1,%2};" : "=l"(r) : "f"(lo), "f"(hi)); return r;
}
__device__ __forceinline__ ull fma2(ull a, ull b, ull c) {
    ull d; asm("fma.rn.f32x2 %0,%1,%2,%3;" : "=l"(d) : "l"(a), "l"(b), "l"(c)); return d;
}
__device__ __forceinline__ void upk2(ull v, float& lo, float& hi) {
    asm("mov.b64 {%0,%1},%2;" : "=f"(lo), "=f"(hi) : "l"(v));
}

__device__ __forceinline__ unsigned tf32cvt(float f) {
    unsigned r; asm("cvt.rna.tf32.f32 %0,%1;" : "=r"(r) : "f"(f)); return r;
}

// ----------------------------------------------------------------------------
// fused prologue: p4 prep, We diffs, b2eff.  grid 131, block 128.
// ----------------------------------------------------------------------------
__global__ void prologue_kernel(const float* __restrict__ p, float4* __restrict__ p4,
                                const float* __restrict__ We1, float* __restrict__ Wd1,
                                const float* __restrict__ We2, float* __restrict__ Wd2,
                                const float* __restrict__ bc1, const float* __restrict__ scv,
                                const float* __restrict__ bcv, float* __restrict__ b2e) {
    int b = blockIdx.x, t = threadIdx.x;
    if (b < 64) {
        int i = b * 128 + t;
        float x = p[3 * i], y = p[3 * i + 1], z = p[3 * i + 2];
        p4[i] = make_float4(x, y, z, x * x + y * y + z * z);
    } else if (b < 66) {
        int j = (b - 64) * 128 + t;
        if (j < 192) Wd1[j] = We1[j] - We1[192 + j];
    } else if (b < 130) {
        int j = (b - 66) * 128 + t;
        Wd2[j] = We2[j] - We2[8192 + j];
    } else {
        b2e[t] = fmaf(bc1[t], scv[t], bcv[t]);
    }
}

// 32x32 tiled transpose: T[C,R] = W[R,C]^T.  grid (C/32, R/32), block (32,8).
__global__ void transpose_kernel(const float* __restrict__ W, float* __restrict__ T,
                                 int R, int C) {
    __shared__ float tile[32][33];
    int c0 = blockIdx.x * 32, r0 = blockIdx.y * 32;
    int x = threadIdx.x, y0 = threadIdx.y;
#pragma unroll
    for (int j = y0; j < 32; j += 8) tile[j][x] = W[(size_t)(r0 + j) * C + c0 + x];
    __syncthreads();
#pragma unroll
    for (int j = y0; j < 32; j += 8) T[(size_t)(c0 + j) * R + r0 + x] = tile[x][j];
}

// ----------------------------------------------------------------------------
// kNN (single pass; downsampled rows are idx at stride 4)
// ----------------------------------------------------------------------------
__device__ __forceinline__ void replace_rescan(float s, int j, float (&d)[KNN], int (&id)[KNN],
                                               float& wval, int& wpos) {
#pragma unroll
    for (int t = 0; t < KNN; ++t) if (t == wpos) { d[t] = s; id[t] = j; }
    wval = d[0]; wpos = 0;
#pragma unroll
    for (int t = 1; t < KNN; ++t) if (d[t] > wval) { wval = d[t]; wpos = t; }
}

__global__ void knn_stage1_kernel(const float4* __restrict__ p4,
                                  float* __restrict__ s1d, int* __restrict__ s1i) {
    const int CH = NPTS / CHUNKS;  // 512
    int q  = blockIdx.x * blockDim.x + threadIdx.x;
    int c0 = blockIdx.y * CH;

    float4 qp = p4[q];
    float qx = -2.f * qp.x, qy = -2.f * qp.y, qz = -2.f * qp.z;

    __shared__ float4 tile[512];
#pragma unroll
    for (int l = 0; l < 4; ++l) tile[threadIdx.x + l * 128] = p4[c0 + threadIdx.x + l * 128];
    __syncthreads();

    float d[KNN]; int id[KNN];
#pragma unroll
    for (int t = 0; t < KNN; ++t) {
        float4 c = tile[t];
        d[t] = fmaf(qx, c.x, fmaf(qy, c.y, fmaf(qz, c.z, c.w)));
        id[t] = c0 + t;
    }
    float wval = d[0]; int wpos = 0;
#pragma unroll
    for (int t = 1; t < KNN; ++t) if (d[t] > wval) { wval = d[t]; wpos = t; }

    float bs0 = 0.f, bs1 = 0.f, bs2 = 0.f, bs3 = 0.f;
    int   bj0 = 0, bj1 = 0, bj2 = 0, bj3 = 0, cnt = 0;

    for (int i = KNN; i < CH; ++i) {
        float4 c = tile[i];
        float s = fmaf(qx, c.x, fmaf(qy, c.y, fmaf(qz, c.z, c.w)));
        if (s < wval) {
            int j = c0 + i;
            if (cnt == 0)      { bs0 = s; bj0 = j; }
            else if (cnt == 1) { bs1 = s; bj1 = j; }
            else if (cnt == 2) { bs2 = s; bj2 = j; }
            else               { bs3 = s; bj3 = j; }
            cnt++;
        }
        if (__any_sync(0xffffffffu, cnt == 4)) {
            if (cnt > 0 && bs0 < wval) replace_rescan(bs0, bj0, d, id, wval, wpos);
            if (cnt > 1 && bs1 < wval) replace_rescan(bs1, bj1, d, id, wval, wpos);
            if (cnt > 2 && bs2 < wval) replace_rescan(bs2, bj2, d, id, wval, wpos);
            if (cnt > 3 && bs3 < wval) replace_rescan(bs3, bj3, d, id, wval, wpos);
            cnt = 0;
        }
    }
    if (cnt > 0 && bs0 < wval) replace_rescan(bs0, bj0, d, id, wval, wpos);
    if (cnt > 1 && bs1 < wval) replace_rescan(bs1, bj1, d, id, wval, wpos);
    if (cnt > 2 && bs2 < wval) replace_rescan(bs2, bj2, d, id, wval, wpos);
    if (cnt > 3 && bs3 < wval) replace_rescan(bs3, bj3, d, id, wval, wpos);

    size_t o = ((size_t)q * CHUNKS + blockIdx.y) * KNN;
#pragma unroll
    for (int t = 0; t < KNN; ++t) { s1d[o + t] = d[t]; s1i[o + t] = id[t]; }
}

__global__ void knn_stage2_kernel(const float* __restrict__ s1d, const int* __restrict__ s1i,
                                  int* __restrict__ outidx) {
    int q = blockIdx.x * blockDim.x + threadIdx.x;
    size_t base = (size_t)q * (CHUNKS * KNN);
    float d[KNN]; int id[KNN];
#pragma unroll
    for (int t = 0; t < KNN; ++t) { d[t] = s1d[base + t]; id[t] = s1i[base + t]; }
    float wval = d[0]; int wpos = 0;
#pragma unroll
    for (int t = 1; t < KNN; ++t) if (d[t] > wval) { wval = d[t]; wpos = t; }
    for (int c = KNN; c < CHUNKS * KNN; ++c) {
        float s = s1d[base + c];
        if (s < wval) replace_rescan(s, s1i[base + c], d, id, wval, wpos);
    }
#pragma unroll
    for (int t = 0; t < KNN; ++t) outidx[q * KNN + t] = id[t];
}

// ----------------------------------------------------------------------------
// Tensor-core GEMM (tf32 mma.sync.m16n8k8): C[M,N] = A[M,K] @ B[K,N].
// 128x128x16 tiles, 256 thr = 8 warps (2m x 4n), warp = 64x32.
// MODE 0: store. MODE 3: acc + p@W3 rows (row ld = ldc).
// ----------------------------------------------------------------------------
#define SP 132

template <int MODE>
__global__ __launch_bounds__(256, 2)
void mma_gemm_kernel(const float* __restrict__ A, int lda,
                     const float* __restrict__ Bp0, const float* __restrict__ Bp1,
                     const float* __restrict__ Bp2, int ldb,
                     float* __restrict__ Cp0, float* __restrict__ Cp1,
                     float* __restrict__ Cp2, int ldc, int K,
                     const float4* __restrict__ p4r, int rstride,
                     const float* __restrict__ W3) {
    __shared__ __align__(16) unsigned As[2][16][SP];
    __shared__ __align__(16) unsigned Bs[2][16][SP];

    const float* B = (blockIdx.z == 0) ? Bp0 : (blockIdx.z == 1) ? Bp1 : Bp2;
    float*       C = (blockIdx.z == 0) ? Cp0 : (blockIdx.z == 1) ? Cp1 : Cp2;

    int tid = threadIdx.x;
    int bm = blockIdx.y * 128, bn = blockIdx.x * 128;

    int ar = tid >> 2, ac4 = tid & 3;
    int bk = tid >> 5, bc = tid & 31;
    const float* Ap = A + (size_t)(bm + ar) * lda + ac4 * 4;
    const float* Bq = B + (size_t)bk * ldb + bn + bc * 4;

    float4 pa0, pa1, pb0, pb1;
    pa0 = *(const float4*)Ap;
    pa1 = *(const float4*)(Ap + (size_t)64 * lda);
    pb0 = *(const float4*)Bq;
    pb1 = *(const float4*)(Bq + (size_t)8 * ldb);
    Ap += 16;
    Bq += (size_t)16 * ldb;

    {
        As[0][ac4 * 4 + 0][ar] = tf32cvt(pa0.x);
        As[0][ac4 * 4 + 1][ar] = tf32cvt(pa0.y);
        As[0][ac4 * 4 + 2][ar] = tf32cvt(pa0.z);
        As[0][ac4 * 4 + 3][ar] = tf32cvt(pa0.w);
        As[0][ac4 * 4 + 0][ar + 64] = tf32cvt(pa1.x);
        As[0][ac4 * 4 + 1][ar + 64] = tf32cvt(pa1.y);
        As[0][ac4 * 4 + 2][ar + 64] = tf32cvt(pa1.z);
        As[0][ac4 * 4 + 3][ar + 64] = tf32cvt(pa1.w);
        uint4 t0 = make_uint4(tf32cvt(pb0.x), tf32cvt(pb0.y), tf32cvt(pb0.z), tf32cvt(pb0.w));
        uint4 t1 = make_uint4(tf32cvt(pb1.x), tf32cvt(pb1.y), tf32cvt(pb1.z), tf32cvt(pb1.w));
        *(uint4*)&Bs[0][bk][bc * 4] = t0;
        *(uint4*)&Bs[0][bk + 8][bc * 4] = t1;
    }
    __syncthreads();

    int lane = tid & 31, wid = tid >> 5;
    int wm = (wid & 1) * 64;
    int wn = (wid >> 1) * 32;
    int grp = lane >> 2, qid = lane & 3;

    float acc[4][4][4];
#pragma unroll
    for (int tm = 0; tm < 4; ++tm)
#pragma unroll
        for (int tn = 0; tn < 4; ++tn)
#pragma unroll
            for (int c = 0; c < 4; ++c) acc[tm][tn][c] = 0.f;

    int ktiles = K >> 4;
    for (int t = 0; t < ktiles; ++t) {
        bool more = (t + 1 < ktiles);
        if (more) {
            pa0 = *(const float4*)Ap;
            pa1 = *(const float4*)(Ap + (size_t)64 * lda);
            pb0 = *(const float4*)Bq;
            pb1 = *(const float4*)(Bq + (size_t)8 * ldb);
            Ap += 16;
            Bq += (size_t)16 * ldb;
        }

        int cb = t & 1;
#pragma unroll
        for (int kh = 0; kh < 2; ++kh) {
            int k0 = kh * 8;
            unsigned af[4][4], bf[4][2];
#pragma unroll
            for (int tm = 0; tm < 4; ++tm) {
                int m0 = wm + tm * 16 + grp;
                af[tm][0] = As[cb][k0 + qid][m0];
                af[tm][1] = As[cb][k0 + qid][m0 + 8];
                af[tm][2] = As[cb][k0 + qid + 4][m0];
                af[tm][3] = As[cb][k0 + qid + 4][m0 + 8];
            }
#pragma unroll
            for (int tn = 0; tn < 4; ++tn) {
                int n0 = wn + tn * 8 + grp;
                bf[tn][0] = Bs[cb][k0 + qid][n0];
                bf[tn][1] = Bs[cb][k0 + qid + 4][n0];
            }
#pragma unroll
            for (int tm = 0; tm < 4; ++tm)
#pragma unroll
                for (int tn = 0; tn < 4; ++tn) {
                    asm volatile(
                        "mma.sync.aligned.m16n8k8.row.col.f32.tf32.tf32.f32 "
                        "{%0,%1,%2,%3},{%4,%5,%6,%7},{%8,%9},{%0,%1,%2,%3};"
                        : "+f"(acc[tm][tn][0]), "+f"(acc[tm][tn][1]),
                          "+f"(acc[tm][tn][2]), "+f"(acc[tm][tn][3])
                        : "r"(af[tm][0]), "r"(af[tm][1]), "r"(af[tm][2]), "r"(af[tm][3]),
                          "r"(bf[tn][0]), "r"(bf[tn][1]));
                }
        }

        if (more) {
            int nb = (t + 1) & 1;
            As[nb][ac4 * 4 + 0][ar] = tf32cvt(pa0.x);
            As[nb][ac4 * 4 + 1][ar] = tf32cvt(pa0.y);
            As[nb][ac4 * 4 + 2][ar] = tf32cvt(pa0.z);
            As[nb][ac4 * 4 + 3][ar] = tf32cvt(pa0.w);
            As[nb][ac4 * 4 + 0][ar + 64] = tf32cvt(pa1.x);
            As[nb][ac4 * 4 + 1][ar + 64] = tf32cvt(pa1.y);
            As[nb][ac4 * 4 + 2][ar + 64] = tf32cvt(pa1.z);
            As[nb][ac4 * 4 + 3][ar + 64] = tf32cvt(pa1.w);
            uint4 t0 = make_uint4(tf32cvt(pb0.x), tf32cvt(pb0.y), tf32cvt(pb0.z), tf32cvt(pb0.w));
            uint4 t1 = make_uint4(tf32cvt(pb1.x), tf32cvt(pb1.y), tf32cvt(pb1.z), tf32cvt(pb1.w));
            *(uint4*)&Bs[nb][bk][bc * 4] = t0;
            *(uint4*)&Bs[nb][bk + 8][bc * 4] = t1;
        }
        __syncthreads();
    }

#pragma unroll
    for (int tm = 0; tm < 4; ++tm) {
        int r0 = bm + wm + tm * 16 + grp;
        int r1 = r0 + 8;
        float4 p0, p1;
        if (MODE == 3) {
            p0 = p4r[(size_t)r0 * rstride];
            p1 = p4r[(size_t)r1 * rstride];
        }
#pragma unroll
        for (int tn = 0; tn < 4; ++tn) {
            int col = bn + wn + tn * 8 + 2 * qid;
            float c0 = acc[tm][tn][0], c1 = acc[tm][tn][1];
            float c2 = acc[tm][tn][2], c3 = acc[tm][tn][3];
            if (MODE == 3) {
                float wa0 = W3[col],           wa1 = W3[col + 1];
                float wb0 = W3[ldc + col],     wb1 = W3[ldc + col + 1];
                float wc0 = W3[2 * ldc + col], wc1 = W3[2 * ldc + col + 1];
                c0 += fmaf(p0.x, wa0, fmaf(p0.y, wb0, p0.z * wc0));
                c1 += fmaf(p0.x, wa1, fmaf(p0.y, wb1, p0.z * wc1));
                c2 += fmaf(p1.x, wa0, fmaf(p1.y, wb0, p1.z * wc0));
                c3 += fmaf(p1.x, wa1, fmaf(p1.y, wb1, p1.z * wc1));
            }
            *(float2*)&C[(size_t)r0 * ldc + col] = make_float2(c0, c1);
            *(float2*)&C[(size_t)r1 * ldc + col] = make_float2(c2, c3);
        }
    }
}

// ----------------------------------------------------------------------------
// f32x2 GEMM, 64x64 tiles.  MODE 0: store.  MODE 2: relu(acc*s+b).
// ----------------------------------------------------------------------------
template <int BM, int BN, int MODE>
__global__ __launch_bounds__(256, 2)
void gemm_kernel(const float* __restrict__ A, int lda,
                 const float* __restrict__ Bp0, int ldb,
                 float* __restrict__ Cp0, int ldc, int K,
                 const float* __restrict__ scv, const float* __restrict__ biv) {
    constexpr int TM = BM / 16;
    constexpr int TN = BN / 16;
    constexpr int RP = TM / 2;
    constexpr int NA = BM / 64;
    constexpr int NB = BN / 64;
    constexpr int F4R = BN / 4;
    constexpr int BROW = 256 / F4R;

    __shared__ __align__(16) float As[2][16][BM + 4];
    __shared__ __align__(16) float Bs[2][16][BN];

    const float* B = Bp0;
    float*       C = Cp0;

    int tid = threadIdx.x;
    int bm = blockIdx.y * BM, bn = blockIdx.x * BN;

    int ar = tid >> 2, ac4 = tid & 3;
    int bk = tid / F4R, bc = tid % F4R;

    const float* Ap = A + (size_t)(bm + ar) * lda + ac4 * 4;
    const float* Bq = B + (size_t)bk * ldb + bn + bc * 4;

    float4 pa[NA], pb[NB];
#pragma unroll
    for (int l = 0; l < NA; ++l) pa[l] = *(const float4*)(Ap + (size_t)(64 * l) * lda);
#pragma unroll
    for (int l = 0; l < NB; ++l) pb[l] = *(const float4*)(Bq + (size_t)(BROW * l) * ldb);
    Ap += 16;
    Bq += (size_t)16 * ldb;

#pragma unroll
    for (int l = 0; l < NA; ++l) {
        int r = ar + 64 * l;
        As[0][ac4 * 4 + 0][r] = pa[l].x;
        As[0][ac4 * 4 + 1][r] = pa[l].y;
        As[0][ac4 * 4 + 2][r] = pa[l].z;
        As[0][ac4 * 4 + 3][r] = pa[l].w;
    }
#pragma unroll
    for (int l = 0; l < NB; ++l)
        *(float4*)&Bs[0][bk + BROW * l][bc * 4] = pb[l];
    __syncthreads();

    int tr = (tid >> 4) * TM;
    int tc = (tid & 15) * TN;

    ull acc[RP][TN];
#pragma unroll
    for (int rp = 0; rp < RP; ++rp)
#pragma unroll
        for (int c = 0; c < TN; ++c) acc[rp][c] = 0ull;

    int ktiles = K >> 4;
    for (int t = 0; t < ktiles; ++t) {
        bool more = (t + 1 < ktiles);
        if (more) {
#pragma unroll
            for (int l = 0; l < NA; ++l) pa[l] = *(const float4*)(Ap + (size_t)(64 * l) * lda);
#pragma unroll
            for (int l = 0; l < NB; ++l) pb[l] = *(const float4*)(Bq + (size_t)(BROW * l) * ldb);
            Ap += 16;
            Bq += (size_t)16 * ldb;
        }

        int cb = t & 1;
#pragma unroll
        for (int k = 0; k < 16; ++k) {
            float4 av[TM / 4], bv[TN / 4];
#pragma unroll
            for (int v = 0; v < TM / 4; ++v) av[v] = *(const float4*)&As[cb][k][tr + 4 * v];
#pragma unroll
            for (int v = 0; v < TN / 4; ++v) bv[v] = *(const float4*)&Bs[cb][k][tc + 4 * v];
            ull apk[RP];
#pragma unroll
            for (int v = 0; v < TM / 4; ++v) {
                apk[2 * v + 0] = pk2(av[v].x, av[v].y);
                apk[2 * v + 1] = pk2(av[v].z, av[v].w);
            }
#pragma unroll
            for (int v = 0; v < TN / 4; ++v) {
                {
                    ull bb = pk2(bv[v].x, bv[v].x);
#pragma unroll
                    for (int rp = 0; rp < RP; ++rp) acc[rp][4 * v + 0] = fma2(apk[rp], bb, acc[rp][4 * v + 0]);
                }
                {
                    ull bb = pk2(bv[v].y, bv[v].y);
#pragma unroll
                    for (int rp = 0; rp < RP; ++rp) acc[rp][4 * v + 1] = fma2(apk[rp], bb, acc[rp][4 * v + 1]);
                }
                {
                    ull bb = pk2(bv[v].z, bv[v].z);
#pragma unroll
                    for (int rp = 0; rp < RP; ++rp) acc[rp][4 * v + 2] = fma2(apk[rp], bb, acc[rp][4 * v + 2]);
                }
                {
                    ull bb = pk2(bv[v].w, bv[v].w);
#pragma unroll
                    for (int rp = 0; rp < RP; ++rp) acc[rp][4 * v + 3] = fma2(apk[rp], bb, acc[rp][4 * v + 3]);
                }
            }
        }

        if (more) {
            int nb = (t + 1) & 1;
#pragma unroll
            for (int l = 0; l < NA; ++l) {
                int r = ar + 64 * l;
                As[nb][ac4 * 4 + 0][r] = pa[l].x;
                As[nb][ac4 * 4 + 1][r] = pa[l].y;
                As[nb][ac4 * 4 + 2][r] = pa[l].z;
                As[nb][ac4 * 4 + 3][r] = pa[l].w;
            }
#pragma unroll
            for (int l = 0; l < NB; ++l)
                *(float4*)&Bs[nb][bk + BROW * l][bc * 4] = pb[l];
        }
        __syncthreads();
    }

    float sc8[TN], bi8[TN];
    if (MODE == 2) {
#pragma unroll
        for (int c = 0; c < TN; ++c) { sc8[c] = scv[bn + tc + c]; bi8[c] = biv[bn + tc + c]; }
    }
#pragma unroll
    for (int rp = 0; rp < RP; ++rp) {
        int r0 = bm + tr + 2 * rp, r1 = r0 + 1;
        float o0[TN], o1[TN];
#pragma unroll
        for (int c = 0; c < TN; ++c) upk2(acc[rp][c], o0[c], o1[c]);
        if (MODE == 2) {
#pragma unroll
            for (int c = 0; c < TN; ++c) {
                o0[c] = fmaxf(fmaf(o0[c], sc8[c], bi8[c]), 0.f);
                o1[c] = fmaxf(fmaf(o1[c], sc8[c], bi8[c]), 0.f);
            }
        }
#pragma unroll
        for (int v = 0; v < TN / 4; ++v) {
            *(float4*)&C[(size_t)r0 * ldc + bn + tc + 4 * v] =
                make_float4(o0[4 * v], o0[4 * v + 1], o0[4 * v + 2], o0[4 * v + 3]);
            *(float4*)&C[(size_t)r1 * ldc + bn + tc + 4 * v] =
                make_float4(o1[4 * v], o1[4 * v + 1], o1[4 * v + 2], o1[4 * v + 3]);
        }
    }
}

// ----------------------------------------------------------------------------
// edge_conv1 fused (K=3, C=64). 4 points/block, 256 threads.
// ----------------------------------------------------------------------------
__global__ void edge1_kernel(const float4* __restrict__ p4,
                             const float* __restrict__ Wd, const float* __restrict__ Wb,
                             const int* __restrict__ idx,
                             const float* __restrict__ s, const float* __restrict__ b,
                             float* __restrict__ out) {
    __shared__ float4 pj[4][KNN];
    int g = threadIdx.x >> 6, c = threadIdx.x & 63;
    int i = blockIdx.x * 4 + g;
    if (c < KNN) pj[g][c] = p4[idx[i * KNN + c]];
    __syncthreads();
    float4 pi = p4[i];
    float w0 = Wd[c], w1 = Wd[64 + c], w2 = Wd[128 + c];
    float u0 = Wb[c], u1 = Wb[64 + c], u2 = Wb[128 + c];
    float a = fmaf(pi.x, w0, fmaf(pi.y, w1, pi.z * w2));
    float sc = s[c], bv = b[c];
    float m = 0.f;
#pragma unroll
    for (int k = 0; k < KNN; ++k) {
        float4 pp = pj[g][k];
        float e = fmaf(pp.x, u0, fmaf(pp.y, u1, fmaf(pp.z, u2, a)));
        m = fmaxf(m, fmaf(e, sc, bv));
    }
    out[(size_t)i * 64 + c] = m;
}

// ----------------------------------------------------------------------------
// edge_conv2 gather-max (C=128, float4): 4 points/block, 128 threads.
// ----------------------------------------------------------------------------
__global__ void gathermax_kernel(const float4* __restrict__ Aa, const float4* __restrict__ Bb,
                                 const int* __restrict__ idx,
                                 const float4* __restrict__ s, const float4* __restrict__ b,
                                 float4* __restrict__ out) {
    const int C4 = 32;
    __shared__ int js[4][KNN];
    int g = threadIdx.x >> 5, c = threadIdx.x & 31;
    int i = blockIdx.x * 4 + g;
    if (c < KNN) js[g][c] = idx[i * KNN + c];
    __syncthreads();
    float4 a = Aa[(size_t)i * C4 + c];
    float4 sc = s[c], bv = b[c];
    float4 m = make_float4(0.f, 0.f, 0.f, 0.f);
#pragma unroll
    for (int k = 0; k < KNN; ++k) {
        float4 bj = Bb[(size_t)js[g][k] * C4 + c];
        m.x = fmaxf(m.x, fmaf(a.x + bj.x, sc.x, bv.x));
        m.y = fmaxf(m.y, fmaf(a.y + bj.y, sc.y, bv.y));
        m.z = fmaxf(m.z, fmaf(a.z + bj.z, sc.z, bv.z));
        m.w = fmaxf(m.w, fmaf(a.w + bj.w, sc.w, bv.w));
    }
    out[(size_t)i * C4 + c] = m;
}

// ----------------------------------------------------------------------------
// graph attention with precomputed y = x @ (Wq Wk^T):
// logits_ij = y_i . x_j (width DIN), values v_j (width D).
// NP points per block, D/4 threads per point; warps process neighbor pairs.
// ----------------------------------------------------------------------------
template <int DIN, int D, int NP>
__global__ void attn_kernel(const float4* __restrict__ y, const float4* __restrict__ xin,
                            const float4* __restrict__ v, const int* __restrict__ idx,
                            const float4* __restrict__ s, const float4* __restrict__ b,
                            float4* __restrict__ out) {
    constexpr int D4 = D / 4, DIN4 = DIN / 4;
    int tid = threadIdx.x;
    int g = tid / D4, t = tid % D4;
    int i = blockIdx.x * NP + g;
    __shared__ float4 qs[NP][DIN4];
    __shared__ float lg[NP][KNN];
    __shared__ float aw[NP][KNN];
    __shared__ int js[NP][KNN];
    if (t < DIN4) qs[g][t] = y[(size_t)i * DIN4 + t];
    if (t < KNN) js[g][t] = idx[i * KNN + t];
    __syncthreads();

    constexpr int NW = D4 / 32;
    int w = t >> 5, lane = t & 31;
    for (int k = w; k < 8; k += NW) {
        const float4* k0 = xin + (size_t)js[g][k] * DIN4;
        const float4* k1 = xin + (size_t)js[g][k + 8] * DIN4;
        float s0 = 0.f, s1 = 0.f;
#pragma unroll
        for (int m = lane; m < DIN4; m += 32) {
            float4 a = qs[g][m];
            float4 c0 = k0[m], c1 = k1[m];
            s0 = fmaf(a.x, c0.x, fmaf(a.y, c0.y, fmaf(a.z, c0.z, fmaf(a.w, c0.w, s0))));
            s1 = fmaf(a.x, c1.x, fmaf(a.y, c1.y, fmaf(a.z, c1.z, fmaf(a.w, c1.w, s1))));
        }
#pragma unroll
        for (int o = 16; o; o >>= 1) {
            s0 += __shfl_xor_sync(0xffffffffu, s0, o);
            s1 += __shfl_xor_sync(0xffffffffu, s1, o);
        }
        if (lane == 0) {
            float sc = rsqrtf((float)D);
            lg[g][k] = s0 * sc;
            lg[g][k + 8] = s1 * sc;
        }
    }
    __syncthreads();
    if (t < 32) {
        float l = (lane < KNN) ? lg[g][lane] : -FLT_MAX;
        float mx = l;
#pragma unroll
        for (int o = 16; o; o >>= 1) mx = fmaxf(mx, __shfl_xor_sync(0xffffffffu, mx, o));
        float e = (lane < KNN) ? expf(l - mx) : 0.f;
        float se = e;
#pragma unroll
        for (int o = 16; o; o >>= 1) se += __shfl_xor_sync(0xffffffffu, se, o);
        if (lane < KNN) aw[g][lane] = e / se;
    }
    __syncthreads();
    float4 yy = make_float4(0.f, 0.f, 0.f, 0.f);
#pragma unroll
    for (int k = 0; k < KNN; ++k) {
        float a = aw[g][k];
        float4 vv = v[(size_t)js[g][k] * D4 + t];
        yy.x = fmaf(a, vv.x, yy.x); yy.y = fmaf(a, vv.y, yy.y);
        yy.z = fmaf(a, vv.z, yy.z); yy.w = fmaf(a, vv.w, yy.w);
    }
    float4 sc = s[t], bv = b[t];
    float4 r;
    r.x = fmaxf(fmaf(yy.x, sc.x, bv.x), 0.f);
    r.y = fmaxf(fmaf(yy.y, sc.y, bv.y), 0.f);
    r.z = fmaxf(fmaf(yy.z, sc.z, bv.z), 0.f);
    r.w = fmaxf(fmaf(yy.w, sc.w, bv.w), 0.f);
    out[(size_t)i * D4 + t] = r;
}

// ----------------------------------------------------------------------------
// downsample gather-max with fused pm = p@W3 (float4): 2 pts/block, 256 thr.
// ----------------------------------------------------------------------------
__global__ void downgather_kernel(const float4* __restrict__ PX, const float4* __restrict__ p4,
                                  const float* __restrict__ W3, const int* __restrict__ idx,
                                  const float4* __restrict__ s, const float4* __restrict__ b,
                                  float4* __restrict__ out) {
    __shared__ int js[2][KNN];
    int g = threadIdx.x >> 7, c = threadIdx.x & 127;
    int i = blockIdx.x * 2 + g;
    if (c < KNN) js[g][c] = idx[(4 * i) * KNN + c];
    __syncthreads();
    float4 p = p4[4 * i];
    float4 wa = *(const float4*)&W3[4 * c];
    float4 wb = *(const float4*)&W3[512 + 4 * c];
    float4 wc = *(const float4*)&W3[1024 + 4 * c];
    float4 pm;
    pm.x = fmaf(p.x, wa.x, fmaf(p.y, wb.x, p.z * wc.x));
    pm.y = fmaf(p.x, wa.y, fmaf(p.y, wb.y, p.z * wc.y));
    pm.z = fmaf(p.x, wa.z, fmaf(p.y, wb.z, p.z * wc.z));
    pm.w = fmaf(p.x, wa.w, fmaf(p.y, wb.w, p.z * wc.w));
    float4 sc = s[c], bv = b[c];
    float4 m = make_float4(0.f, 0.f, 0.f, 0.f);
#pragma unroll
    for (int k = 0; k < KNN; ++k) {
        float4 px = PX[(size_t)js[g][k] * 128 + c];
        m.x = fmaxf(m.x, fmaf(px.x - pm.x, sc.x, bv.x));
        m.y = fmaxf(m.y, fmaf(px.y - pm.y, sc.y, bv.y));
        m.z = fmaxf(m.z, fmaf(px.z - pm.z, sc.z, bv.z));
        m.w = fmaxf(m.w, fmaf(px.w - pm.w, sc.w, bv.w));
    }
    out[(size_t)i * 128 + c] = m;
}

__global__ void colsum_part_kernel(const float* __restrict__ xd, float* __restrict__ gs2) {
    int c = blockIdx.x * blockDim.x + threadIdx.x;
    int g = blockIdx.y;
    float s = 0.f;
    for (int r = g * 256; r < (g + 1) * 256; ++r) s += xd[(size_t)r * 512 + c];
    gs2[g * 512 + c] = s;
}

// fused: reduce gs2 partials + beff.  1 block, 256 threads.
__global__ void beff_kernel(const float* __restrict__ gs2, const float* __restrict__ Wu2,
                            const float* __restrict__ su2, const float* __restrict__ bu1,
                            const float* __restrict__ bu2, float* __restrict__ be) {
    __shared__ float gsum[512];
    int tid = threadIdx.x;
    for (int c = tid; c < 512; c += 256) {
        float s = 0.f;
#pragma unroll
        for (int g = 0; g < 8; ++g) s += gs2[g * 512 + c];
        gsum[c] = s;
    }
    __syncthreads();
    float acc = 0.f;
    for (int d = 0; d < 512; ++d) acc = fmaf(gsum[d], Wu2[(size_t)d * 256 + tid], acc);
    be[tid] = bu1[tid] + bu2[tid] + su2[tid] * (acc * (1.f / 2048.f));
}

__global__ void final_kernel(const float* __restrict__ h, const float* __restrict__ Wc2,
                             const float* __restrict__ bc2, float* __restrict__ out) {
    int t = blockIdx.x * blockDim.x + threadIdx.x;
    if (t >= NDOWN * 6) return;
    int i = t / 6, c = t % 6;
    float acc = bc2[c];
    for (int d = 0; d < 128; ++d) acc = fmaf(h[(size_t)i * 128 + d], Wc2[d * 6 + c], acc);
    out[t] = acc;
}

// ----------------------------------------------------------------------------
// launch
// ----------------------------------------------------------------------------
extern "C" void kernel_launch(void* const* d_in, const int* in_sizes, int n_in,
                              void* d_out, int out_size) {
    const float* points = (const float*)d_in[0];
    const float* We1 = (const float*)d_in[1];
    const float* se1 = (const float*)d_in[2];
    const float* be1 = (const float*)d_in[3];
    const float* We2 = (const float*)d_in[4];
    const float* se2 = (const float*)d_in[5];
    const float* be2 = (const float*)d_in[6];
    const float* Wq1 = (const float*)d_in[7];
    const float* Wk1 = (const float*)d_in[8];
    const float* Wv1 = (const float*)d_in[9];
    const float* sa1 = (const float*)d_in[10];
    const float* ba1 = (const float*)d_in[11];
    const float* Wq2 = (const float*)d_in[12];
    const float* Wk2 = (const float*)d_in[13];
    const float* Wv2 = (const float*)d_in[14];
    const float* sa2 = (const float*)d_in[15];
    const float* ba2 = (const float*)d_in[16];
    const float* Wtd = (const float*)d_in[17];
    const float* sd  = (const float*)d_in[18];
    const float* bd  = (const float*)d_in[19];
    const float* Wu1 = (const float*)d_in[20];
    const float* su1 = (const float*)d_in[21];
    const float* bu1 = (const float*)d_in[22];
    const float* Wu2 = (const float*)d_in[23];
    const float* su2 = (const float*)d_in[24];
    const float* bu2 = (const float*)d_in[25];
    const float* Wc1 = (const float*)d_in[26];
    const float* bc1 = (const float*)d_in[27];
    const float* scv = (const float*)d_in[28];
    const float* bcv = (const float*)d_in[29];
    const float* Wc2 = (const float*)d_in[30];
    const float* bc2 = (const float*)d_in[31];

    float* F = nullptr;
    int*   I = nullptr;
    cudaGetSymbolAddress((void**)&F, g_f);
    cudaGetSymbolAddress((void**)&I, g_i);

    float4* p4  = (float4*)(F + O_P4);
    float*  s1d = F + O_S1D;
    int*    s1i = I + OI_S1I;
    int*    idx = I + OI_IDX;

    // --- fused prologue (p4, weight diffs, b2eff) ---
    prologue_kernel<<<131, 128>>>(points, p4, We1, F + O_WD1, We2, F + O_WD2,
                                  bc1, scv, bcv, F + O_B2E);

    // --- precompute M1 = Wq1 @ Wk1^T, M2 = Wq2 @ Wk2^T (fp32) ---
    transpose_kernel<<<dim3(8, 4), dim3(32, 8)>>>(Wk1, F + O_WKT1, 128, 256);
    transpose_kernel<<<dim3(16, 8), dim3(32, 8)>>>(Wk2, F + O_WKT2, 256, 512);
    gemm_kernel<64, 64, 0><<<dim3(2, 2), 256>>>(
        Wq1, 256, F + O_WKT1, 128, F + O_M1, 128, 256, nullptr, nullptr);
    gemm_kernel<64, 64, 0><<<dim3(4, 4), 256>>>(
        Wq2, 512, F + O_WKT2, 256, F + O_M2, 256, 512, nullptr, nullptr);

    // --- kNN (single full pass; downsampled rows are idx at stride 4) ---
    knn_stage1_kernel<<<dim3(NPTS / 128, CHUNKS), 128>>>(p4, s1d, s1i);
    knn_stage2_kernel<<<NPTS / 128, 128>>>(s1d, s1i, idx);

    // --- edge_conv 1 (fused, K=3, C=64) ---
    edge1_kernel<<<NPTS / 4, 256>>>(p4, F + O_WD1, We1 + 192, idx, se1, be1, F + O_X1);

    // --- edge_conv 2: C=128, batched A/B halves (tf32) ---
    mma_gemm_kernel<0><<<dim3(1, 64, 2), 256>>>(
        F + O_X1, 64, F + O_WD2, We2 + 8192, nullptr, 128,
        F + O_A2, F + O_B2, nullptr, 128, 64, nullptr, 0, nullptr);
    gathermax_kernel<<<NPTS / 4, 128>>>((const float4*)(F + O_A2), (const float4*)(F + O_B2), idx,
                                        (const float4*)se2, (const float4*)be2,
                                        (float4*)(F + O_X2));

    // --- graph_attn 1: y1 = x2@M1, v1 = x2@Wv1, logits via x2 gathers ---
    mma_gemm_kernel<0><<<dim3(1, 64, 1), 256>>>(
        F + O_X2, 128, F + O_M1, nullptr, nullptr, 128,
        F + O_Q1, nullptr, nullptr, 128, 128, nullptr, 0, nullptr);
    mma_gemm_kernel<0><<<dim3(2, 64, 1), 256>>>(
        F + O_X2, 128, Wv1, nullptr, nullptr, 256,
        F + O_V1, nullptr, nullptr, 256, 128, nullptr, 0, nullptr);
    attn_kernel<128, 256, 4><<<NPTS / 4, 256>>>(
        (const float4*)(F + O_Q1), (const float4*)(F + O_X2), (const float4*)(F + O_V1), idx,
        (const float4*)sa1, (const float4*)ba1, (float4*)(F + O_X3));

    // --- graph_attn 2: y2 = x3@M2, v2 = x3@Wv2, logits via x3 gathers ---
    mma_gemm_kernel<0><<<dim3(2, 64, 1), 256>>>(
        F + O_X3, 256, F + O_M2, nullptr, nullptr, 256,
        F + O_Q2, nullptr, nullptr, 256, 256, nullptr, 0, nullptr);
    mma_gemm_kernel<0><<<dim3(4, 64, 1), 256>>>(
        F + O_X3, 256, Wv2, nullptr, nullptr, 512,
        F + O_V2, nullptr, nullptr, 512, 256, nullptr, 0, nullptr);
    attn_kernel<256, 512, 2><<<NPTS / 2, 256>>>(
        (const float4*)(F + O_Q2), (const float4*)(F + O_X3), (const float4*)(F + O_V2), idx,
        (const float4*)sa2, (const float4*)ba2, (float4*)(F + O_X4));

    // --- downsample: PX = x4@Wtd[3:] + p@Wtd[0:3]; gather-max with fused pm ---
    mma_gemm_kernel<3><<<dim3(4, 64, 1), 256>>>(
        F + O_X4, 512, Wtd + 3 * 512, nullptr, nullptr, 512,
        F + O_PX, nullptr, nullptr, 512, 512, p4, 1, Wtd);
    downgather_kernel<<<NDOWN / 2, 256>>>((const float4*)(F + O_PX), p4, Wtd, idx,
                                          (const float4*)sd, (const float4*)bd,
                                          (float4*)(F + O_XD));

    // --- global mean folded into bias; xu = relu(xd@Wu1*su1 + beff) ---
    colsum_part_kernel<<<dim3(4, 8), 128>>>(F + O_XD, F + O_GS2);
    beff_kernel<<<1, 256>>>(F + O_GS2, Wu2, su2, bu1, bu2, F + O_BE);
    gemm_kernel<64, 64, 2><<<dim3(4, 32), 256>>>(
        F + O_XD, 512, Wu1, 256, F + O_XU, 256, 512, su1, F + O_BE);

    // --- h = relu((xu@Wc1)*sc + (bc1*sc+bc)) ---
    gemm_kernel<64, 64, 2><<<dim3(2, 32), 256>>>(
        F + O_XU, 256, Wc1, 128, F + O_H, 128, 256, scv, F + O_B2E);

    // --- out = h@Wc2 + bc2 ---
    final_kernel<<<96, 128>>>(F + O_H, Wc2, bc2, (float*)d_out);
}

// round 8
// speedup vs baseline: 1.9152x; 1.0658x over previous
#include <cuda_runtime.h>
#include <math.h>
#include <float.h>

#define NPTS   8192
#define NDOWN  2048
#define KNN    16
#define CHUNKS 16

// ----------------------------------------------------------------------------
// Scratch arenas (no cudaMalloc allowed).
// ----------------------------------------------------------------------------
__device__ float g_f[40200000];
__device__ int   g_i[2400000];

static const size_t O_A1  = 0;
static const size_t O_B1  = O_A1  + (size_t)8192*64;
static const size_t O_X1  = O_B1  + (size_t)8192*64;
static const size_t O_A2  = O_X1  + (size_t)8192*64;
static const size_t O_B2  = O_A2  + (size_t)8192*128;
static const size_t O_X2  = O_B2  + (size_t)8192*128;
static const size_t O_Q1  = O_X2  + (size_t)8192*128;   // y1 [8192,128]
static const size_t O_K1  = O_Q1  + (size_t)8192*256;   // region reused for M1/M2
static const size_t O_V1  = O_K1  + (size_t)8192*256;
static const size_t O_X3  = O_V1  + (size_t)8192*256;
static const size_t O_Q2  = O_X3  + (size_t)8192*256;   // y2 [8192,256]
static const size_t O_K2  = O_Q2  + (size_t)8192*512;
static const size_t O_V2  = O_K2  + (size_t)8192*512;
static const size_t O_X4  = O_V2  + (size_t)8192*512;
static const size_t O_PX  = O_X4  + (size_t)8192*512;
static const size_t O_PM  = O_PX  + (size_t)8192*512;
static const size_t O_XD  = O_PM  + (size_t)2048*512;
static const size_t O_XU  = O_XD  + (size_t)2048*512;
static const size_t O_H   = O_XU  + (size_t)2048*256;
static const size_t O_GS  = O_H   + (size_t)2048*128;   // 512
static const size_t O_BE  = O_GS  + 512;                // 256
static const size_t O_B2E = O_BE  + 256;                // 128
static const size_t O_WD1 = O_B2E + 128;                // 192
static const size_t O_WD2 = O_WD1 + 192;                // 8192
static const size_t O_P4  = O_WD2 + 8192;               // 8192*4
static const size_t O_S1D = O_P4  + (size_t)8192*4;     // 8192*256
static const size_t O_GS2 = O_S1D + (size_t)8192*256;   // 4096

static const size_t O_M1   = O_K1;            // 128*128
static const size_t O_M2   = O_K1 + 65536;    // 256*256

static const size_t OI_IDX  = 0;                          // 8192*16
static const size_t OI_S1I  = (size_t)8192*16;            // 8192*256

// ----------------------------------------------------------------------------
// f32x2 helpers
// ----------------------------------------------------------------------------
typedef unsigned long long ull;

__device__ __forceinline__ ull pk2(float lo, float hi) {
    ull r; asm("mov.b64 %0,{%1,%2};" : "=l"(r) : "f"(lo), "f"(hi)); return r;
}
__device__ __forceinline__ ull fma2(ull a, ull b, ull c) {
    ull d; asm("fma.rn.f32x2 %0,%1,%2,%3;" : "=l"(d) : "l"(a), "l"(b), "l"(c)); return d;
}
__device__ __forceinline__ void upk2(ull v, float& lo, float& hi) {
    asm("mov.b64 {%0,%1},%2;" : "=f"(lo), "=f"(hi) : "l"(v));
}

__device__ __forceinline__ unsigned tf32cvt(float f) {
    unsigned r; asm("cvt.rna.tf32.f32 %0,%1;" : "=r"(r) : "f"(f)); return r;
}

// ----------------------------------------------------------------------------
// fused prologue: p4 prep, We diffs, b2eff.  grid 131, block 128.
// ----------------------------------------------------------------------------
__global__ void prologue_kernel(const float* __restrict__ p, float4* __restrict__ p4,
                                const float* __restrict__ We1, float* __restrict__ Wd1,
                                const float* __restrict__ We2, float* __restrict__ Wd2,
                                const float* __restrict__ bc1, const float* __restrict__ scv,
                                const float* __restrict__ bcv, float* __restrict__ b2e) {
    int b = blockIdx.x, t = threadIdx.x;
    if (b < 64) {
        int i = b * 128 + t;
        float x = p[3 * i], y = p[3 * i + 1], z = p[3 * i + 2];
        p4[i] = make_float4(x, y, z, x * x + y * y + z * z);
    } else if (b < 66) {
        int j = (b - 64) * 128 + t;
        if (j < 192) Wd1[j] = We1[j] - We1[192 + j];
    } else if (b < 130) {
        int j = (b - 66) * 128 + t;
        Wd2[j] = We2[j] - We2[8192 + j];
    } else {
        b2e[t] = fmaf(bc1[t], scv[t], bcv[t]);
    }
}

// ----------------------------------------------------------------------------
// M = scale * Wq @ Wk^T  (both [Din, D] row-major).  4 i's x 32 j's per block.
// ----------------------------------------------------------------------------
__global__ void abt_kernel(const float* __restrict__ Wq, const float* __restrict__ Wk,
                           float* __restrict__ M, int Din, int D, float scale) {
    int j = blockIdx.x * 32 + (threadIdx.x & 31);
    int i = blockIdx.y * 4 + (threadIdx.x >> 5);
    const float4* a = (const float4*)(Wq + (size_t)i * D);
    const float4* b = (const float4*)(Wk + (size_t)j * D);
    float s = 0.f;
    int n4 = D >> 2;
    for (int d = 0; d < n4; ++d) {
        float4 x = a[d], y = b[d];
        s = fmaf(x.x, y.x, fmaf(x.y, y.y, fmaf(x.z, y.z, fmaf(x.w, y.w, s))));
    }
    M[(size_t)i * Din + j] = s * scale;
}

// ----------------------------------------------------------------------------
// kNN (single pass; downsampled rows are idx at stride 4)
// ----------------------------------------------------------------------------
__device__ __forceinline__ void replace_rescan(float s, int j, float (&d)[KNN], int (&id)[KNN],
                                               float& wval, int& wpos) {
#pragma unroll
    for (int t = 0; t < KNN; ++t) if (t == wpos) { d[t] = s; id[t] = j; }
    wval = d[0]; wpos = 0;
#pragma unroll
    for (int t = 1; t < KNN; ++t) if (d[t] > wval) { wval = d[t]; wpos = t; }
}

__global__ void knn_stage1_kernel(const float4* __restrict__ p4,
                                  float* __restrict__ s1d, int* __restrict__ s1i) {
    const int CH = NPTS / CHUNKS;  // 512
    int q  = blockIdx.x * blockDim.x + threadIdx.x;
    int c0 = blockIdx.y * CH;

    float4 qp = p4[q];
    float qx = -2.f * qp.x, qy = -2.f * qp.y, qz = -2.f * qp.z;

    __shared__ float4 tile[512];
#pragma unroll
    for (int l = 0; l < 4; ++l) tile[threadIdx.x + l * 128] = p4[c0 + threadIdx.x + l * 128];
    __syncthreads();

    float d[KNN]; int id[KNN];
#pragma unroll
    for (int t = 0; t < KNN; ++t) {
        float4 c = tile[t];
        d[t] = fmaf(qx, c.x, fmaf(qy, c.y, fmaf(qz, c.z, c.w)));
        id[t] = c0 + t;
    }
    float wval = d[0]; int wpos = 0;
#pragma unroll
    for (int t = 1; t < KNN; ++t) if (d[t] > wval) { wval = d[t]; wpos = t; }

    float bs0 = 0.f, bs1 = 0.f, bs2 = 0.f, bs3 = 0.f;
    int   bj0 = 0, bj1 = 0, bj2 = 0, bj3 = 0, cnt = 0;

    for (int i = KNN; i < CH; ++i) {
        float4 c = tile[i];
        float s = fmaf(qx, c.x, fmaf(qy, c.y, fmaf(qz, c.z, c.w)));
        if (s < wval) {
            int j = c0 + i;
            if (cnt == 0)      { bs0 = s; bj0 = j; }
            else if (cnt == 1) { bs1 = s; bj1 = j; }
            else if (cnt == 2) { bs2 = s; bj2 = j; }
            else               { bs3 = s; bj3 = j; }
            cnt++;
        }
        if (__any_sync(0xffffffffu, cnt == 4)) {
            if (cnt > 0 && bs0 < wval) replace_rescan(bs0, bj0, d, id, wval, wpos);
            if (cnt > 1 && bs1 < wval) replace_rescan(bs1, bj1, d, id, wval, wpos);
            if (cnt > 2 && bs2 < wval) replace_rescan(bs2, bj2, d, id, wval, wpos);
            if (cnt > 3 && bs3 < wval) replace_rescan(bs3, bj3, d, id, wval, wpos);
            cnt = 0;
        }
    }
    if (cnt > 0 && bs0 < wval) replace_rescan(bs0, bj0, d, id, wval, wpos);
    if (cnt > 1 && bs1 < wval) replace_rescan(bs1, bj1, d, id, wval, wpos);
    if (cnt > 2 && bs2 < wval) replace_rescan(bs2, bj2, d, id, wval, wpos);
    if (cnt > 3 && bs3 < wval) replace_rescan(bs3, bj3, d, id, wval, wpos);

    size_t o = ((size_t)q * CHUNKS + blockIdx.y) * KNN;
#pragma unroll
    for (int t = 0; t < KNN; ++t) { s1d[o + t] = d[t]; s1i[o + t] = id[t]; }
}

__global__ void knn_stage2_kernel(const float* __restrict__ s1d, const int* __restrict__ s1i,
                                  int* __restrict__ outidx) {
    int q = blockIdx.x * blockDim.x + threadIdx.x;
    size_t base = (size_t)q * (CHUNKS * KNN);
    float d[KNN]; int id[KNN];
#pragma unroll
    for (int t = 0; t < KNN; ++t) { d[t] = s1d[base + t]; id[t] = s1i[base + t]; }
    float wval = d[0]; int wpos = 0;
#pragma unroll
    for (int t = 1; t < KNN; ++t) if (d[t] > wval) { wval = d[t]; wpos = t; }
    for (int c = KNN; c < CHUNKS * KNN; ++c) {
        float s = s1d[base + c];
        if (s < wval) replace_rescan(s, s1i[base + c], d, id, wval, wpos);
    }
#pragma unroll
    for (int t = 0; t < KNN; ++t) outidx[q * KNN + t] = id[t];
}

// ----------------------------------------------------------------------------
// Tensor-core GEMM (tf32 mma.sync.m16n8k8): C[M,N] = A[M,K] @ B[K,N].
// MODE 0: store. MODE 3: acc + p@W3 rows (row ld = ldc).
// ----------------------------------------------------------------------------
#define SP 132

template <int MODE>
__global__ __launch_bounds__(256, 2)
void mma_gemm_kernel(const float* __restrict__ A, int lda,
                     const float* __restrict__ Bp0, const float* __restrict__ Bp1,
                     const float* __restrict__ Bp2, int ldb,
                     float* __restrict__ Cp0, float* __restrict__ Cp1,
                     float* __restrict__ Cp2, int ldc, int K,
                     const float4* __restrict__ p4r, int rstride,
                     const float* __restrict__ W3) {
    __shared__ __align__(16) unsigned As[2][16][SP];
    __shared__ __align__(16) unsigned Bs[2][16][SP];

    const float* B = (blockIdx.z == 0) ? Bp0 : (blockIdx.z == 1) ? Bp1 : Bp2;
    float*       C = (blockIdx.z == 0) ? Cp0 : (blockIdx.z == 1) ? Cp1 : Cp2;

    int tid = threadIdx.x;
    int bm = blockIdx.y * 128, bn = blockIdx.x * 128;

    int ar = tid >> 2, ac4 = tid & 3;
    int bk = tid >> 5, bc = tid & 31;
    const float* Ap = A + (size_t)(bm + ar) * lda + ac4 * 4;
    const float* Bq = B + (size_t)bk * ldb + bn + bc * 4;

    float4 pa0, pa1, pb0, pb1;
    pa0 = *(const float4*)Ap;
    pa1 = *(const float4*)(Ap + (size_t)64 * lda);
    pb0 = *(const float4*)Bq;
    pb1 = *(const float4*)(Bq + (size_t)8 * ldb);
    Ap += 16;
    Bq += (size_t)16 * ldb;

    {
        As[0][ac4 * 4 + 0][ar] = tf32cvt(pa0.x);
        As[0][ac4 * 4 + 1][ar] = tf32cvt(pa0.y);
        As[0][ac4 * 4 + 2][ar] = tf32cvt(pa0.z);
        As[0][ac4 * 4 + 3][ar] = tf32cvt(pa0.w);
        As[0][ac4 * 4 + 0][ar + 64] = tf32cvt(pa1.x);
        As[0][ac4 * 4 + 1][ar + 64] = tf32cvt(pa1.y);
        As[0][ac4 * 4 + 2][ar + 64] = tf32cvt(pa1.z);
        As[0][ac4 * 4 + 3][ar + 64] = tf32cvt(pa1.w);
        uint4 t0 = make_uint4(tf32cvt(pb0.x), tf32cvt(pb0.y), tf32cvt(pb0.z), tf32cvt(pb0.w));
        uint4 t1 = make_uint4(tf32cvt(pb1.x), tf32cvt(pb1.y), tf32cvt(pb1.z), tf32cvt(pb1.w));
        *(uint4*)&Bs[0][bk][bc * 4] = t0;
        *(uint4*)&Bs[0][bk + 8][bc * 4] = t1;
    }
    __syncthreads();

    int lane = tid & 31, wid = tid >> 5;
    int wm = (wid & 1) * 64;
    int wn = (wid >> 1) * 32;
    int grp = lane >> 2, qid = lane & 3;

    float acc[4][4][4];
#pragma unroll
    for (int tm = 0; tm < 4; ++tm)
#pragma unroll
        for (int tn = 0; tn < 4; ++tn)
#pragma unroll
            for (int c = 0; c < 4; ++c) acc[tm][tn][c] = 0.f;

    int ktiles = K >> 4;
    for (int t = 0; t < ktiles; ++t) {
        bool more = (t + 1 < ktiles);
        if (more) {
            pa0 = *(const float4*)Ap;
            pa1 = *(const float4*)(Ap + (size_t)64 * lda);
            pb0 = *(const float4*)Bq;
            pb1 = *(const float4*)(Bq + (size_t)8 * ldb);
            Ap += 16;
            Bq += (size_t)16 * ldb;
        }

        int cb = t & 1;
#pragma unroll
        for (int kh = 0; kh < 2; ++kh) {
            int k0 = kh * 8;
            unsigned af[4][4], bf[4][2];
#pragma unroll
            for (int tm = 0; tm < 4; ++tm) {
                int m0 = wm + tm * 16 + grp;
                af[tm][0] = As[cb][k0 + qid][m0];
                af[tm][1] = As[cb][k0 + qid][m0 + 8];
                af[tm][2] = As[cb][k0 + qid + 4][m0];
                af[tm][3] = As[cb][k0 + qid + 4][m0 + 8];
            }
#pragma unroll
            for (int tn = 0; tn < 4; ++tn) {
                int n0 = wn + tn * 8 + grp;
                bf[tn][0] = Bs[cb][k0 + qid][n0];
                bf[tn][1] = Bs[cb][k0 + qid + 4][n0];
            }
#pragma unroll
            for (int tm = 0; tm < 4; ++tm)
#pragma unroll
                for (int tn = 0; tn < 4; ++tn) {
                    asm volatile(
                        "mma.sync.aligned.m16n8k8.row.col.f32.tf32.tf32.f32 "
                        "{%0,%1,%2,%3},{%4,%5,%6,%7},{%8,%9},{%0,%1,%2,%3};"
                        : "+f"(acc[tm][tn][0]), "+f"(acc[tm][tn][1]),
                          "+f"(acc[tm][tn][2]), "+f"(acc[tm][tn][3])
                        : "r"(af[tm][0]), "r"(af[tm][1]), "r"(af[tm][2]), "r"(af[tm][3]),
                          "r"(bf[tn][0]), "r"(bf[tn][1]));
                }
        }

        if (more) {
            int nb = (t + 1) & 1;
            As[nb][ac4 * 4 + 0][ar] = tf32cvt(pa0.x);
            As[nb][ac4 * 4 + 1][ar] = tf32cvt(pa0.y);
            As[nb][ac4 * 4 + 2][ar] = tf32cvt(pa0.z);
            As[nb][ac4 * 4 + 3][ar] = tf32cvt(pa0.w);
            As[nb][ac4 * 4 + 0][ar + 64] = tf32cvt(pa1.x);
            As[nb][ac4 * 4 + 1][ar + 64] = tf32cvt(pa1.y);
            As[nb][ac4 * 4 + 2][ar + 64] = tf32cvt(pa1.z);
            As[nb][ac4 * 4 + 3][ar + 64] = tf32cvt(pa1.w);
            uint4 t0 = make_uint4(tf32cvt(pb0.x), tf32cvt(pb0.y), tf32cvt(pb0.z), tf32cvt(pb0.w));
            uint4 t1 = make_uint4(tf32cvt(pb1.x), tf32cvt(pb1.y), tf32cvt(pb1.z), tf32cvt(pb1.w));
            *(uint4*)&Bs[nb][bk][bc * 4] = t0;
            *(uint4*)&Bs[nb][bk + 8][bc * 4] = t1;
        }
        __syncthreads();
    }

#pragma unroll
    for (int tm = 0; tm < 4; ++tm) {
        int r0 = bm + wm + tm * 16 + grp;
        int r1 = r0 + 8;
        float4 p0, p1;
        if (MODE == 3) {
            p0 = p4r[(size_t)r0 * rstride];
            p1 = p4r[(size_t)r1 * rstride];
        }
#pragma unroll
        for (int tn = 0; tn < 4; ++tn) {
            int col = bn + wn + tn * 8 + 2 * qid;
            float c0 = acc[tm][tn][0], c1 = acc[tm][tn][1];
            float c2 = acc[tm][tn][2], c3 = acc[tm][tn][3];
            if (MODE == 3) {
                float wa0 = W3[col],           wa1 = W3[col + 1];
                float wb0 = W3[ldc + col],     wb1 = W3[ldc + col + 1];
                float wc0 = W3[2 * ldc + col], wc1 = W3[2 * ldc + col + 1];
                c0 += fmaf(p0.x, wa0, fmaf(p0.y, wb0, p0.z * wc0));
                c1 += fmaf(p0.x, wa1, fmaf(p0.y, wb1, p0.z * wc1));
                c2 += fmaf(p1.x, wa0, fmaf(p1.y, wb0, p1.z * wc0));
                c3 += fmaf(p1.x, wa1, fmaf(p1.y, wb1, p1.z * wc1));
            }
            *(float2*)&C[(size_t)r0 * ldc + col] = make_float2(c0, c1);
            *(float2*)&C[(size_t)r1 * ldc + col] = make_float2(c2, c3);
        }
    }
}

// ----------------------------------------------------------------------------
// f32x2 GEMM, 64x64 tiles.  MODE 0: store.  MODE 2: relu(acc*s+b).
// ----------------------------------------------------------------------------
template <int BM, int BN, int MODE>
__global__ __launch_bounds__(256, 2)
void gemm_kernel(const float* __restrict__ A, int lda,
                 const float* __restrict__ Bp0, int ldb,
                 float* __restrict__ Cp0, int ldc, int K,
                 const float* __restrict__ scv, const float* __restrict__ biv) {
    constexpr int TM = BM / 16;
    constexpr int TN = BN / 16;
    constexpr int RP = TM / 2;
    constexpr int NA = BM / 64;
    constexpr int NB = BN / 64;
    constexpr int F4R = BN / 4;
    constexpr int BROW = 256 / F4R;

    __shared__ __align__(16) float As[2][16][BM + 4];
    __shared__ __align__(16) float Bs[2][16][BN];

    const float* B = Bp0;
    float*       C = Cp0;

    int tid = threadIdx.x;
    int bm = blockIdx.y * BM, bn = blockIdx.x * BN;

    int ar = tid >> 2, ac4 = tid & 3;
    int bk = tid / F4R, bc = tid % F4R;

    const float* Ap = A + (size_t)(bm + ar) * lda + ac4 * 4;
    const float* Bq = B + (size_t)bk * ldb + bn + bc * 4;

    float4 pa[NA], pb[NB];
#pragma unroll
    for (int l = 0; l < NA; ++l) pa[l] = *(const float4*)(Ap + (size_t)(64 * l) * lda);
#pragma unroll
    for (int l = 0; l < NB; ++l) pb[l] = *(const float4*)(Bq + (size_t)(BROW * l) * ldb);
    Ap += 16;
    Bq += (size_t)16 * ldb;

#pragma unroll
    for (int l = 0; l < NA; ++l) {
        int r = ar + 64 * l;
        As[0][ac4 * 4 + 0][r] = pa[l].x;
        As[0][ac4 * 4 + 1][r] = pa[l].y;
        As[0][ac4 * 4 + 2][r] = pa[l].z;
        As[0][ac4 * 4 + 3][r] = pa[l].w;
    }
#pragma unroll
    for (int l = 0; l < NB; ++l)
        *(float4*)&Bs[0][bk + BROW * l][bc * 4] = pb[l];
    __syncthreads();

    int tr = (tid >> 4) * TM;
    int tc = (tid & 15) * TN;

    ull acc[RP][TN];
#pragma unroll
    for (int rp = 0; rp < RP; ++rp)
#pragma unroll
        for (int c = 0; c < TN; ++c) acc[rp][c] = 0ull;

    int ktiles = K >> 4;
    for (int t = 0; t < ktiles; ++t) {
        bool more = (t + 1 < ktiles);
        if (more) {
#pragma unroll
            for (int l = 0; l < NA; ++l) pa[l] = *(const float4*)(Ap + (size_t)(64 * l) * lda);
#pragma unroll
            for (int l = 0; l < NB; ++l) pb[l] = *(const float4*)(Bq + (size_t)(BROW * l) * ldb);
            Ap += 16;
            Bq += (size_t)16 * ldb;
        }

        int cb = t & 1;
#pragma unroll
        for (int k = 0; k < 16; ++k) {
            float4 av[TM / 4], bv[TN / 4];
#pragma unroll
            for (int v = 0; v < TM / 4; ++v) av[v] = *(const float4*)&As[cb][k][tr + 4 * v];
#pragma unroll
            for (int v = 0; v < TN / 4; ++v) bv[v] = *(const float4*)&Bs[cb][k][tc + 4 * v];
            ull apk[RP];
#pragma unroll
            for (int v = 0; v < TM / 4; ++v) {
                apk[2 * v + 0] = pk2(av[v].x, av[v].y);
                apk[2 * v + 1] = pk2(av[v].z, av[v].w);
            }
#pragma unroll
            for (int v = 0; v < TN / 4; ++v) {
                {
                    ull bb = pk2(bv[v].x, bv[v].x);
#pragma unroll
                    for (int rp = 0; rp < RP; ++rp) acc[rp][4 * v + 0] = fma2(apk[rp], bb, acc[rp][4 * v + 0]);
                }
                {
                    ull bb = pk2(bv[v].y, bv[v].y);
#pragma unroll
                    for (int rp = 0; rp < RP; ++rp) acc[rp][4 * v + 1] = fma2(apk[rp], bb, acc[rp][4 * v + 1]);
                }
                {
                    ull bb = pk2(bv[v].z, bv[v].z);
#pragma unroll
                    for (int rp = 0; rp < RP; ++rp) acc[rp][4 * v + 2] = fma2(apk[rp], bb, acc[rp][4 * v + 2]);
                }
                {
                    ull bb = pk2(bv[v].w, bv[v].w);
#pragma unroll
                    for (int rp = 0; rp < RP; ++rp) acc[rp][4 * v + 3] = fma2(apk[rp], bb, acc[rp][4 * v + 3]);
                }
            }
        }

        if (more) {
            int nb = (t + 1) & 1;
#pragma unroll
            for (int l = 0; l < NA; ++l) {
                int r = ar + 64 * l;
                As[nb][ac4 * 4 + 0][r] = pa[l].x;
                As[nb][ac4 * 4 + 1][r] = pa[l].y;
                As[nb][ac4 * 4 + 2][r] = pa[l].z;
                As[nb][ac4 * 4 + 3][r] = pa[l].w;
            }
#pragma unroll
            for (int l = 0; l < NB; ++l)
                *(float4*)&Bs[nb][bk + BROW * l][bc * 4] = pb[l];
        }
        __syncthreads();
    }

    float sc8[TN], bi8[TN];
    if (MODE == 2) {
#pragma unroll
        for (int c = 0; c < TN; ++c) { sc8[c] = scv[bn + tc + c]; bi8[c] = biv[bn + tc + c]; }
    }
#pragma unroll
    for (int rp = 0; rp < RP; ++rp) {
        int r0 = bm + tr + 2 * rp, r1 = r0 + 1;
        float o0[TN], o1[TN];
#pragma unroll
        for (int c = 0; c < TN; ++c) upk2(acc[rp][c], o0[c], o1[c]);
        if (MODE == 2) {
#pragma unroll
            for (int c = 0; c < TN; ++c) {
                o0[c] = fmaxf(fmaf(o0[c], sc8[c], bi8[c]), 0.f);
                o1[c] = fmaxf(fmaf(o1[c], sc8[c], bi8[c]), 0.f);
            }
        }
#pragma unroll
        for (int v = 0; v < TN / 4; ++v) {
            *(float4*)&C[(size_t)r0 * ldc + bn + tc + 4 * v] =
                make_float4(o0[4 * v], o0[4 * v + 1], o0[4 * v + 2], o0[4 * v + 3]);
            *(float4*)&C[(size_t)r1 * ldc + bn + tc + 4 * v] =
                make_float4(o1[4 * v], o1[4 * v + 1], o1[4 * v + 2], o1[4 * v + 3]);
        }
    }
}

// ----------------------------------------------------------------------------
// edge_conv1 fused (K=3, C=64). 4 points/block, 256 threads.
// ----------------------------------------------------------------------------
__global__ void edge1_kernel(const float4* __restrict__ p4,
                             const float* __restrict__ Wd, const float* __restrict__ Wb,
                             const int* __restrict__ idx,
                             const float* __restrict__ s, const float* __restrict__ b,
                             float* __restrict__ out) {
    __shared__ float4 pj[4][KNN];
    int g = threadIdx.x >> 6, c = threadIdx.x & 63;
    int i = blockIdx.x * 4 + g;
    if (c < KNN) pj[g][c] = p4[idx[i * KNN + c]];
    __syncthreads();
    float4 pi = p4[i];
    float w0 = Wd[c], w1 = Wd[64 + c], w2 = Wd[128 + c];
    float u0 = Wb[c], u1 = Wb[64 + c], u2 = Wb[128 + c];
    float a = fmaf(pi.x, w0, fmaf(pi.y, w1, pi.z * w2));
    float sc = s[c], bv = b[c];
    float m = 0.f;
#pragma unroll
    for (int k = 0; k < KNN; ++k) {
        float4 pp = pj[g][k];
        float e = fmaf(pp.x, u0, fmaf(pp.y, u1, fmaf(pp.z, u2, a)));
        m = fmaxf(m, fmaf(e, sc, bv));
    }
    out[(size_t)i * 64 + c] = m;
}

// ----------------------------------------------------------------------------
// edge_conv2 gather-max (C=128, float4): 4 points/block, 128 threads.
// ----------------------------------------------------------------------------
__global__ void gathermax_kernel(const float4* __restrict__ Aa, const float4* __restrict__ Bb,
                                 const int* __restrict__ idx,
                                 const float4* __restrict__ s, const float4* __restrict__ b,
                                 float4* __restrict__ out) {
    const int C4 = 32;
    __shared__ int js[4][KNN];
    int g = threadIdx.x >> 5, c = threadIdx.x & 31;
    int i = blockIdx.x * 4 + g;
    if (c < KNN) js[g][c] = idx[i * KNN + c];
    __syncthreads();
    float4 a = Aa[(size_t)i * C4 + c];
    float4 sc = s[c], bv = b[c];
    float4 m = make_float4(0.f, 0.f, 0.f, 0.f);
#pragma unroll
    for (int k = 0; k < KNN; ++k) {
        float4 bj = Bb[(size_t)js[g][k] * C4 + c];
        m.x = fmaxf(m.x, fmaf(a.x + bj.x, sc.x, bv.x));
        m.y = fmaxf(m.y, fmaf(a.y + bj.y, sc.y, bv.y));
        m.z = fmaxf(m.z, fmaf(a.z + bj.z, sc.z, bv.z));
        m.w = fmaxf(m.w, fmaf(a.w + bj.w, sc.w, bv.w));
    }
    out[(size_t)i * C4 + c] = m;
}

// ----------------------------------------------------------------------------
// graph attention with precomputed y = x @ (scale * Wq Wk^T):
// logits_ij = y_i . x_j (scale folded into M).
// ----------------------------------------------------------------------------
template <int DIN, int D, int NP>
__global__ void attn_kernel(const float4* __restrict__ y, const float4* __restrict__ xin,
                            const float4* __restrict__ v, const int* __restrict__ idx,
                            const float4* __restrict__ s, const float4* __restrict__ b,
                            float4* __restrict__ out) {
    constexpr int D4 = D / 4, DIN4 = DIN / 4;
    int tid = threadIdx.x;
    int g = tid / D4, t = tid % D4;
    int i = blockIdx.x * NP + g;
    __shared__ float4 qs[NP][DIN4];
    __shared__ float lg[NP][KNN];
    __shared__ float aw[NP][KNN];
    __shared__ int js[NP][KNN];
    if (t < DIN4) qs[g][t] = y[(size_t)i * DIN4 + t];
    if (t < KNN) js[g][t] = idx[i * KNN + t];
    __syncthreads();

    constexpr int NW = D4 / 32;
    int w = t >> 5, lane = t & 31;
    for (int k = w; k < 8; k += NW) {
        const float4* k0 = xin + (size_t)js[g][k] * DIN4;
        const float4* k1 = xin + (size_t)js[g][k + 8] * DIN4;
        float s0 = 0.f, s1 = 0.f;
#pragma unroll
        for (int m = lane; m < DIN4; m += 32) {
            float4 a = qs[g][m];
            float4 c0 = k0[m], c1 = k1[m];
            s0 = fmaf(a.x, c0.x, fmaf(a.y, c0.y, fmaf(a.z, c0.z, fmaf(a.w, c0.w, s0))));
            s1 = fmaf(a.x, c1.x, fmaf(a.y, c1.y, fmaf(a.z, c1.z, fmaf(a.w, c1.w, s1))));
        }
#pragma unroll
        for (int o = 16; o; o >>= 1) {
            s0 += __shfl_xor_sync(0xffffffffu, s0, o);
            s1 += __shfl_xor_sync(0xffffffffu, s1, o);
        }
        if (lane == 0) {
            lg[g][k] = s0;
            lg[g][k + 8] = s1;
        }
    }
    __syncthreads();
    if (t < 32) {
        float l = (lane < KNN) ? lg[g][lane] : -FLT_MAX;
        float mx = l;
#pragma unroll
        for (int o = 16; o; o >>= 1) mx = fmaxf(mx, __shfl_xor_sync(0xffffffffu, mx, o));
        float e = (lane < KNN) ? expf(l - mx) : 0.f;
        float se = e;
#pragma unroll
        for (int o = 16; o; o >>= 1) se += __shfl_xor_sync(0xffffffffu, se, o);
        if (lane < KNN) aw[g][lane] = e / se;
    }
    __syncthreads();
    float4 yy = make_float4(0.f, 0.f, 0.f, 0.f);
#pragma unroll
    for (int k = 0; k < KNN; ++k) {
        float a = aw[g][k];
        float4 vv = v[(size_t)js[g][k] * D4 + t];
        yy.x = fmaf(a, vv.x, yy.x); yy.y = fmaf(a, vv.y, yy.y);
        yy.z = fmaf(a, vv.z, yy.z); yy.w = fmaf(a, vv.w, yy.w);
    }
    float4 sc = s[t], bv = b[t];
    float4 r;
    r.x = fmaxf(fmaf(yy.x, sc.x, bv.x), 0.f);
    r.y = fmaxf(fmaf(yy.y, sc.y, bv.y), 0.f);
    r.z = fmaxf(fmaf(yy.z, sc.z, bv.z), 0.f);
    r.w = fmaxf(fmaf(yy.w, sc.w, bv.w), 0.f);
    out[(size_t)i * D4 + t] = r;
}

// ----------------------------------------------------------------------------
// downsample gather-max with fused pm = p@W3 (float4): 2 pts/block, 256 thr.
// ----------------------------------------------------------------------------
__global__ void downgather_kernel(const float4* __restrict__ PX, const float4* __restrict__ p4,
                                  const float* __restrict__ W3, const int* __restrict__ idx,
                                  const float4* __restrict__ s, const float4* __restrict__ b,
                                  float4* __restrict__ out) {
    __shared__ int js[2][KNN];
    int g = threadIdx.x >> 7, c = threadIdx.x & 127;
    int i = blockIdx.x * 2 + g;
    if (c < KNN) js[g][c] = idx[(4 * i) * KNN + c];
    __syncthreads();
    float4 p = p4[4 * i];
    float4 wa = *(const float4*)&W3[4 * c];
    float4 wb = *(const float4*)&W3[512 + 4 * c];
    float4 wc = *(const float4*)&W3[1024 + 4 * c];
    float4 pm;
    pm.x = fmaf(p.x, wa.x, fmaf(p.y, wb.x, p.z * wc.x));
    pm.y = fmaf(p.x, wa.y, fmaf(p.y, wb.y, p.z * wc.y));
    pm.z = fmaf(p.x, wa.z, fmaf(p.y, wb.z, p.z * wc.z));
    pm.w = fmaf(p.x, wa.w, fmaf(p.y, wb.w, p.z * wc.w));
    float4 sc = s[c], bv = b[c];
    float4 m = make_float4(0.f, 0.f, 0.f, 0.f);
#pragma unroll
    for (int k = 0; k < KNN; ++k) {
        float4 px = PX[(size_t)js[g][k] * 128 + c];
        m.x = fmaxf(m.x, fmaf(px.x - pm.x, sc.x, bv.x));
        m.y = fmaxf(m.y, fmaf(px.y - pm.y, sc.y, bv.y));
        m.z = fmaxf(m.z, fmaf(px.z - pm.z, sc.z, bv.z));
        m.w = fmaxf(m.w, fmaf(px.w - pm.w, sc.w, bv.w));
    }
    out[(size_t)i * 128 + c] = m;
}

__global__ void colsum_part_kernel(const float* __restrict__ xd, float* __restrict__ gs2) {
    int c = blockIdx.x * blockDim.x + threadIdx.x;
    int g = blockIdx.y;
    float s = 0.f;
    for (int r = g * 256; r < (g + 1) * 256; ++r) s += xd[(size_t)r * 512 + c];
    gs2[g * 512 + c] = s;
}

// fused: reduce gs2 partials + beff.  1 block, 256 threads.
__global__ void beff_kernel(const float* __restrict__ gs2, const float* __restrict__ Wu2,
                            const float* __restrict__ su2, const float* __restrict__ bu1,
                            const float* __restrict__ bu2, float* __restrict__ be) {
    __shared__ float gsum[512];
    int tid = threadIdx.x;
    for (int c = tid; c < 512; c += 256) {
        float s = 0.f;
#pragma unroll
        for (int g = 0; g < 8; ++g) s += gs2[g * 512 + c];
        gsum[c] = s;
    }
    __syncthreads();
    float acc = 0.f;
    for (int d = 0; d < 512; ++d) acc = fmaf(gsum[d], Wu2[(size_t)d * 256 + tid], acc);
    be[tid] = bu1[tid] + bu2[tid] + su2[tid] * (acc * (1.f / 2048.f));
}

// xu = relu(xu * s[c] + b[c]), [2048,256]
__global__ void bias_relu_kernel(float* __restrict__ x, const float* __restrict__ s,
                                 const float* __restrict__ b) {
    int t = blockIdx.x * 256 + threadIdx.x;
    int c = t & 255;
    x[t] = fmaxf(fmaf(x[t], s[c], b[c]), 0.f);
}

__global__ void final_kernel(const float* __restrict__ h, const float* __restrict__ Wc2,
                             const float* __restrict__ bc2, float* __restrict__ out) {
    int t = blockIdx.x * blockDim.x + threadIdx.x;
    if (t >= NDOWN * 6) return;
    int i = t / 6, c = t % 6;
    float acc = bc2[c];
    for (int d = 0; d < 128; ++d) acc = fmaf(h[(size_t)i * 128 + d], Wc2[d * 6 + c], acc);
    out[t] = acc;
}

// ----------------------------------------------------------------------------
// launch (stream-parallel graph capture with event fork/join)
// ----------------------------------------------------------------------------
extern "C" void kernel_launch(void* const* d_in, const int* in_sizes, int n_in,
                              void* d_out, int out_size) {
    const float* points = (const float*)d_in[0];
    const float* We1 = (const float*)d_in[1];
    const float* se1 = (const float*)d_in[2];
    const float* be1 = (const float*)d_in[3];
    const float* We2 = (const float*)d_in[4];
    const float* se2 = (const float*)d_in[5];
    const float* be2 = (const float*)d_in[6];
    const float* Wq1 = (const float*)d_in[7];
    const float* Wk1 = (const float*)d_in[8];
    const float* Wv1 = (const float*)d_in[9];
    const float* sa1 = (const float*)d_in[10];
    const float* ba1 = (const float*)d_in[11];
    const float* Wq2 = (const float*)d_in[12];
    const float* Wk2 = (const float*)d_in[13];
    const float* Wv2 = (const float*)d_in[14];
    const float* sa2 = (const float*)d_in[15];
    const float* ba2 = (const float*)d_in[16];
    const float* Wtd = (const float*)d_in[17];
    const float* sd  = (const float*)d_in[18];
    const float* bd  = (const float*)d_in[19];
    const float* Wu1 = (const float*)d_in[20];
    const float* su1 = (const float*)d_in[21];
    const float* bu1 = (const float*)d_in[22];
    const float* Wu2 = (const float*)d_in[23];
    const float* su2 = (const float*)d_in[24];
    const float* bu2 = (const float*)d_in[25];
    const float* Wc1 = (const float*)d_in[26];
    const float* bc1 = (const float*)d_in[27];
    const float* scv = (const float*)d_in[28];
    const float* bcv = (const float*)d_in[29];
    const float* Wc2 = (const float*)d_in[30];
    const float* bc2 = (const float*)d_in[31];

    float* F = nullptr;
    int*   I = nullptr;
    cudaGetSymbolAddress((void**)&F, g_f);
    cudaGetSymbolAddress((void**)&I, g_i);

    float4* p4  = (float4*)(F + O_P4);
    float*  s1d = F + O_S1D;
    int*    s1i = I + OI_S1I;
    int*    idx = I + OI_IDX;

    // side stream + events (created per call; never destroyed — capture-safe)
    cudaStream_t st1;
    cudaStreamCreateWithFlags(&st1, cudaStreamNonBlocking);
    cudaEvent_t ev0, ev1, ev2, ev3, ev4, ev5;
    cudaEventCreateWithFlags(&ev0, cudaEventDisableTiming);
    cudaEventCreateWithFlags(&ev1, cudaEventDisableTiming);
    cudaEventCreateWithFlags(&ev2, cudaEventDisableTiming);
    cudaEventCreateWithFlags(&ev3, cudaEventDisableTiming);
    cudaEventCreateWithFlags(&ev4, cudaEventDisableTiming);
    cudaEventCreateWithFlags(&ev5, cudaEventDisableTiming);

    // --- fused prologue ---
    prologue_kernel<<<131, 128>>>(points, p4, We1, F + O_WD1, We2, F + O_WD2,
                                  bc1, scv, bcv, F + O_B2E);

    // --- fork: M1/M2 precompute on st1, kNN on main ---
    cudaEventRecord(ev0, 0);
    cudaStreamWaitEvent(st1, ev0, 0);
    abt_kernel<<<dim3(4, 32), 128, 0, st1>>>(Wq1, Wk1, F + O_M1, 128, 256, 1.f / sqrtf(256.f));
    abt_kernel<<<dim3(8, 64), 128, 0, st1>>>(Wq2, Wk2, F + O_M2, 256, 512, 1.f / sqrtf(512.f));

    knn_stage1_kernel<<<dim3(NPTS / 128, CHUNKS), 128>>>(p4, s1d, s1i);
    knn_stage2_kernel<<<NPTS / 128, 128>>>(s1d, s1i, idx);

    // --- edge_conv 1 ---
    edge1_kernel<<<NPTS / 4, 256>>>(p4, F + O_WD1, We1 + 192, idx, se1, be1, F + O_X1);

    // --- edge_conv 2 (tf32, batched halves) ---
    mma_gemm_kernel<0><<<dim3(1, 64, 2), 256>>>(
        F + O_X1, 64, F + O_WD2, We2 + 8192, nullptr, 128,
        F + O_A2, F + O_B2, nullptr, 128, 64, nullptr, 0, nullptr);
    gathermax_kernel<<<NPTS / 4, 128>>>((const float4*)(F + O_A2), (const float4*)(F + O_B2), idx,
                                        (const float4*)se2, (const float4*)be2,
                                        (float4*)(F + O_X2));

    // --- attn1: y1 on st1 (needs M1 - in st1 order), v1 on main, join ---
    cudaEventRecord(ev1, 0);
    cudaStreamWaitEvent(st1, ev1, 0);
    mma_gemm_kernel<0><<<dim3(1, 64, 1), 256, 0, st1>>>(
        F + O_X2, 128, F + O_M1, nullptr, nullptr, 128,
        F + O_Q1, nullptr, nullptr, 128, 128, nullptr, 0, nullptr);
    cudaEventRecord(ev2, st1);
    mma_gemm_kernel<0><<<dim3(2, 64, 1), 256>>>(
        F + O_X2, 128, Wv1, nullptr, nullptr, 256,
        F + O_V1, nullptr, nullptr, 256, 128, nullptr, 0, nullptr);
    cudaStreamWaitEvent(0, ev2, 0);
    attn_kernel<128, 256, 4><<<NPTS / 4, 256>>>(
        (const float4*)(F + O_Q1), (const float4*)(F + O_X2), (const float4*)(F + O_V1), idx,
        (const float4*)sa1, (const float4*)ba1, (float4*)(F + O_X3));

    // --- attn2: y2 on st1, v2 on main, join ---
    cudaEventRecord(ev3, 0);
    cudaStreamWaitEvent(st1, ev3, 0);
    mma_gemm_kernel<0><<<dim3(2, 64, 1), 256, 0, st1>>>(
        F + O_X3, 256, F + O_M2, nullptr, nullptr, 256,
        F + O_Q2, nullptr, nullptr, 256, 256, nullptr, 0, nullptr);
    cudaEventRecord(ev4, st1);
    mma_gemm_kernel<0><<<dim3(4, 64, 1), 256>>>(
        F + O_X3, 256, Wv2, nullptr, nullptr, 512,
        F + O_V2, nullptr, nullptr, 512, 256, nullptr, 0, nullptr);
    cudaStreamWaitEvent(0, ev4, 0);
    attn_kernel<256, 512, 2><<<NPTS / 2, 256>>>(
        (const float4*)(F + O_Q2), (const float4*)(F + O_X3), (const float4*)(F + O_V2), idx,
        (const float4*)sa2, (const float4*)ba2, (float4*)(F + O_X4));

    // --- downsample: PX = x4@Wtd[3:] + p@Wtd[0:3]; gather-max with fused pm ---
    mma_gemm_kernel<3><<<dim3(4, 64, 1), 256>>>(
        F + O_X4, 512, Wtd + 3 * 512, nullptr, nullptr, 512,
        F + O_PX, nullptr, nullptr, 512, 512, p4, 1, Wtd);
    downgather_kernel<<<NDOWN / 2, 256>>>((const float4*)(F + O_PX), p4, Wtd, idx,
                                          (const float4*)sd, (const float4*)bd,
                                          (float4*)(F + O_XD));

    // --- fork: Wu1 raw gemm on st1 || colsum+beff on main; join; bias_relu ---
    cudaEventRecord(ev5, 0);
    cudaStreamWaitEvent(st1, ev5, 0);
    gemm_kernel<64, 64, 0><<<dim3(4, 32), 256, 0, st1>>>(
        F + O_XD, 512, Wu1, 256, F + O_XU, 256, 512, nullptr, nullptr);
    cudaEvent_t ev6;
    cudaEventCreateWithFlags(&ev6, cudaEventDisableTiming);
    cudaEventRecord(ev6, st1);
    colsum_part_kernel<<<dim3(4, 8), 128>>>(F + O_XD, F + O_GS2);
    beff_kernel<<<1, 256>>>(F + O_GS2, Wu2, su2, bu1, bu2, F + O_BE);
    cudaStreamWaitEvent(0, ev6, 0);
    bias_relu_kernel<<<NDOWN, 256>>>(F + O_XU, su1, F + O_BE);

    // --- h = relu((xu@Wc1)*sc + (bc1*sc+bc)) ---
    gemm_kernel<64, 64, 2><<<dim3(2, 32), 256>>>(
        F + O_XU, 256, Wc1, 128, F + O_H, 128, 256, scv, F + O_B2E);

    // --- out = h@Wc2 + bc2 ---
    final_kernel<<<96, 128>>>(F + O_H, Wc2, bc2, (float*)d_out);
}

// round 9
// speedup vs baseline: 1.9206x; 1.0028x over previous
#include <cuda_runtime.h>
#include <math.h>
#include <float.h>

#define NPTS   8192
#define NDOWN  2048
#define KNN    16
#define CHUNKS 16

// ----------------------------------------------------------------------------
// Scratch arenas (no cudaMalloc allowed).
// ----------------------------------------------------------------------------
__device__ float g_f[40200000];
__device__ int   g_i[2400000];

static const size_t O_A1  = 0;
static const size_t O_B1  = O_A1  + (size_t)8192*64;
static const size_t O_X1  = O_B1  + (size_t)8192*64;
static const size_t O_A2  = O_X1  + (size_t)8192*64;
static const size_t O_B2  = O_A2  + (size_t)8192*128;
static const size_t O_X2  = O_B2  + (size_t)8192*128;
static const size_t O_Q1  = O_X2  + (size_t)8192*128;   // y1 [8192,128]
static const size_t O_K1  = O_Q1  + (size_t)8192*256;   // region reused for M1/M2
static const size_t O_V1  = O_K1  + (size_t)8192*256;
static const size_t O_X3  = O_V1  + (size_t)8192*256;
static const size_t O_Q2  = O_X3  + (size_t)8192*256;   // y2 [8192,256]
static const size_t O_K2  = O_Q2  + (size_t)8192*512;
static const size_t O_V2  = O_K2  + (size_t)8192*512;
static const size_t O_X4  = O_V2  + (size_t)8192*512;
static const size_t O_PX  = O_X4  + (size_t)8192*512;
static const size_t O_PM  = O_PX  + (size_t)8192*512;
static const size_t O_XD  = O_PM  + (size_t)2048*512;
static const size_t O_XU  = O_XD  + (size_t)2048*512;
static const size_t O_H   = O_XU  + (size_t)2048*256;
static const size_t O_GS  = O_H   + (size_t)2048*128;   // 512
static const size_t O_BE  = O_GS  + 512;                // 256
static const size_t O_B2E = O_BE  + 256;                // 128
static const size_t O_WD1 = O_B2E + 128;                // 192
static const size_t O_WD2 = O_WD1 + 192;                // 8192
static const size_t O_P4  = O_WD2 + 8192;               // 8192*4
static const size_t O_S1D = O_P4  + (size_t)8192*4;     // 8192*256
static const size_t O_GS2 = O_S1D + (size_t)8192*256;   // 4096

static const size_t O_M1   = O_K1;            // 128*128
static const size_t O_M2   = O_K1 + 65536;    // 256*256

static const size_t OI_IDX  = 0;                          // 8192*16
static const size_t OI_S1I  = (size_t)8192*16;            // 8192*256

// ----------------------------------------------------------------------------
// f32x2 helpers
// ----------------------------------------------------------------------------
typedef unsigned long long ull;

__device__ __forceinline__ ull pk2(float lo, float hi) {
    ull r; asm("mov.b64 %0,{%1,%2};" : "=l"(r) : "f"(lo), "f"(hi)); return r;
}
__device__ __forceinline__ ull fma2(ull a, ull b, ull c) {
    ull d; asm("fma.rn.f32x2 %0,%1,%2,%3;" : "=l"(d) : "l"(a), "l"(b), "l"(c)); return d;
}
__device__ __forceinline__ void upk2(ull v, float& lo, float& hi) {
    asm("mov.b64 {%0,%1},%2;" : "=f"(lo), "=f"(hi) : "l"(v));
}

__device__ __forceinline__ unsigned tf32cvt(float f) {
    unsigned r; asm("cvt.rna.tf32.f32 %0,%1;" : "=r"(r) : "f"(f)); return r;
}

// ----------------------------------------------------------------------------
// fused prologue: p4 prep, We diffs, b2eff.  grid 131, block 128.
// ----------------------------------------------------------------------------
__global__ void prologue_kernel(const float* __restrict__ p, float4* __restrict__ p4,
                                const float* __restrict__ We1, float* __restrict__ Wd1,
                                const float* __restrict__ We2, float* __restrict__ Wd2,
                                const float* __restrict__ bc1, const float* __restrict__ scv,
                                const float* __restrict__ bcv, float* __restrict__ b2e) {
    int b = blockIdx.x, t = threadIdx.x;
    if (b < 64) {
        int i = b * 128 + t;
        float x = p[3 * i], y = p[3 * i + 1], z = p[3 * i + 2];
        p4[i] = make_float4(x, y, z, x * x + y * y + z * z);
    } else if (b < 66) {
        int j = (b - 64) * 128 + t;
        if (j < 192) Wd1[j] = We1[j] - We1[192 + j];
    } else if (b < 130) {
        int j = (b - 66) * 128 + t;
        Wd2[j] = We2[j] - We2[8192 + j];
    } else {
        b2e[t] = fmaf(bc1[t], scv[t], bcv[t]);
    }
}

// ----------------------------------------------------------------------------
// M = scale * Wq @ Wk^T  (both [Din, D] row-major).  4 i's x 32 j's per block.
// ----------------------------------------------------------------------------
__global__ void abt_kernel(const float* __restrict__ Wq, const float* __restrict__ Wk,
                           float* __restrict__ M, int Din, int D, float scale) {
    int j = blockIdx.x * 32 + (threadIdx.x & 31);
    int i = blockIdx.y * 4 + (threadIdx.x >> 5);
    const float4* a = (const float4*)(Wq + (size_t)i * D);
    const float4* b = (const float4*)(Wk + (size_t)j * D);
    float s = 0.f;
    int n4 = D >> 2;
    for (int d = 0; d < n4; ++d) {
        float4 x = a[d], y = b[d];
        s = fmaf(x.x, y.x, fmaf(x.y, y.y, fmaf(x.z, y.z, fmaf(x.w, y.w, s))));
    }
    M[(size_t)i * Din + j] = s * scale;
}

// ----------------------------------------------------------------------------
// kNN (single pass; downsampled rows are idx at stride 4)
// ----------------------------------------------------------------------------
__device__ __forceinline__ void replace_rescan(float s, int j, float (&d)[KNN], int (&id)[KNN],
                                               float& wval, int& wpos) {
#pragma unroll
    for (int t = 0; t < KNN; ++t) if (t == wpos) { d[t] = s; id[t] = j; }
    wval = d[0]; wpos = 0;
#pragma unroll
    for (int t = 1; t < KNN; ++t) if (d[t] > wval) { wval = d[t]; wpos = t; }
}

__global__ void knn_stage1_kernel(const float4* __restrict__ p4,
                                  float* __restrict__ s1d, int* __restrict__ s1i) {
    const int CH = NPTS / CHUNKS;  // 512
    int q  = blockIdx.x * blockDim.x + threadIdx.x;
    int c0 = blockIdx.y * CH;

    float4 qp = p4[q];
    float qx = -2.f * qp.x, qy = -2.f * qp.y, qz = -2.f * qp.z;

    __shared__ float4 tile[512];
#pragma unroll
    for (int l = 0; l < 4; ++l) tile[threadIdx.x + l * 128] = p4[c0 + threadIdx.x + l * 128];
    __syncthreads();

    float d[KNN]; int id[KNN];
#pragma unroll
    for (int t = 0; t < KNN; ++t) {
        float4 c = tile[t];
        d[t] = fmaf(qx, c.x, fmaf(qy, c.y, fmaf(qz, c.z, c.w)));
        id[t] = c0 + t;
    }
    float wval = d[0]; int wpos = 0;
#pragma unroll
    for (int t = 1; t < KNN; ++t) if (d[t] > wval) { wval = d[t]; wpos = t; }

    float bs0 = 0.f, bs1 = 0.f, bs2 = 0.f, bs3 = 0.f;
    int   bj0 = 0, bj1 = 0, bj2 = 0, bj3 = 0, cnt = 0;

    for (int i = KNN; i < CH; ++i) {
        float4 c = tile[i];
        float s = fmaf(qx, c.x, fmaf(qy, c.y, fmaf(qz, c.z, c.w)));
        if (s < wval) {
            int j = c0 + i;
            if (cnt == 0)      { bs0 = s; bj0 = j; }
            else if (cnt == 1) { bs1 = s; bj1 = j; }
            else if (cnt == 2) { bs2 = s; bj2 = j; }
            else               { bs3 = s; bj3 = j; }
            cnt++;
        }
        if (__any_sync(0xffffffffu, cnt == 4)) {
            if (cnt > 0 && bs0 < wval) replace_rescan(bs0, bj0, d, id, wval, wpos);
            if (cnt > 1 && bs1 < wval) replace_rescan(bs1, bj1, d, id, wval, wpos);
            if (cnt > 2 && bs2 < wval) replace_rescan(bs2, bj2, d, id, wval, wpos);
            if (cnt > 3 && bs3 < wval) replace_rescan(bs3, bj3, d, id, wval, wpos);
            cnt = 0;
        }
    }
    if (cnt > 0 && bs0 < wval) replace_rescan(bs0, bj0, d, id, wval, wpos);
    if (cnt > 1 && bs1 < wval) replace_rescan(bs1, bj1, d, id, wval, wpos);
    if (cnt > 2 && bs2 < wval) replace_rescan(bs2, bj2, d, id, wval, wpos);
    if (cnt > 3 && bs3 < wval) replace_rescan(bs3, bj3, d, id, wval, wpos);

    size_t o = ((size_t)q * CHUNKS + blockIdx.y) * KNN;
#pragma unroll
    for (int t = 0; t < KNN; ++t) { s1d[o + t] = d[t]; s1i[o + t] = id[t]; }
}

__global__ void knn_stage2_kernel(const float* __restrict__ s1d, const int* __restrict__ s1i,
                                  int* __restrict__ outidx) {
    int q = blockIdx.x * blockDim.x + threadIdx.x;
    size_t base = (size_t)q * (CHUNKS * KNN);
    float d[KNN]; int id[KNN];
#pragma unroll
    for (int t = 0; t < KNN; ++t) { d[t] = s1d[base + t]; id[t] = s1i[base + t]; }
    float wval = d[0]; int wpos = 0;
#pragma unroll
    for (int t = 1; t < KNN; ++t) if (d[t] > wval) { wval = d[t]; wpos = t; }
    for (int c = KNN; c < CHUNKS * KNN; ++c) {
        float s = s1d[base + c];
        if (s < wval) replace_rescan(s, s1i[base + c], d, id, wval, wpos);
    }
#pragma unroll
    for (int t = 0; t < KNN; ++t) outidx[q * KNN + t] = id[t];
}

// ----------------------------------------------------------------------------
// Tensor-core GEMM (tf32 mma.sync.m16n8k8): C[M,N] = A[M,K] @ B[K,N].
// MODE 0: store. MODE 3: acc + p@W3 rows (row ld = ldc).
// ----------------------------------------------------------------------------
#define SP 132

template <int MODE>
__global__ __launch_bounds__(256, 2)
void mma_gemm_kernel(const float* __restrict__ A, int lda,
                     const float* __restrict__ Bp0, const float* __restrict__ Bp1,
                     const float* __restrict__ Bp2, int ldb,
                     float* __restrict__ Cp0, float* __restrict__ Cp1,
                     float* __restrict__ Cp2, int ldc, int K,
                     const float4* __restrict__ p4r, int rstride,
                     const float* __restrict__ W3) {
    __shared__ __align__(16) unsigned As[2][16][SP];
    __shared__ __align__(16) unsigned Bs[2][16][SP];

    const float* B = (blockIdx.z == 0) ? Bp0 : (blockIdx.z == 1) ? Bp1 : Bp2;
    float*       C = (blockIdx.z == 0) ? Cp0 : (blockIdx.z == 1) ? Cp1 : Cp2;

    int tid = threadIdx.x;
    int bm = blockIdx.y * 128, bn = blockIdx.x * 128;

    int ar = tid >> 2, ac4 = tid & 3;
    int bk = tid >> 5, bc = tid & 31;
    const float* Ap = A + (size_t)(bm + ar) * lda + ac4 * 4;
    const float* Bq = B + (size_t)bk * ldb + bn + bc * 4;

    float4 pa0, pa1, pb0, pb1;
    pa0 = *(const float4*)Ap;
    pa1 = *(const float4*)(Ap + (size_t)64 * lda);
    pb0 = *(const float4*)Bq;
    pb1 = *(const float4*)(Bq + (size_t)8 * ldb);
    Ap += 16;
    Bq += (size_t)16 * ldb;

    {
        As[0][ac4 * 4 + 0][ar] = tf32cvt(pa0.x);
        As[0][ac4 * 4 + 1][ar] = tf32cvt(pa0.y);
        As[0][ac4 * 4 + 2][ar] = tf32cvt(pa0.z);
        As[0][ac4 * 4 + 3][ar] = tf32cvt(pa0.w);
        As[0][ac4 * 4 + 0][ar + 64] = tf32cvt(pa1.x);
        As[0][ac4 * 4 + 1][ar + 64] = tf32cvt(pa1.y);
        As[0][ac4 * 4 + 2][ar + 64] = tf32cvt(pa1.z);
        As[0][ac4 * 4 + 3][ar + 64] = tf32cvt(pa1.w);
        uint4 t0 = make_uint4(tf32cvt(pb0.x), tf32cvt(pb0.y), tf32cvt(pb0.z), tf32cvt(pb0.w));
        uint4 t1 = make_uint4(tf32cvt(pb1.x), tf32cvt(pb1.y), tf32cvt(pb1.z), tf32cvt(pb1.w));
        *(uint4*)&Bs[0][bk][bc * 4] = t0;
        *(uint4*)&Bs[0][bk + 8][bc * 4] = t1;
    }
    __syncthreads();

    int lane = tid & 31, wid = tid >> 5;
    int wm = (wid & 1) * 64;
    int wn = (wid >> 1) * 32;
    int grp = lane >> 2, qid = lane & 3;

    float acc[4][4][4];
#pragma unroll
    for (int tm = 0; tm < 4; ++tm)
#pragma unroll
        for (int tn = 0; tn < 4; ++tn)
#pragma unroll
            for (int c = 0; c < 4; ++c) acc[tm][tn][c] = 0.f;

    int ktiles = K >> 4;
    for (int t = 0; t < ktiles; ++t) {
        bool more = (t + 1 < ktiles);
        if (more) {
            pa0 = *(const float4*)Ap;
            pa1 = *(const float4*)(Ap + (size_t)64 * lda);
            pb0 = *(const float4*)Bq;
            pb1 = *(const float4*)(Bq + (size_t)8 * ldb);
            Ap += 16;
            Bq += (size_t)16 * ldb;
        }

        int cb = t & 1;
#pragma unroll
        for (int kh = 0; kh < 2; ++kh) {
            int k0 = kh * 8;
            unsigned af[4][4], bf[4][2];
#pragma unroll
            for (int tm = 0; tm < 4; ++tm) {
                int m0 = wm + tm * 16 + grp;
                af[tm][0] = As[cb][k0 + qid][m0];
                af[tm][1] = As[cb][k0 + qid][m0 + 8];
                af[tm][2] = As[cb][k0 + qid + 4][m0];
                af[tm][3] = As[cb][k0 + qid + 4][m0 + 8];
            }
#pragma unroll
            for (int tn = 0; tn < 4; ++tn) {
                int n0 = wn + tn * 8 + grp;
                bf[tn][0] = Bs[cb][k0 + qid][n0];
                bf[tn][1] = Bs[cb][k0 + qid + 4][n0];
            }
#pragma unroll
            for (int tm = 0; tm < 4; ++tm)
#pragma unroll
                for (int tn = 0; tn < 4; ++tn) {
                    asm volatile(
                        "mma.sync.aligned.m16n8k8.row.col.f32.tf32.tf32.f32 "
                        "{%0,%1,%2,%3},{%4,%5,%6,%7},{%8,%9},{%0,%1,%2,%3};"
                        : "+f"(acc[tm][tn][0]), "+f"(acc[tm][tn][1]),
                          "+f"(acc[tm][tn][2]), "+f"(acc[tm][tn][3])
                        : "r"(af[tm][0]), "r"(af[tm][1]), "r"(af[tm][2]), "r"(af[tm][3]),
                          "r"(bf[tn][0]), "r"(bf[tn][1]));
                }
        }

        if (more) {
            int nb = (t + 1) & 1;
            As[nb][ac4 * 4 + 0][ar] = tf32cvt(pa0.x);
            As[nb][ac4 * 4 + 1][ar] = tf32cvt(pa0.y);
            As[nb][ac4 * 4 + 2][ar] = tf32cvt(pa0.z);
            As[nb][ac4 * 4 + 3][ar] = tf32cvt(pa0.w);
            As[nb][ac4 * 4 + 0][ar + 64] = tf32cvt(pa1.x);
            As[nb][ac4 * 4 + 1][ar + 64] = tf32cvt(pa1.y);
            As[nb][ac4 * 4 + 2][ar + 64] = tf32cvt(pa1.z);
            As[nb][ac4 * 4 + 3][ar + 64] = tf32cvt(pa1.w);
            uint4 t0 = make_uint4(tf32cvt(pb0.x), tf32cvt(pb0.y), tf32cvt(pb0.z), tf32cvt(pb0.w));
            uint4 t1 = make_uint4(tf32cvt(pb1.x), tf32cvt(pb1.y), tf32cvt(pb1.z), tf32cvt(pb1.w));
            *(uint4*)&Bs[nb][bk][bc * 4] = t0;
            *(uint4*)&Bs[nb][bk + 8][bc * 4] = t1;
        }
        __syncthreads();
    }

#pragma unroll
    for (int tm = 0; tm < 4; ++tm) {
        int r0 = bm + wm + tm * 16 + grp;
        int r1 = r0 + 8;
        float4 p0, p1;
        if (MODE == 3) {
            p0 = p4r[(size_t)r0 * rstride];
            p1 = p4r[(size_t)r1 * rstride];
        }
#pragma unroll
        for (int tn = 0; tn < 4; ++tn) {
            int col = bn + wn + tn * 8 + 2 * qid;
            float c0 = acc[tm][tn][0], c1 = acc[tm][tn][1];
            float c2 = acc[tm][tn][2], c3 = acc[tm][tn][3];
            if (MODE == 3) {
                float wa0 = W3[col],           wa1 = W3[col + 1];
                float wb0 = W3[ldc + col],     wb1 = W3[ldc + col + 1];
                float wc0 = W3[2 * ldc + col], wc1 = W3[2 * ldc + col + 1];
                c0 += fmaf(p0.x, wa0, fmaf(p0.y, wb0, p0.z * wc0));
                c1 += fmaf(p0.x, wa1, fmaf(p0.y, wb1, p0.z * wc1));
                c2 += fmaf(p1.x, wa0, fmaf(p1.y, wb0, p1.z * wc0));
                c3 += fmaf(p1.x, wa1, fmaf(p1.y, wb1, p1.z * wc1));
            }
            *(float2*)&C[(size_t)r0 * ldc + col] = make_float2(c0, c1);
            *(float2*)&C[(size_t)r1 * ldc + col] = make_float2(c2, c3);
        }
    }
}

// ----------------------------------------------------------------------------
// f32x2 GEMM, 64x64 tiles.  MODE 0: store.  MODE 2: relu(acc*s+b).
// ----------------------------------------------------------------------------
template <int BM, int BN, int MODE>
__global__ __launch_bounds__(256, 2)
void gemm_kernel(const float* __restrict__ A, int lda,
                 const float* __restrict__ Bp0, int ldb,
                 float* __restrict__ Cp0, int ldc, int K,
                 const float* __restrict__ scv, const float* __restrict__ biv) {
    constexpr int TM = BM / 16;
    constexpr int TN = BN / 16;
    constexpr int RP = TM / 2;
    constexpr int NA = BM / 64;
    constexpr int NB = BN / 64;
    constexpr int F4R = BN / 4;
    constexpr int BROW = 256 / F4R;

    __shared__ __align__(16) float As[2][16][BM + 4];
    __shared__ __align__(16) float Bs[2][16][BN];

    const float* B = Bp0;
    float*       C = Cp0;

    int tid = threadIdx.x;
    int bm = blockIdx.y * BM, bn = blockIdx.x * BN;

    int ar = tid >> 2, ac4 = tid & 3;
    int bk = tid / F4R, bc = tid % F4R;

    const float* Ap = A + (size_t)(bm + ar) * lda + ac4 * 4;
    const float* Bq = B + (size_t)bk * ldb + bn + bc * 4;

    float4 pa[NA], pb[NB];
#pragma unroll
    for (int l = 0; l < NA; ++l) pa[l] = *(const float4*)(Ap + (size_t)(64 * l) * lda);
#pragma unroll
    for (int l = 0; l < NB; ++l) pb[l] = *(const float4*)(Bq + (size_t)(BROW * l) * ldb);
    Ap += 16;
    Bq += (size_t)16 * ldb;

#pragma unroll
    for (int l = 0; l < NA; ++l) {
        int r = ar + 64 * l;
        As[0][ac4 * 4 + 0][r] = pa[l].x;
        As[0][ac4 * 4 + 1][r] = pa[l].y;
        As[0][ac4 * 4 + 2][r] = pa[l].z;
        As[0][ac4 * 4 + 3][r] = pa[l].w;
    }
#pragma unroll
    for (int l = 0; l < NB; ++l)
        *(float4*)&Bs[0][bk + BROW * l][bc * 4] = pb[l];
    __syncthreads();

    int tr = (tid >> 4) * TM;
    int tc = (tid & 15) * TN;

    ull acc[RP][TN];
#pragma unroll
    for (int rp = 0; rp < RP; ++rp)
#pragma unroll
        for (int c = 0; c < TN; ++c) acc[rp][c] = 0ull;

    int ktiles = K >> 4;
    for (int t = 0; t < ktiles; ++t) {
        bool more = (t + 1 < ktiles);
        if (more) {
#pragma unroll
            for (int l = 0; l < NA; ++l) pa[l] = *(const float4*)(Ap + (size_t)(64 * l) * lda);
#pragma unroll
            for (int l = 0; l < NB; ++l) pb[l] = *(const float4*)(Bq + (size_t)(BROW * l) * ldb);
            Ap += 16;
            Bq += (size_t)16 * ldb;
        }

        int cb = t & 1;
#pragma unroll
        for (int k = 0; k < 16; ++k) {
            float4 av[TM / 4], bv[TN / 4];
#pragma unroll
            for (int v = 0; v < TM / 4; ++v) av[v] = *(const float4*)&As[cb][k][tr + 4 * v];
#pragma unroll
            for (int v = 0; v < TN / 4; ++v) bv[v] = *(const float4*)&Bs[cb][k][tc + 4 * v];
            ull apk[RP];
#pragma unroll
            for (int v = 0; v < TM / 4; ++v) {
                apk[2 * v + 0] = pk2(av[v].x, av[v].y);
                apk[2 * v + 1] = pk2(av[v].z, av[v].w);
            }
#pragma unroll
            for (int v = 0; v < TN / 4; ++v) {
                {
                    ull bb = pk2(bv[v].x, bv[v].x);
#pragma unroll
                    for (int rp = 0; rp < RP; ++rp) acc[rp][4 * v + 0] = fma2(apk[rp], bb, acc[rp][4 * v + 0]);
                }
                {
                    ull bb = pk2(bv[v].y, bv[v].y);
#pragma unroll
                    for (int rp = 0; rp < RP; ++rp) acc[rp][4 * v + 1] = fma2(apk[rp], bb, acc[rp][4 * v + 1]);
                }
                {
                    ull bb = pk2(bv[v].z, bv[v].z);
#pragma unroll
                    for (int rp = 0; rp < RP; ++rp) acc[rp][4 * v + 2] = fma2(apk[rp], bb, acc[rp][4 * v + 2]);
                }
                {
                    ull bb = pk2(bv[v].w, bv[v].w);
#pragma unroll
                    for (int rp = 0; rp < RP; ++rp) acc[rp][4 * v + 3] = fma2(apk[rp], bb, acc[rp][4 * v + 3]);
                }
            }
        }

        if (more) {
            int nb = (t + 1) & 1;
#pragma unroll
            for (int l = 0; l < NA; ++l) {
                int r = ar + 64 * l;
                As[nb][ac4 * 4 + 0][r] = pa[l].x;
                As[nb][ac4 * 4 + 1][r] = pa[l].y;
                As[nb][ac4 * 4 + 2][r] = pa[l].z;
                As[nb][ac4 * 4 + 3][r] = pa[l].w;
            }
#pragma unroll
            for (int l = 0; l < NB; ++l)
                *(float4*)&Bs[nb][bk + BROW * l][bc * 4] = pb[l];
        }
        __syncthreads();
    }

    float sc8[TN], bi8[TN];
    if (MODE == 2) {
#pragma unroll
        for (int c = 0; c < TN; ++c) { sc8[c] = scv[bn + tc + c]; bi8[c] = biv[bn + tc + c]; }
    }
#pragma unroll
    for (int rp = 0; rp < RP; ++rp) {
        int r0 = bm + tr + 2 * rp, r1 = r0 + 1;
        float o0[TN], o1[TN];
#pragma unroll
        for (int c = 0; c < TN; ++c) upk2(acc[rp][c], o0[c], o1[c]);
        if (MODE == 2) {
#pragma unroll
            for (int c = 0; c < TN; ++c) {
                o0[c] = fmaxf(fmaf(o0[c], sc8[c], bi8[c]), 0.f);
                o1[c] = fmaxf(fmaf(o1[c], sc8[c], bi8[c]), 0.f);
            }
        }
#pragma unroll
        for (int v = 0; v < TN / 4; ++v) {
            *(float4*)&C[(size_t)r0 * ldc + bn + tc + 4 * v] =
                make_float4(o0[4 * v], o0[4 * v + 1], o0[4 * v + 2], o0[4 * v + 3]);
            *(float4*)&C[(size_t)r1 * ldc + bn + tc + 4 * v] =
                make_float4(o1[4 * v], o1[4 * v + 1], o1[4 * v + 2], o1[4 * v + 3]);
        }
    }
}

// ----------------------------------------------------------------------------
// edge_conv1 fused (K=3, C=64). 4 points/block, 256 threads.
// ----------------------------------------------------------------------------
__global__ void edge1_kernel(const float4* __restrict__ p4,
                             const float* __restrict__ Wd, const float* __restrict__ Wb,
                             const int* __restrict__ idx,
                             const float* __restrict__ s, const float* __restrict__ b,
                             float* __restrict__ out) {
    __shared__ float4 pj[4][KNN];
    int g = threadIdx.x >> 6, c = threadIdx.x & 63;
    int i = blockIdx.x * 4 + g;
    if (c < KNN) pj[g][c] = p4[idx[i * KNN + c]];
    __syncthreads();
    float4 pi = p4[i];
    float w0 = Wd[c], w1 = Wd[64 + c], w2 = Wd[128 + c];
    float u0 = Wb[c], u1 = Wb[64 + c], u2 = Wb[128 + c];
    float a = fmaf(pi.x, w0, fmaf(pi.y, w1, pi.z * w2));
    float sc = s[c], bv = b[c];
    float m = 0.f;
#pragma unroll
    for (int k = 0; k < KNN; ++k) {
        float4 pp = pj[g][k];
        float e = fmaf(pp.x, u0, fmaf(pp.y, u1, fmaf(pp.z, u2, a)));
        m = fmaxf(m, fmaf(e, sc, bv));
    }
    out[(size_t)i * 64 + c] = m;
}

// ----------------------------------------------------------------------------
// edge_conv2 gather-max (C=128, float4): 4 points/block, 128 threads.
// ----------------------------------------------------------------------------
__global__ void gathermax_kernel(const float4* __restrict__ Aa, const float4* __restrict__ Bb,
                                 const int* __restrict__ idx,
                                 const float4* __restrict__ s, const float4* __restrict__ b,
                                 float4* __restrict__ out) {
    const int C4 = 32;
    __shared__ int js[4][KNN];
    int g = threadIdx.x >> 5, c = threadIdx.x & 31;
    int i = blockIdx.x * 4 + g;
    if (c < KNN) js[g][c] = idx[i * KNN + c];
    __syncthreads();
    float4 a = Aa[(size_t)i * C4 + c];
    float4 sc = s[c], bv = b[c];
    float4 m = make_float4(0.f, 0.f, 0.f, 0.f);
#pragma unroll
    for (int k = 0; k < KNN; ++k) {
        float4 bj = Bb[(size_t)js[g][k] * C4 + c];
        m.x = fmaxf(m.x, fmaf(a.x + bj.x, sc.x, bv.x));
        m.y = fmaxf(m.y, fmaf(a.y + bj.y, sc.y, bv.y));
        m.z = fmaxf(m.z, fmaf(a.z + bj.z, sc.z, bv.z));
        m.w = fmaxf(m.w, fmaf(a.w + bj.w, sc.w, bv.w));
    }
    out[(size_t)i * C4 + c] = m;
}

// ----------------------------------------------------------------------------
// graph attention with precomputed y = x @ (scale * Wq Wk^T):
// logits_ij = y_i . x_j (scale folded into M).
// ----------------------------------------------------------------------------
template <int DIN, int D, int NP>
__global__ void attn_kernel(const float4* __restrict__ y, const float4* __restrict__ xin,
                            const float4* __restrict__ v, const int* __restrict__ idx,
                            const float4* __restrict__ s, const float4* __restrict__ b,
                            float4* __restrict__ out) {
    constexpr int D4 = D / 4, DIN4 = DIN / 4;
    int tid = threadIdx.x;
    int g = tid / D4, t = tid % D4;
    int i = blockIdx.x * NP + g;
    __shared__ float4 qs[NP][DIN4];
    __shared__ float lg[NP][KNN];
    __shared__ float aw[NP][KNN];
    __shared__ int js[NP][KNN];
    if (t < DIN4) qs[g][t] = y[(size_t)i * DIN4 + t];
    if (t < KNN) js[g][t] = idx[i * KNN + t];
    __syncthreads();

    constexpr int NW = D4 / 32;
    int w = t >> 5, lane = t & 31;
    for (int k = w; k < 8; k += NW) {
        const float4* k0 = xin + (size_t)js[g][k] * DIN4;
        const float4* k1 = xin + (size_t)js[g][k + 8] * DIN4;
        float s0 = 0.f, s1 = 0.f;
#pragma unroll
        for (int m = lane; m < DIN4; m += 32) {
            float4 a = qs[g][m];
            float4 c0 = k0[m], c1 = k1[m];
            s0 = fmaf(a.x, c0.x, fmaf(a.y, c0.y, fmaf(a.z, c0.z, fmaf(a.w, c0.w, s0))));
            s1 = fmaf(a.x, c1.x, fmaf(a.y, c1.y, fmaf(a.z, c1.z, fmaf(a.w, c1.w, s1))));
        }
#pragma unroll
        for (int o = 16; o; o >>= 1) {
            s0 += __shfl_xor_sync(0xffffffffu, s0, o);
            s1 += __shfl_xor_sync(0xffffffffu, s1, o);
        }
        if (lane == 0) {
            lg[g][k] = s0;
            lg[g][k + 8] = s1;
        }
    }
    __syncthreads();
    if (t < 32) {
        float l = (lane < KNN) ? lg[g][lane] : -FLT_MAX;
        float mx = l;
#pragma unroll
        for (int o = 16; o; o >>= 1) mx = fmaxf(mx, __shfl_xor_sync(0xffffffffu, mx, o));
        float e = (lane < KNN) ? expf(l - mx) : 0.f;
        float se = e;
#pragma unroll
        for (int o = 16; o; o >>= 1) se += __shfl_xor_sync(0xffffffffu, se, o);
        if (lane < KNN) aw[g][lane] = e / se;
    }
    __syncthreads();
    float4 yy = make_float4(0.f, 0.f, 0.f, 0.f);
#pragma unroll
    for (int k = 0; k < KNN; ++k) {
        float a = aw[g][k];
        float4 vv = v[(size_t)js[g][k] * D4 + t];
        yy.x = fmaf(a, vv.x, yy.x); yy.y = fmaf(a, vv.y, yy.y);
        yy.z = fmaf(a, vv.z, yy.z); yy.w = fmaf(a, vv.w, yy.w);
    }
    float4 sc = s[t], bv = b[t];
    float4 r;
    r.x = fmaxf(fmaf(yy.x, sc.x, bv.x), 0.f);
    r.y = fmaxf(fmaf(yy.y, sc.y, bv.y), 0.f);
    r.z = fmaxf(fmaf(yy.z, sc.z, bv.z), 0.f);
    r.w = fmaxf(fmaf(yy.w, sc.w, bv.w), 0.f);
    out[(size_t)i * D4 + t] = r;
}

// ----------------------------------------------------------------------------
// downsample gather-max with fused pm = p@W3 (float4): 2 pts/block, 256 thr.
// ----------------------------------------------------------------------------
__global__ void downgather_kernel(const float4* __restrict__ PX, const float4* __restrict__ p4,
                                  const float* __restrict__ W3, const int* __restrict__ idx,
                                  const float4* __restrict__ s, const float4* __restrict__ b,
                                  float4* __restrict__ out) {
    __shared__ int js[2][KNN];
    int g = threadIdx.x >> 7, c = threadIdx.x & 127;
    int i = blockIdx.x * 2 + g;
    if (c < KNN) js[g][c] = idx[(4 * i) * KNN + c];
    __syncthreads();
    float4 p = p4[4 * i];
    float4 wa = *(const float4*)&W3[4 * c];
    float4 wb = *(const float4*)&W3[512 + 4 * c];
    float4 wc = *(const float4*)&W3[1024 + 4 * c];
    float4 pm;
    pm.x = fmaf(p.x, wa.x, fmaf(p.y, wb.x, p.z * wc.x));
    pm.y = fmaf(p.x, wa.y, fmaf(p.y, wb.y, p.z * wc.y));
    pm.z = fmaf(p.x, wa.z, fmaf(p.y, wb.z, p.z * wc.z));
    pm.w = fmaf(p.x, wa.w, fmaf(p.y, wb.w, p.z * wc.w));
    float4 sc = s[c], bv = b[c];
    float4 m = make_float4(0.f, 0.f, 0.f, 0.f);
#pragma unroll
    for (int k = 0; k < KNN; ++k) {
        float4 px = PX[(size_t)js[g][k] * 128 + c];
        m.x = fmaxf(m.x, fmaf(px.x - pm.x, sc.x, bv.x));
        m.y = fmaxf(m.y, fmaf(px.y - pm.y, sc.y, bv.y));
        m.z = fmaxf(m.z, fmaf(px.z - pm.z, sc.z, bv.z));
        m.w = fmaxf(m.w, fmaf(px.w - pm.w, sc.w, bv.w));
    }
    out[(size_t)i * 128 + c] = m;
}

__global__ void colsum_part_kernel(const float* __restrict__ xd, float* __restrict__ gs2) {
    int c = blockIdx.x * blockDim.x + threadIdx.x;
    int g = blockIdx.y;
    float s = 0.f;
    for (int r = g * 256; r < (g + 1) * 256; ++r) s += xd[(size_t)r * 512 + c];
    gs2[g * 512 + c] = s;
}

// fused: reduce gs2 partials + beff.  1 block, 256 threads.
__global__ void beff_kernel(const float* __restrict__ gs2, const float* __restrict__ Wu2,
                            const float* __restrict__ su2, const float* __restrict__ bu1,
                            const float* __restrict__ bu2, float* __restrict__ be) {
    __shared__ float gsum[512];
    int tid = threadIdx.x;
    for (int c = tid; c < 512; c += 256) {
        float s = 0.f;
#pragma unroll
        for (int g = 0; g < 8; ++g) s += gs2[g * 512 + c];
        gsum[c] = s;
    }
    __syncthreads();
    float acc = 0.f;
    for (int d = 0; d < 512; ++d) acc = fmaf(gsum[d], Wu2[(size_t)d * 256 + tid], acc);
    be[tid] = bu1[tid] + bu2[tid] + su2[tid] * (acc * (1.f / 2048.f));
}

// xu = relu(xu * s[c] + b[c]), [2048,256]
__global__ void bias_relu_kernel(float* __restrict__ x, const float* __restrict__ s,
                                 const float* __restrict__ b) {
    int t = blockIdx.x * 256 + threadIdx.x;
    int c = t & 255;
    x[t] = fmaxf(fmaf(x[t], s[c], b[c]), 0.f);
}

__global__ void final_kernel(const float* __restrict__ h, const float* __restrict__ Wc2,
                             const float* __restrict__ bc2, float* __restrict__ out) {
    int t = blockIdx.x * blockDim.x + threadIdx.x;
    if (t >= NDOWN * 6) return;
    int i = t / 6, c = t % 6;
    float acc = bc2[c];
    for (int d = 0; d < 128; ++d) acc = fmaf(h[(size_t)i * 128 + d], Wc2[d * 6 + c], acc);
    out[t] = acc;
}

// ----------------------------------------------------------------------------
// launch (stream-parallel graph capture with event fork/join)
// ----------------------------------------------------------------------------
extern "C" void kernel_launch(void* const* d_in, const int* in_sizes, int n_in,
                              void* d_out, int out_size) {
    const float* points = (const float*)d_in[0];
    const float* We1 = (const float*)d_in[1];
    const float* se1 = (const float*)d_in[2];
    const float* be1 = (const float*)d_in[3];
    const float* We2 = (const float*)d_in[4];
    const float* se2 = (const float*)d_in[5];
    const float* be2 = (const float*)d_in[6];
    const float* Wq1 = (const float*)d_in[7];
    const float* Wk1 = (const float*)d_in[8];
    const float* Wv1 = (const float*)d_in[9];
    const float* sa1 = (const float*)d_in[10];
    const float* ba1 = (const float*)d_in[11];
    const float* Wq2 = (const float*)d_in[12];
    const float* Wk2 = (const float*)d_in[13];
    const float* Wv2 = (const float*)d_in[14];
    const float* sa2 = (const float*)d_in[15];
    const float* ba2 = (const float*)d_in[16];
    const float* Wtd = (const float*)d_in[17];
    const float* sd  = (const float*)d_in[18];
    const float* bd  = (const float*)d_in[19];
    const float* Wu1 = (const float*)d_in[20];
    const float* su1 = (const float*)d_in[21];
    const float* bu1 = (const float*)d_in[22];
    const float* Wu2 = (const float*)d_in[23];
    const float* su2 = (const float*)d_in[24];
    const float* bu2 = (const float*)d_in[25];
    const float* Wc1 = (const float*)d_in[26];
    const float* bc1 = (const float*)d_in[27];
    const float* scv = (const float*)d_in[28];
    const float* bcv = (const float*)d_in[29];
    const float* Wc2 = (const float*)d_in[30];
    const float* bc2 = (const float*)d_in[31];

    float* F = nullptr;
    int*   I = nullptr;
    cudaGetSymbolAddress((void**)&F, g_f);
    cudaGetSymbolAddress((void**)&I, g_i);

    float4* p4  = (float4*)(F + O_P4);
    float*  s1d = F + O_S1D;
    int*    s1i = I + OI_S1I;
    int*    idx = I + OI_IDX;

    // side stream + events (created per call; never destroyed — capture-safe)
    cudaStream_t st1;
    cudaStreamCreateWithFlags(&st1, cudaStreamNonBlocking);
    cudaEvent_t ev0, ev1, ev2, ev3, ev4, ev5;
    cudaEventCreateWithFlags(&ev0, cudaEventDisableTiming);
    cudaEventCreateWithFlags(&ev1, cudaEventDisableTiming);
    cudaEventCreateWithFlags(&ev2, cudaEventDisableTiming);
    cudaEventCreateWithFlags(&ev3, cudaEventDisableTiming);
    cudaEventCreateWithFlags(&ev4, cudaEventDisableTiming);
    cudaEventCreateWithFlags(&ev5, cudaEventDisableTiming);

    // --- fused prologue ---
    prologue_kernel<<<131, 128>>>(points, p4, We1, F + O_WD1, We2, F + O_WD2,
                                  bc1, scv, bcv, F + O_B2E);

    // --- fork: M1/M2 precompute on st1, kNN on main ---
    cudaEventRecord(ev0, 0);
    cudaStreamWaitEvent(st1, ev0, 0);
    abt_kernel<<<dim3(4, 32), 128, 0, st1>>>(Wq1, Wk1, F + O_M1, 128, 256, 1.f / sqrtf(256.f));
    abt_kernel<<<dim3(8, 64), 128, 0, st1>>>(Wq2, Wk2, F + O_M2, 256, 512, 1.f / sqrtf(512.f));

    knn_stage1_kernel<<<dim3(NPTS / 128, CHUNKS), 128>>>(p4, s1d, s1i);
    knn_stage2_kernel<<<NPTS / 128, 128>>>(s1d, s1i, idx);

    // --- edge_conv 1 ---
    edge1_kernel<<<NPTS / 4, 256>>>(p4, F + O_WD1, We1 + 192, idx, se1, be1, F + O_X1);

    // --- edge_conv 2 (tf32, batched halves) ---
    mma_gemm_kernel<0><<<dim3(1, 64, 2), 256>>>(
        F + O_X1, 64, F + O_WD2, We2 + 8192, nullptr, 128,
        F + O_A2, F + O_B2, nullptr, 128, 64, nullptr, 0, nullptr);
    gathermax_kernel<<<NPTS / 4, 128>>>((const float4*)(F + O_A2), (const float4*)(F + O_B2), idx,
                                        (const float4*)se2, (const float4*)be2,
                                        (float4*)(F + O_X2));

    // --- attn1: y1 on st1 (needs M1 - in st1 order), v1 on main, join ---
    cudaEventRecord(ev1, 0);
    cudaStreamWaitEvent(st1, ev1, 0);
    mma_gemm_kernel<0><<<dim3(1, 64, 1), 256, 0, st1>>>(
        F + O_X2, 128, F + O_M1, nullptr, nullptr, 128,
        F + O_Q1, nullptr, nullptr, 128, 128, nullptr, 0, nullptr);
    cudaEventRecord(ev2, st1);
    mma_gemm_kernel<0><<<dim3(2, 64, 1), 256>>>(
        F + O_X2, 128, Wv1, nullptr, nullptr, 256,
        F + O_V1, nullptr, nullptr, 256, 128, nullptr, 0, nullptr);
    cudaStreamWaitEvent(0, ev2, 0);
    attn_kernel<128, 256, 4><<<NPTS / 4, 256>>>(
        (const float4*)(F + O_Q1), (const float4*)(F + O_X2), (const float4*)(F + O_V1), idx,
        (const float4*)sa1, (const float4*)ba1, (float4*)(F + O_X3));

    // --- attn2: y2 on st1, v2 on main, join ---
    cudaEventRecord(ev3, 0);
    cudaStreamWaitEvent(st1, ev3, 0);
    mma_gemm_kernel<0><<<dim3(2, 64, 1), 256, 0, st1>>>(
        F + O_X3, 256, F + O_M2, nullptr, nullptr, 256,
        F + O_Q2, nullptr, nullptr, 256, 256, nullptr, 0, nullptr);
    cudaEventRecord(ev4, st1);
    mma_gemm_kernel<0><<<dim3(4, 64, 1), 256>>>(
        F + O_X3, 256, Wv2, nullptr, nullptr, 512,
        F + O_V2, nullptr, nullptr, 512, 256, nullptr, 0, nullptr);
    cudaStreamWaitEvent(0, ev4, 0);
    attn_kernel<256, 512, 2><<<NPTS / 2, 256>>>(
        (const float4*)(F + O_Q2), (const float4*)(F + O_X3), (const float4*)(F + O_V2), idx,
        (const float4*)sa2, (const float4*)ba2, (float4*)(F + O_X4));

    // --- downsample: PX = x4@Wtd[3:] + p@Wtd[0:3]; gather-max with fused pm ---
    mma_gemm_kernel<3><<<dim3(4, 64, 1), 256>>>(
        F + O_X4, 512, Wtd + 3 * 512, nullptr, nullptr, 512,
        F + O_PX, nullptr, nullptr, 512, 512, p4, 1, Wtd);
    downgather_kernel<<<NDOWN / 2, 256>>>((const float4*)(F + O_PX), p4, Wtd, idx,
                                          (const float4*)sd, (const float4*)bd,
                                          (float4*)(F + O_XD));

    // --- fork: Wu1 raw gemm on st1 || colsum+beff on main; join; bias_relu ---
    cudaEventRecord(ev5, 0);
    cudaStreamWaitEvent(st1, ev5, 0);
    gemm_kernel<64, 64, 0><<<dim3(4, 32), 256, 0, st1>>>(
        F + O_XD, 512, Wu1, 256, F + O_XU, 256, 512, nullptr, nullptr);
    cudaEvent_t ev6;
    cudaEventCreateWithFlags(&ev6, cudaEventDisableTiming);
    cudaEventRecord(ev6, st1);
    colsum_part_kernel<<<dim3(4, 8), 128>>>(F + O_XD, F + O_GS2);
    beff_kernel<<<1, 256>>>(F + O_GS2, Wu2, su2, bu1, bu2, F + O_BE);
    cudaStreamWaitEvent(0, ev6, 0);
    bias_relu_kernel<<<NDOWN, 256>>>(F + O_XU, su1, F + O_BE);

    // --- h = relu((xu@Wc1)*sc + (bc1*sc+bc)) ---
    gemm_kernel<64, 64, 2><<<dim3(2, 32), 256>>>(
        F + O_XU, 256, Wc1, 128, F + O_H, 128, 256, scv, F + O_B2E);

    // --- out = h@Wc2 + bc2 ---
    final_kernel<<<96, 128>>>(F + O_H, Wc2, bc2, (float*)d_out);
}

// round 10
// speedup vs baseline: 2.2106x; 1.1510x over previous
#include <cuda_runtime.h>
#include <math.h>
#include <float.h>

#define NPTS   8192
#define NDOWN  2048
#define KNN    16
#define CHUNKS 16

// ----------------------------------------------------------------------------
// Scratch arenas (no cudaMalloc allowed).
// ----------------------------------------------------------------------------
__device__ float g_f[40200000];
__device__ int   g_i[2400000];

static const size_t O_A1  = 0;
static const size_t O_B1  = O_A1  + (size_t)8192*64;
static const size_t O_X1  = O_B1  + (size_t)8192*64;
static const size_t O_A2  = O_X1  + (size_t)8192*64;
static const size_t O_B2  = O_A2  + (size_t)8192*128;
static const size_t O_X2  = O_B2  + (size_t)8192*128;
static const size_t O_Q1  = O_X2  + (size_t)8192*128;   // y1 [8192,128]
static const size_t O_K1  = O_Q1  + (size_t)8192*256;   // region reused for M1/M2
static const size_t O_V1  = O_K1  + (size_t)8192*256;
static const size_t O_X3  = O_V1  + (size_t)8192*256;
static const size_t O_Q2  = O_X3  + (size_t)8192*256;   // y2 [8192,256]
static const size_t O_K2  = O_Q2  + (size_t)8192*512;
static const size_t O_V2  = O_K2  + (size_t)8192*512;
static const size_t O_X4  = O_V2  + (size_t)8192*512;
static const size_t O_PX  = O_X4  + (size_t)8192*512;
static const size_t O_TAU = O_PX  + (size_t)8192*512;   // 8192 (reuses old PM slot)
static const size_t O_XD  = O_TAU + (size_t)2048*512;
static const size_t O_XU  = O_XD  + (size_t)2048*512;
static const size_t O_H   = O_XU  + (size_t)2048*256;
static const size_t O_GS  = O_H   + (size_t)2048*128;   // 512
static const size_t O_BE  = O_GS  + 512;                // 256
static const size_t O_B2E = O_BE  + 256;                // 128
static const size_t O_WD1 = O_B2E + 128;                // 192
static const size_t O_WD2 = O_WD1 + 192;                // 8192
static const size_t O_P4  = O_WD2 + 8192;               // 8192*4
static const size_t O_S1D = O_P4  + (size_t)8192*4;     // 8192*256
static const size_t O_GS2 = O_S1D + (size_t)8192*256;   // 4096

static const size_t O_M1   = O_K1;            // 128*128
static const size_t O_M2   = O_K1 + 65536;    // 256*256

static const size_t OI_IDX  = 0;                          // 8192*16
static const size_t OI_S1I  = (size_t)8192*16;            // 8192*256

// ----------------------------------------------------------------------------
// f32x2 helpers
// ----------------------------------------------------------------------------
typedef unsigned long long ull;

__device__ __forceinline__ ull pk2(float lo, float hi) {
    ull r; asm("mov.b64 %0,{%1,%2};" : "=l"(r) : "f"(lo), "f"(hi)); return r;
}
__device__ __forceinline__ ull fma2(ull a, ull b, ull c) {
    ull d; asm("fma.rn.f32x2 %0,%1,%2,%3;" : "=l"(d) : "l"(a), "l"(b), "l"(c)); return d;
}
__device__ __forceinline__ void upk2(ull v, float& lo, float& hi) {
    asm("mov.b64 {%0,%1},%2;" : "=f"(lo), "=f"(hi) : "l"(v));
}

__device__ __forceinline__ unsigned tf32cvt(float f) {
    unsigned r; asm("cvt.rna.tf32.f32 %0,%1;" : "=r"(r) : "f"(f)); return r;
}

// ----------------------------------------------------------------------------
// fused prologue: p4 prep, We diffs, b2eff.  grid 131, block 128.
// ----------------------------------------------------------------------------
__global__ void prologue_kernel(const float* __restrict__ p, float4* __restrict__ p4,
                                const float* __restrict__ We1, float* __restrict__ Wd1,
                                const float* __restrict__ We2, float* __restrict__ Wd2,
                                const float* __restrict__ bc1, const float* __restrict__ scv,
                                const float* __restrict__ bcv, float* __restrict__ b2e) {
    int b = blockIdx.x, t = threadIdx.x;
    if (b < 64) {
        int i = b * 128 + t;
        float x = p[3 * i], y = p[3 * i + 1], z = p[3 * i + 2];
        p4[i] = make_float4(x, y, z, x * x + y * y + z * z);
    } else if (b < 66) {
        int j = (b - 64) * 128 + t;
        if (j < 192) Wd1[j] = We1[j] - We1[192 + j];
    } else if (b < 130) {
        int j = (b - 66) * 128 + t;
        Wd2[j] = We2[j] - We2[8192 + j];
    } else {
        b2e[t] = fmaf(bc1[t], scv[t], bcv[t]);
    }
}

// ----------------------------------------------------------------------------
// M = scale * Wq @ Wk^T  (both [Din, D] row-major).  4 i's x 32 j's per block.
// ----------------------------------------------------------------------------
__global__ void abt_kernel(const float* __restrict__ Wq, const float* __restrict__ Wk,
                           float* __restrict__ M, int Din, int D, float scale) {
    int j = blockIdx.x * 32 + (threadIdx.x & 31);
    int i = blockIdx.y * 4 + (threadIdx.x >> 5);
    const float4* a = (const float4*)(Wq + (size_t)i * D);
    const float4* b = (const float4*)(Wk + (size_t)j * D);
    float s = 0.f;
    int n4 = D >> 2;
    for (int d = 0; d < n4; ++d) {
        float4 x = a[d], y = b[d];
        s = fmaf(x.x, y.x, fmaf(x.y, y.y, fmaf(x.z, y.z, fmaf(x.w, y.w, s))));
    }
    M[(size_t)i * Din + j] = s * scale;
}

// ----------------------------------------------------------------------------
// kNN with conservative precomputed threshold.
// ----------------------------------------------------------------------------
__device__ __forceinline__ void replace_rescan(float s, int j, float (&d)[KNN], int (&id)[KNN],
                                               float& wval, int& wpos) {
#pragma unroll
    for (int t = 0; t < KNN; ++t) if (t == wpos) { d[t] = s; id[t] = j; }
    wval = d[0]; wpos = 0;
#pragma unroll
    for (int t = 1; t < KNN; ++t) if (d[t] > wval) { wval = d[t]; wpos = t; }
}

// tau[q] = 16th-smallest of the 32 lane-mins over 64 strided candidates each.
// Safe upper bound on the query's true 16th-NN score (16 distinct candidates <= tau).
// warp per query; block 128 -> 4 queries; grid 2048.
__global__ void knn_tau_kernel(const float4* __restrict__ p4, float* __restrict__ tau) {
    int q = (blockIdx.x * blockDim.x + threadIdx.x) >> 5;
    int lane = threadIdx.x & 31;
    float4 qp = p4[q];
    float qx = -2.f * qp.x, qy = -2.f * qp.y, qz = -2.f * qp.z;
    float m = FLT_MAX;
#pragma unroll 8
    for (int t = 0; t < 64; ++t) {
        float4 c = p4[t * 32 + lane];
        float s = fmaf(qx, c.x, fmaf(qy, c.y, fmaf(qz, c.z, c.w)));
        m = fminf(m, s);
    }
    float v = m, tv = 0.f;
#pragma unroll
    for (int r = 0; r < KNN; ++r) {
        float mn = v;
#pragma unroll
        for (int o = 16; o; o >>= 1) mn = fminf(mn, __shfl_xor_sync(0xffffffffu, mn, o));
        tv = mn;
        unsigned ball = __ballot_sync(0xffffffffu, v == mn);
        int src = __ffs(ball) - 1;
        if (lane == src) v = FLT_MAX;
    }
    if (lane == 0) tau[q] = tv;
}

// grid (NPTS/128, CHUNKS), block 128. One 512-candidate tile per chunk.
// Keeps chunk top-16 of candidates with s <= tau (INF-padded).
__global__ void knn_stage1_kernel(const float4* __restrict__ p4, const float* __restrict__ taub,
                                  float* __restrict__ s1d, int* __restrict__ s1i) {
    const int CH = NPTS / CHUNKS;  // 512
    int q  = blockIdx.x * blockDim.x + threadIdx.x;
    int c0 = blockIdx.y * CH;

    float4 qp = p4[q];
    float qx = -2.f * qp.x, qy = -2.f * qp.y, qz = -2.f * qp.z;
    float tau = taub[q];

    __shared__ float4 tile[512];
#pragma unroll
    for (int l = 0; l < 4; ++l) tile[threadIdx.x + l * 128] = p4[c0 + threadIdx.x + l * 128];
    __syncthreads();

    float d[KNN]; int id[KNN];
#pragma unroll
    for (int t = 0; t < KNN; ++t) { d[t] = FLT_MAX; id[t] = 0; }
    float wval = FLT_MAX; int wpos = 0;

    for (int i = 0; i < CH; ++i) {
        float4 c = tile[i];
        float s = fmaf(qx, c.x, fmaf(qy, c.y, fmaf(qz, c.z, c.w)));
        if (s <= tau && s < wval) {
            replace_rescan(s, c0 + i, d, id, wval, wpos);
        }
    }

    size_t o = ((size_t)q * CHUNKS + blockIdx.y) * KNN;
#pragma unroll
    for (int t = 0; t < KNN; ++t) { s1d[o + t] = d[t]; s1i[o + t] = id[t]; }
}

__global__ void knn_stage2_kernel(const float* __restrict__ s1d, const int* __restrict__ s1i,
                                  int* __restrict__ outidx) {
    int q = blockIdx.x * blockDim.x + threadIdx.x;
    size_t base = (size_t)q * (CHUNKS * KNN);
    float d[KNN]; int id[KNN];
#pragma unroll
    for (int t = 0; t < KNN; ++t) { d[t] = s1d[base + t]; id[t] = s1i[base + t]; }
    float wval = d[0]; int wpos = 0;
#pragma unroll
    for (int t = 1; t < KNN; ++t) if (d[t] > wval) { wval = d[t]; wpos = t; }
    for (int c = KNN; c < CHUNKS * KNN; ++c) {
        float s = s1d[base + c];
        if (s < wval) replace_rescan(s, s1i[base + c], d, id, wval, wpos);
    }
#pragma unroll
    for (int t = 0; t < KNN; ++t) outidx[q * KNN + t] = id[t];
}

// ----------------------------------------------------------------------------
// Tensor-core GEMM (tf32 mma.sync.m16n8k8): C[M,N] = A[M,K] @ B[K,N].
// MODE 0: store. MODE 3: acc + p@W3 rows (row ld = ldc).
// ----------------------------------------------------------------------------
#define SP 132

template <int MODE>
__global__ __launch_bounds__(256, 2)
void mma_gemm_kernel(const float* __restrict__ A, int lda,
                     const float* __restrict__ Bp0, const float* __restrict__ Bp1,
                     const float* __restrict__ Bp2, int ldb,
                     float* __restrict__ Cp0, float* __restrict__ Cp1,
                     float* __restrict__ Cp2, int ldc, int K,
                     const float4* __restrict__ p4r, int rstride,
                     const float* __restrict__ W3) {
    __shared__ __align__(16) unsigned As[2][16][SP];
    __shared__ __align__(16) unsigned Bs[2][16][SP];

    const float* B = (blockIdx.z == 0) ? Bp0 : (blockIdx.z == 1) ? Bp1 : Bp2;
    float*       C = (blockIdx.z == 0) ? Cp0 : (blockIdx.z == 1) ? Cp1 : Cp2;

    int tid = threadIdx.x;
    int bm = blockIdx.y * 128, bn = blockIdx.x * 128;

    int ar = tid >> 2, ac4 = tid & 3;
    int bk = tid >> 5, bc = tid & 31;
    const float* Ap = A + (size_t)(bm + ar) * lda + ac4 * 4;
    const float* Bq = B + (size_t)bk * ldb + bn + bc * 4;

    float4 pa0, pa1, pb0, pb1;
    pa0 = *(const float4*)Ap;
    pa1 = *(const float4*)(Ap + (size_t)64 * lda);
    pb0 = *(const float4*)Bq;
    pb1 = *(const float4*)(Bq + (size_t)8 * ldb);
    Ap += 16;
    Bq += (size_t)16 * ldb;

    {
        As[0][ac4 * 4 + 0][ar] = tf32cvt(pa0.x);
        As[0][ac4 * 4 + 1][ar] = tf32cvt(pa0.y);
        As[0][ac4 * 4 + 2][ar] = tf32cvt(pa0.z);
        As[0][ac4 * 4 + 3][ar] = tf32cvt(pa0.w);
        As[0][ac4 * 4 + 0][ar + 64] = tf32cvt(pa1.x);
        As[0][ac4 * 4 + 1][ar + 64] = tf32cvt(pa1.y);
        As[0][ac4 * 4 + 2][ar + 64] = tf32cvt(pa1.z);
        As[0][ac4 * 4 + 3][ar + 64] = tf32cvt(pa1.w);
        uint4 t0 = make_uint4(tf32cvt(pb0.x), tf32cvt(pb0.y), tf32cvt(pb0.z), tf32cvt(pb0.w));
        uint4 t1 = make_uint4(tf32cvt(pb1.x), tf32cvt(pb1.y), tf32cvt(pb1.z), tf32cvt(pb1.w));
        *(uint4*)&Bs[0][bk][bc * 4] = t0;
        *(uint4*)&Bs[0][bk + 8][bc * 4] = t1;
    }
    __syncthreads();

    int lane = tid & 31, wid = tid >> 5;
    int wm = (wid & 1) * 64;
    int wn = (wid >> 1) * 32;
    int grp = lane >> 2, qid = lane & 3;

    float acc[4][4][4];
#pragma unroll
    for (int tm = 0; tm < 4; ++tm)
#pragma unroll
        for (int tn = 0; tn < 4; ++tn)
#pragma unroll
            for (int c = 0; c < 4; ++c) acc[tm][tn][c] = 0.f;

    int ktiles = K >> 4;
    for (int t = 0; t < ktiles; ++t) {
        bool more = (t + 1 < ktiles);
        if (more) {
            pa0 = *(const float4*)Ap;
            pa1 = *(const float4*)(Ap + (size_t)64 * lda);
            pb0 = *(const float4*)Bq;
            pb1 = *(const float4*)(Bq + (size_t)8 * ldb);
            Ap += 16;
            Bq += (size_t)16 * ldb;
        }

        int cb = t & 1;
#pragma unroll
        for (int kh = 0; kh < 2; ++kh) {
            int k0 = kh * 8;
            unsigned af[4][4], bf[4][2];
#pragma unroll
            for (int tm = 0; tm < 4; ++tm) {
                int m0 = wm + tm * 16 + grp;
                af[tm][0] = As[cb][k0 + qid][m0];
                af[tm][1] = As[cb][k0 + qid][m0 + 8];
                af[tm][2] = As[cb][k0 + qid + 4][m0];
                af[tm][3] = As[cb][k0 + qid + 4][m0 + 8];
            }
#pragma unroll
            for (int tn = 0; tn < 4; ++tn) {
                int n0 = wn + tn * 8 + grp;
                bf[tn][0] = Bs[cb][k0 + qid][n0];
                bf[tn][1] = Bs[cb][k0 + qid + 4][n0];
            }
#pragma unroll
            for (int tm = 0; tm < 4; ++tm)
#pragma unroll
                for (int tn = 0; tn < 4; ++tn) {
                    asm volatile(
                        "mma.sync.aligned.m16n8k8.row.col.f32.tf32.tf32.f32 "
                        "{%0,%1,%2,%3},{%4,%5,%6,%7},{%8,%9},{%0,%1,%2,%3};"
                        : "+f"(acc[tm][tn][0]), "+f"(acc[tm][tn][1]),
                          "+f"(acc[tm][tn][2]), "+f"(acc[tm][tn][3])
                        : "r"(af[tm][0]), "r"(af[tm][1]), "r"(af[tm][2]), "r"(af[tm][3]),
                          "r"(bf[tn][0]), "r"(bf[tn][1]));
                }
        }

        if (more) {
            int nb = (t + 1) & 1;
            As[nb][ac4 * 4 + 0][ar] = tf32cvt(pa0.x);
            As[nb][ac4 * 4 + 1][ar] = tf32cvt(pa0.y);
            As[nb][ac4 * 4 + 2][ar] = tf32cvt(pa0.z);
            As[nb][ac4 * 4 + 3][ar] = tf32cvt(pa0.w);
            As[nb][ac4 * 4 + 0][ar + 64] = tf32cvt(pa1.x);
            As[nb][ac4 * 4 + 1][ar + 64] = tf32cvt(pa1.y);
            As[nb][ac4 * 4 + 2][ar + 64] = tf32cvt(pa1.z);
            As[nb][ac4 * 4 + 3][ar + 64] = tf32cvt(pa1.w);
            uint4 t0 = make_uint4(tf32cvt(pb0.x), tf32cvt(pb0.y), tf32cvt(pb0.z), tf32cvt(pb0.w));
            uint4 t1 = make_uint4(tf32cvt(pb1.x), tf32cvt(pb1.y), tf32cvt(pb1.z), tf32cvt(pb1.w));
            *(uint4*)&Bs[nb][bk][bc * 4] = t0;
            *(uint4*)&Bs[nb][bk + 8][bc * 4] = t1;
        }
        __syncthreads();
    }

#pragma unroll
    for (int tm = 0; tm < 4; ++tm) {
        int r0 = bm + wm + tm * 16 + grp;
        int r1 = r0 + 8;
        float4 p0, p1;
        if (MODE == 3) {
            p0 = p4r[(size_t)r0 * rstride];
            p1 = p4r[(size_t)r1 * rstride];
        }
#pragma unroll
        for (int tn = 0; tn < 4; ++tn) {
            int col = bn + wn + tn * 8 + 2 * qid;
            float c0 = acc[tm][tn][0], c1 = acc[tm][tn][1];
            float c2 = acc[tm][tn][2], c3 = acc[tm][tn][3];
            if (MODE == 3) {
                float wa0 = W3[col],           wa1 = W3[col + 1];
                float wb0 = W3[ldc + col],     wb1 = W3[ldc + col + 1];
                float wc0 = W3[2 * ldc + col], wc1 = W3[2 * ldc + col + 1];
                c0 += fmaf(p0.x, wa0, fmaf(p0.y, wb0, p0.z * wc0));
                c1 += fmaf(p0.x, wa1, fmaf(p0.y, wb1, p0.z * wc1));
                c2 += fmaf(p1.x, wa0, fmaf(p1.y, wb0, p1.z * wc0));
                c3 += fmaf(p1.x, wa1, fmaf(p1.y, wb1, p1.z * wc1));
            }
            *(float2*)&C[(size_t)r0 * ldc + col] = make_float2(c0, c1);
            *(float2*)&C[(size_t)r1 * ldc + col] = make_float2(c2, c3);
        }
    }
}

// ----------------------------------------------------------------------------
// f32x2 GEMM, 64x64 tiles.  MODE 0: store.  MODE 2: relu(acc*s+b).
// ----------------------------------------------------------------------------
template <int BM, int BN, int MODE>
__global__ __launch_bounds__(256, 2)
void gemm_kernel(const float* __restrict__ A, int lda,
                 const float* __restrict__ Bp0, int ldb,
                 float* __restrict__ Cp0, int ldc, int K,
                 const float* __restrict__ scv, const float* __restrict__ biv) {
    constexpr int TM = BM / 16;
    constexpr int TN = BN / 16;
    constexpr int RP = TM / 2;
    constexpr int NA = BM / 64;
    constexpr int NB = BN / 64;
    constexpr int F4R = BN / 4;
    constexpr int BROW = 256 / F4R;

    __shared__ __align__(16) float As[2][16][BM + 4];
    __shared__ __align__(16) float Bs[2][16][BN];

    const float* B = Bp0;
    float*       C = Cp0;

    int tid = threadIdx.x;
    int bm = blockIdx.y * BM, bn = blockIdx.x * BN;

    int ar = tid >> 2, ac4 = tid & 3;
    int bk = tid / F4R, bc = tid % F4R;

    const float* Ap = A + (size_t)(bm + ar) * lda + ac4 * 4;
    const float* Bq = B + (size_t)bk * ldb + bn + bc * 4;

    float4 pa[NA], pb[NB];
#pragma unroll
    for (int l = 0; l < NA; ++l) pa[l] = *(const float4*)(Ap + (size_t)(64 * l) * lda);
#pragma unroll
    for (int l = 0; l < NB; ++l) pb[l] = *(const float4*)(Bq + (size_t)(BROW * l) * ldb);
    Ap += 16;
    Bq += (size_t)16 * ldb;

#pragma unroll
    for (int l = 0; l < NA; ++l) {
        int r = ar + 64 * l;
        As[0][ac4 * 4 + 0][r] = pa[l].x;
        As[0][ac4 * 4 + 1][r] = pa[l].y;
        As[0][ac4 * 4 + 2][r] = pa[l].z;
        As[0][ac4 * 4 + 3][r] = pa[l].w;
    }
#pragma unroll
    for (int l = 0; l < NB; ++l)
        *(float4*)&Bs[0][bk + BROW * l][bc * 4] = pb[l];
    __syncthreads();

    int tr = (tid >> 4) * TM;
    int tc = (tid & 15) * TN;

    ull acc[RP][TN];
#pragma unroll
    for (int rp = 0; rp < RP; ++rp)
#pragma unroll
        for (int c = 0; c < TN; ++c) acc[rp][c] = 0ull;

    int ktiles = K >> 4;
    for (int t = 0; t < ktiles; ++t) {
        bool more = (t + 1 < ktiles);
        if (more) {
#pragma unroll
            for (int l = 0; l < NA; ++l) pa[l] = *(const float4*)(Ap + (size_t)(64 * l) * lda);
#pragma unroll
            for (int l = 0; l < NB; ++l) pb[l] = *(const float4*)(Bq + (size_t)(BROW * l) * ldb);
            Ap += 16;
            Bq += (size_t)16 * ldb;
        }

        int cb = t & 1;
#pragma unroll
        for (int k = 0; k < 16; ++k) {
            float4 av[TM / 4], bv[TN / 4];
#pragma unroll
            for (int v = 0; v < TM / 4; ++v) av[v] = *(const float4*)&As[cb][k][tr + 4 * v];
#pragma unroll
            for (int v = 0; v < TN / 4; ++v) bv[v] = *(const float4*)&Bs[cb][k][tc + 4 * v];
            ull apk[RP];
#pragma unroll
            for (int v = 0; v < TM / 4; ++v) {
                apk[2 * v + 0] = pk2(av[v].x, av[v].y);
                apk[2 * v + 1] = pk2(av[v].z, av[v].w);
            }
#pragma unroll
            for (int v = 0; v < TN / 4; ++v) {
                {
                    ull bb = pk2(bv[v].x, bv[v].x);
#pragma unroll
                    for (int rp = 0; rp < RP; ++rp) acc[rp][4 * v + 0] = fma2(apk[rp], bb, acc[rp][4 * v + 0]);
                }
                {
                    ull bb = pk2(bv[v].y, bv[v].y);
#pragma unroll
                    for (int rp = 0; rp < RP; ++rp) acc[rp][4 * v + 1] = fma2(apk[rp], bb, acc[rp][4 * v + 1]);
                }
                {
                    ull bb = pk2(bv[v].z, bv[v].z);
#pragma unroll
                    for (int rp = 0; rp < RP; ++rp) acc[rp][4 * v + 2] = fma2(apk[rp], bb, acc[rp][4 * v + 2]);
                }
                {
                    ull bb = pk2(bv[v].w, bv[v].w);
#pragma unroll
                    for (int rp = 0; rp < RP; ++rp) acc[rp][4 * v + 3] = fma2(apk[rp], bb, acc[rp][4 * v + 3]);
                }
            }
        }

        if (more) {
            int nb = (t + 1) & 1;
#pragma unroll
            for (int l = 0; l < NA; ++l) {
                int r = ar + 64 * l;
                As[nb][ac4 * 4 + 0][r] = pa[l].x;
                As[nb][ac4 * 4 + 1][r] = pa[l].y;
                As[nb][ac4 * 4 + 2][r] = pa[l].z;
                As[nb][ac4 * 4 + 3][r] = pa[l].w;
            }
#pragma unroll
            for (int l = 0; l < NB; ++l)
                *(float4*)&Bs[nb][bk + BROW * l][bc * 4] = pb[l];
        }
        __syncthreads();
    }

    float sc8[TN], bi8[TN];
    if (MODE == 2) {
#pragma unroll
        for (int c = 0; c < TN; ++c) { sc8[c] = scv[bn + tc + c]; bi8[c] = biv[bn + tc + c]; }
    }
#pragma unroll
    for (int rp = 0; rp < RP; ++rp) {
        int r0 = bm + tr + 2 * rp, r1 = r0 + 1;
        float o0[TN], o1[TN];
#pragma unroll
        for (int c = 0; c < TN; ++c) upk2(acc[rp][c], o0[c], o1[c]);
        if (MODE == 2) {
#pragma unroll
            for (int c = 0; c < TN; ++c) {
                o0[c] = fmaxf(fmaf(o0[c], sc8[c], bi8[c]), 0.f);
                o1[c] = fmaxf(fmaf(o1[c], sc8[c], bi8[c]), 0.f);
            }
        }
#pragma unroll
        for (int v = 0; v < TN / 4; ++v) {
            *(float4*)&C[(size_t)r0 * ldc + bn + tc + 4 * v] =
                make_float4(o0[4 * v], o0[4 * v + 1], o0[4 * v + 2], o0[4 * v + 3]);
            *(float4*)&C[(size_t)r1 * ldc + bn + tc + 4 * v] =
                make_float4(o1[4 * v], o1[4 * v + 1], o1[4 * v + 2], o1[4 * v + 3]);
        }
    }
}

// ----------------------------------------------------------------------------
// edge_conv1 fused (K=3, C=64). 4 points/block, 256 threads.
// ----------------------------------------------------------------------------
__global__ void edge1_kernel(const float4* __restrict__ p4,
                             const float* __restrict__ Wd, const float* __restrict__ Wb,
                             const int* __restrict__ idx,
                             const float* __restrict__ s, const float* __restrict__ b,
                             float* __restrict__ out) {
    __shared__ float4 pj[4][KNN];
    int g = threadIdx.x >> 6, c = threadIdx.x & 63;
    int i = blockIdx.x * 4 + g;
    if (c < KNN) pj[g][c] = p4[idx[i * KNN + c]];
    __syncthreads();
    float4 pi = p4[i];
    float w0 = Wd[c], w1 = Wd[64 + c], w2 = Wd[128 + c];
    float u0 = Wb[c], u1 = Wb[64 + c], u2 = Wb[128 + c];
    float a = fmaf(pi.x, w0, fmaf(pi.y, w1, pi.z * w2));
    float sc = s[c], bv = b[c];
    float m = 0.f;
#pragma unroll
    for (int k = 0; k < KNN; ++k) {
        float4 pp = pj[g][k];
        float e = fmaf(pp.x, u0, fmaf(pp.y, u1, fmaf(pp.z, u2, a)));
        m = fmaxf(m, fmaf(e, sc, bv));
    }
    out[(size_t)i * 64 + c] = m;
}

// ----------------------------------------------------------------------------
// edge_conv2 gather-max (C=128, float4): 4 points/block, 128 threads.
// ----------------------------------------------------------------------------
__global__ void gathermax_kernel(const float4* __restrict__ Aa, const float4* __restrict__ Bb,
                                 const int* __restrict__ idx,
                                 const float4* __restrict__ s, const float4* __restrict__ b,
                                 float4* __restrict__ out) {
    const int C4 = 32;
    __shared__ int js[4][KNN];
    int g = threadIdx.x >> 5, c = threadIdx.x & 31;
    int i = blockIdx.x * 4 + g;
    if (c < KNN) js[g][c] = idx[i * KNN + c];
    __syncthreads();
    float4 a = Aa[(size_t)i * C4 + c];
    float4 sc = s[c], bv = b[c];
    float4 m = make_float4(0.f, 0.f, 0.f, 0.f);
#pragma unroll
    for (int k = 0; k < KNN; ++k) {
        float4 bj = Bb[(size_t)js[g][k] * C4 + c];
        m.x = fmaxf(m.x, fmaf(a.x + bj.x, sc.x, bv.x));
        m.y = fmaxf(m.y, fmaf(a.y + bj.y, sc.y, bv.y));
        m.z = fmaxf(m.z, fmaf(a.z + bj.z, sc.z, bv.z));
        m.w = fmaxf(m.w, fmaf(a.w + bj.w, sc.w, bv.w));
    }
    out[(size_t)i * C4 + c] = m;
}

// ----------------------------------------------------------------------------
// graph attention with precomputed y = x @ (scale * Wq Wk^T):
// logits_ij = y_i . x_j (scale folded into M).
// ----------------------------------------------------------------------------
template <int DIN, int D, int NP>
__global__ void attn_kernel(const float4* __restrict__ y, const float4* __restrict__ xin,
                            const float4* __restrict__ v, const int* __restrict__ idx,
                            const float4* __restrict__ s, const float4* __restrict__ b,
                            float4* __restrict__ out) {
    constexpr int D4 = D / 4, DIN4 = DIN / 4;
    int tid = threadIdx.x;
    int g = tid / D4, t = tid % D4;
    int i = blockIdx.x * NP + g;
    __shared__ float4 qs[NP][DIN4];
    __shared__ float lg[NP][KNN];
    __shared__ float aw[NP][KNN];
    __shared__ int js[NP][KNN];
    if (t < DIN4) qs[g][t] = y[(size_t)i * DIN4 + t];
    if (t < KNN) js[g][t] = idx[i * KNN + t];
    __syncthreads();

    constexpr int NW = D4 / 32;
    int w = t >> 5, lane = t & 31;
    for (int k = w; k < 8; k += NW) {
        const float4* k0 = xin + (size_t)js[g][k] * DIN4;
        const float4* k1 = xin + (size_t)js[g][k + 8] * DIN4;
        float s0 = 0.f, s1 = 0.f;
#pragma unroll
        for (int m = lane; m < DIN4; m += 32) {
            float4 a = qs[g][m];
            float4 c0 = k0[m], c1 = k1[m];
            s0 = fmaf(a.x, c0.x, fmaf(a.y, c0.y, fmaf(a.z, c0.z, fmaf(a.w, c0.w, s0))));
            s1 = fmaf(a.x, c1.x, fmaf(a.y, c1.y, fmaf(a.z, c1.z, fmaf(a.w, c1.w, s1))));
        }
#pragma unroll
        for (int o = 16; o; o >>= 1) {
            s0 += __shfl_xor_sync(0xffffffffu, s0, o);
            s1 += __shfl_xor_sync(0xffffffffu, s1, o);
        }
        if (lane == 0) {
            lg[g][k] = s0;
            lg[g][k + 8] = s1;
        }
    }
    __syncthreads();
    if (t < 32) {
        float l = (lane < KNN) ? lg[g][lane] : -FLT_MAX;
        float mx = l;
#pragma unroll
        for (int o = 16; o; o >>= 1) mx = fmaxf(mx, __shfl_xor_sync(0xffffffffu, mx, o));
        float e = (lane < KNN) ? expf(l - mx) : 0.f;
        float se = e;
#pragma unroll
        for (int o = 16; o; o >>= 1) se += __shfl_xor_sync(0xffffffffu, se, o);
        if (lane < KNN) aw[g][lane] = e / se;
    }
    __syncthreads();
    float4 yy = make_float4(0.f, 0.f, 0.f, 0.f);
#pragma unroll
    for (int k = 0; k < KNN; ++k) {
        float a = aw[g][k];
        float4 vv = v[(size_t)js[g][k] * D4 + t];
        yy.x = fmaf(a, vv.x, yy.x); yy.y = fmaf(a, vv.y, yy.y);
        yy.z = fmaf(a, vv.z, yy.z); yy.w = fmaf(a, vv.w, yy.w);
    }
    float4 sc = s[t], bv = b[t];
    float4 r;
    r.x = fmaxf(fmaf(yy.x, sc.x, bv.x), 0.f);
    r.y = fmaxf(fmaf(yy.y, sc.y, bv.y), 0.f);
    r.z = fmaxf(fmaf(yy.z, sc.z, bv.z), 0.f);
    r.w = fmaxf(fmaf(yy.w, sc.w, bv.w), 0.f);
    out[(size_t)i * D4 + t] = r;
}

// ----------------------------------------------------------------------------
// downsample gather-max with fused pm = p@W3 (float4): 2 pts/block, 256 thr.
// ----------------------------------------------------------------------------
__global__ void downgather_kernel(const float4* __restrict__ PX, const float4* __restrict__ p4,
                                  const float* __restrict__ W3, const int* __restrict__ idx,
                                  const float4* __restrict__ s, const float4* __restrict__ b,
                                  float4* __restrict__ out) {
    __shared__ int js[2][KNN];
    int g = threadIdx.x >> 7, c = threadIdx.x & 127;
    int i = blockIdx.x * 2 + g;
    if (c < KNN) js[g][c] = idx[(4 * i) * KNN + c];
    __syncthreads();
    float4 p = p4[4 * i];
    float4 wa = *(const float4*)&W3[4 * c];
    float4 wb = *(const float4*)&W3[512 + 4 * c];
    float4 wc = *(const float4*)&W3[1024 + 4 * c];
    float4 pm;
    pm.x = fmaf(p.x, wa.x, fmaf(p.y, wb.x, p.z * wc.x));
    pm.y = fmaf(p.x, wa.y, fmaf(p.y, wb.y, p.z * wc.y));
    pm.z = fmaf(p.x, wa.z, fmaf(p.y, wb.z, p.z * wc.z));
    pm.w = fmaf(p.x, wa.w, fmaf(p.y, wb.w, p.z * wc.w));
    float4 sc = s[c], bv = b[c];
    float4 m = make_float4(0.f, 0.f, 0.f, 0.f);
#pragma unroll
    for (int k = 0; k < KNN; ++k) {
        float4 px = PX[(size_t)js[g][k] * 128 + c];
        m.x = fmaxf(m.x, fmaf(px.x - pm.x, sc.x, bv.x));
        m.y = fmaxf(m.y, fmaf(px.y - pm.y, sc.y, bv.y));
        m.z = fmaxf(m.z, fmaf(px.z - pm.z, sc.z, bv.z));
        m.w = fmaxf(m.w, fmaf(px.w - pm.w, sc.w, bv.w));
    }
    out[(size_t)i * 128 + c] = m;
}

__global__ void colsum_part_kernel(const float* __restrict__ xd, float* __restrict__ gs2) {
    int c = blockIdx.x * blockDim.x + threadIdx.x;
    int g = blockIdx.y;
    float s = 0.f;
    for (int r = g * 256; r < (g + 1) * 256; ++r) s += xd[(size_t)r * 512 + c];
    gs2[g * 512 + c] = s;
}

// fused: reduce gs2 partials + beff.  1 block, 256 threads.
__global__ void beff_kernel(const float* __restrict__ gs2, const float* __restrict__ Wu2,
                            const float* __restrict__ su2, const float* __restrict__ bu1,
                            const float* __restrict__ bu2, float* __restrict__ be) {
    __shared__ float gsum[512];
    int tid = threadIdx.x;
    for (int c = tid; c < 512; c += 256) {
        float s = 0.f;
#pragma unroll
        for (int g = 0; g < 8; ++g) s += gs2[g * 512 + c];
        gsum[c] = s;
    }
    __syncthreads();
    float acc = 0.f;
    for (int d = 0; d < 512; ++d) acc = fmaf(gsum[d], Wu2[(size_t)d * 256 + tid], acc);
    be[tid] = bu1[tid] + bu2[tid] + su2[tid] * (acc * (1.f / 2048.f));
}

// xu = relu(xu * s[c] + b[c]), [2048,256]
__global__ void bias_relu_kernel(float* __restrict__ x, const float* __restrict__ s,
                                 const float* __restrict__ b) {
    int t = blockIdx.x * 256 + threadIdx.x;
    int c = t & 255;
    x[t] = fmaxf(fmaf(x[t], s[c], b[c]), 0.f);
}

__global__ void final_kernel(const float* __restrict__ h, const float* __restrict__ Wc2,
                             const float* __restrict__ bc2, float* __restrict__ out) {
    int t = blockIdx.x * blockDim.x + threadIdx.x;
    if (t >= NDOWN * 6) return;
    int i = t / 6, c = t % 6;
    float acc = bc2[c];
    for (int d = 0; d < 128; ++d) acc = fmaf(h[(size_t)i * 128 + d], Wc2[d * 6 + c], acc);
    out[t] = acc;
}

// ----------------------------------------------------------------------------
// launch (stream-parallel graph capture with event fork/join)
// ----------------------------------------------------------------------------
extern "C" void kernel_launch(void* const* d_in, const int* in_sizes, int n_in,
                              void* d_out, int out_size) {
    const float* points = (const float*)d_in[0];
    const float* We1 = (const float*)d_in[1];
    const float* se1 = (const float*)d_in[2];
    const float* be1 = (const float*)d_in[3];
    const float* We2 = (const float*)d_in[4];
    const float* se2 = (const float*)d_in[5];
    const float* be2 = (const float*)d_in[6];
    const float* Wq1 = (const float*)d_in[7];
    const float* Wk1 = (const float*)d_in[8];
    const float* Wv1 = (const float*)d_in[9];
    const float* sa1 = (const float*)d_in[10];
    const float* ba1 = (const float*)d_in[11];
    const float* Wq2 = (const float*)d_in[12];
    const float* Wk2 = (const float*)d_in[13];
    const float* Wv2 = (const float*)d_in[14];
    const float* sa2 = (const float*)d_in[15];
    const float* ba2 = (const float*)d_in[16];
    const float* Wtd = (const float*)d_in[17];
    const float* sd  = (const float*)d_in[18];
    const float* bd  = (const float*)d_in[19];
    const float* Wu1 = (const float*)d_in[20];
    const float* su1 = (const float*)d_in[21];
    const float* bu1 = (const float*)d_in[22];
    const float* Wu2 = (const float*)d_in[23];
    const float* su2 = (const float*)d_in[24];
    const float* bu2 = (const float*)d_in[25];
    const float* Wc1 = (const float*)d_in[26];
    const float* bc1 = (const float*)d_in[27];
    const float* scv = (const float*)d_in[28];
    const float* bcv = (const float*)d_in[29];
    const float* Wc2 = (const float*)d_in[30];
    const float* bc2 = (const float*)d_in[31];

    float* F = nullptr;
    int*   I = nullptr;
    cudaGetSymbolAddress((void**)&F, g_f);
    cudaGetSymbolAddress((void**)&I, g_i);

    float4* p4  = (float4*)(F + O_P4);
    float*  s1d = F + O_S1D;
    int*    s1i = I + OI_S1I;
    int*    idx = I + OI_IDX;

    // side stream + events (created per call; capture-safe)
    cudaStream_t st1;
    cudaStreamCreateWithFlags(&st1, cudaStreamNonBlocking);
    cudaEvent_t ev0, ev1, ev2, ev3, ev4, ev5, ev6;
    cudaEventCreateWithFlags(&ev0, cudaEventDisableTiming);
    cudaEventCreateWithFlags(&ev1, cudaEventDisableTiming);
    cudaEventCreateWithFlags(&ev2, cudaEventDisableTiming);
    cudaEventCreateWithFlags(&ev3, cudaEventDisableTiming);
    cudaEventCreateWithFlags(&ev4, cudaEventDisableTiming);
    cudaEventCreateWithFlags(&ev5, cudaEventDisableTiming);
    cudaEventCreateWithFlags(&ev6, cudaEventDisableTiming);

    // --- fused prologue ---
    prologue_kernel<<<131, 128>>>(points, p4, We1, F + O_WD1, We2, F + O_WD2,
                                  bc1, scv, bcv, F + O_B2E);

    // --- fork: M1/M2 precompute on st1, kNN on main ---
    cudaEventRecord(ev0, 0);
    cudaStreamWaitEvent(st1, ev0, 0);
    abt_kernel<<<dim3(4, 32), 128, 0, st1>>>(Wq1, Wk1, F + O_M1, 128, 256, 1.f / sqrtf(256.f));
    abt_kernel<<<dim3(8, 64), 128, 0, st1>>>(Wq2, Wk2, F + O_M2, 256, 512, 1.f / sqrtf(512.f));

    // kNN: conservative threshold, then sparse chunked scan, then merge
    knn_tau_kernel<<<2048, 128>>>(p4, F + O_TAU);
    knn_stage1_kernel<<<dim3(NPTS / 128, CHUNKS), 128>>>(p4, F + O_TAU, s1d, s1i);
    knn_stage2_kernel<<<NPTS / 128, 128>>>(s1d, s1i, idx);

    // --- edge_conv 1 ---
    edge1_kernel<<<NPTS / 4, 256>>>(p4, F + O_WD1, We1 + 192, idx, se1, be1, F + O_X1);

    // --- edge_conv 2 (tf32, batched halves) ---
    mma_gemm_kernel<0><<<dim3(1, 64, 2), 256>>>(
        F + O_X1, 64, F + O_WD2, We2 + 8192, nullptr, 128,
        F + O_A2, F + O_B2, nullptr, 128, 64, nullptr, 0, nullptr);
    gathermax_kernel<<<NPTS / 4, 128>>>((const float4*)(F + O_A2), (const float4*)(F + O_B2), idx,
                                        (const float4*)se2, (const float4*)be2,
                                        (float4*)(F + O_X2));

    // --- attn1: y1 on st1 (needs M1 - in st1 order), v1 on main, join ---
    cudaEventRecord(ev1, 0);
    cudaStreamWaitEvent(st1, ev1, 0);
    mma_gemm_kernel<0><<<dim3(1, 64, 1), 256, 0, st1>>>(
        F + O_X2, 128, F + O_M1, nullptr, nullptr, 128,
        F + O_Q1, nullptr, nullptr, 128, 128, nullptr, 0, nullptr);
    cudaEventRecord(ev2, st1);
    mma_gemm_kernel<0><<<dim3(2, 64, 1), 256>>>(
        F + O_X2, 128, Wv1, nullptr, nullptr, 256,
        F + O_V1, nullptr, nullptr, 256, 128, nullptr, 0, nullptr);
    cudaStreamWaitEvent(0, ev2, 0);
    attn_kernel<128, 256, 4><<<NPTS / 4, 256>>>(
        (const float4*)(F + O_Q1), (const float4*)(F + O_X2), (const float4*)(F + O_V1), idx,
        (const float4*)sa1, (const float4*)ba1, (float4*)(F + O_X3));

    // --- attn2: y2 on st1, v2 on main, join ---
    cudaEventRecord(ev3, 0);
    cudaStreamWaitEvent(st1, ev3, 0);
    mma_gemm_kernel<0><<<dim3(2, 64, 1), 256, 0, st1>>>(
        F + O_X3, 256, F + O_M2, nullptr, nullptr, 256,
        F + O_Q2, nullptr, nullptr, 256, 256, nullptr, 0, nullptr);
    cudaEventRecord(ev4, st1);
    mma_gemm_kernel<0><<<dim3(4, 64, 1), 256>>>(
        F + O_X3, 256, Wv2, nullptr, nullptr, 512,
        F + O_V2, nullptr, nullptr, 512, 256, nullptr, 0, nullptr);
    cudaStreamWaitEvent(0, ev4, 0);
    attn_kernel<256, 512, 2><<<NPTS / 2, 256>>>(
        (const float4*)(F + O_Q2), (const float4*)(F + O_X3), (const float4*)(F + O_V2), idx,
        (const float4*)sa2, (const float4*)ba2, (float4*)(F + O_X4));

    // --- downsample: PX = x4@Wtd[3:] + p@Wtd[0:3]; gather-max with fused pm ---
    mma_gemm_kernel<3><<<dim3(4, 64, 1), 256>>>(
        F + O_X4, 512, Wtd + 3 * 512, nullptr, nullptr, 512,
        F + O_PX, nullptr, nullptr, 512, 512, p4, 1, Wtd);
    downgather_kernel<<<NDOWN / 2, 256>>>((const float4*)(F + O_PX), p4, Wtd, idx,
                                          (const float4*)sd, (const float4*)bd,
                                          (float4*)(F + O_XD));

    // --- fork: Wu1 raw gemm on st1 || colsum+beff on main; join; bias_relu ---
    cudaEventRecord(ev5, 0);
    cudaStreamWaitEvent(st1, ev5, 0);
    gemm_kernel<64, 64, 0><<<dim3(4, 32), 256, 0, st1>>>(
        F + O_XD, 512, Wu1, 256, F + O_XU, 256, 512, nullptr, nullptr);
    cudaEventRecord(ev6, st1);
    colsum_part_kernel<<<dim3(4, 8), 128>>>(F + O_XD, F + O_GS2);
    beff_kernel<<<1, 256>>>(F + O_GS2, Wu2, su2, bu1, bu2, F + O_BE);
    cudaStreamWaitEvent(0, ev6, 0);
    bias_relu_kernel<<<NDOWN, 256>>>(F + O_XU, su1, F + O_BE);

    // --- h = relu((xu@Wc1)*sc + (bc1*sc+bc)) ---
    gemm_kernel<64, 64, 2><<<dim3(2, 32), 256>>>(
        F + O_XU, 256, Wc1, 128, F + O_H, 128, 256, scv, F + O_B2E);

    // --- out = h@Wc2 + bc2 ---
    final_kernel<<<96, 128>>>(F + O_H, Wc2, bc2, (float*)d_out);
}

// round 11
// speedup vs baseline: 2.4460x; 1.1065x over previous
#include <cuda_runtime.h>
#include <math.h>
#include <float.h>

#define NPTS   8192
#define NDOWN  2048
#define KNN    16
#define CHUNKS 16

// ----------------------------------------------------------------------------
// Scratch arenas (no cudaMalloc allowed).
// ----------------------------------------------------------------------------
__device__ float g_f[40200000];
__device__ int   g_i[2400000];

static const size_t O_A1  = 0;
static const size_t O_B1  = O_A1  + (size_t)8192*64;
static const size_t O_X1  = O_B1  + (size_t)8192*64;
static const size_t O_A2  = O_X1  + (size_t)8192*64;
static const size_t O_B2  = O_A2  + (size_t)8192*128;
static const size_t O_X2  = O_B2  + (size_t)8192*128;
static const size_t O_Q1  = O_X2  + (size_t)8192*128;   // y1 [8192,128]
static const size_t O_K1  = O_Q1  + (size_t)8192*256;   // region reused for M1/M2
static const size_t O_V1  = O_K1  + (size_t)8192*256;
static const size_t O_X3  = O_V1  + (size_t)8192*256;
static const size_t O_Q2  = O_X3  + (size_t)8192*256;   // y2 [8192,256]
static const size_t O_K2  = O_Q2  + (size_t)8192*512;
static const size_t O_V2  = O_K2  + (size_t)8192*512;
static const size_t O_X4  = O_V2  + (size_t)8192*512;
static const size_t O_PX  = O_X4  + (size_t)8192*512;
static const size_t O_TAU = O_PX  + (size_t)8192*512;   // 8192
static const size_t O_XD  = O_TAU + (size_t)2048*512;
static const size_t O_XU  = O_XD  + (size_t)2048*512;
static const size_t O_H   = O_XU  + (size_t)2048*256;
static const size_t O_GS  = O_H   + (size_t)2048*128;   // 512
static const size_t O_BE  = O_GS  + 512;                // 256
static const size_t O_B2E = O_BE  + 256;                // 128
static const size_t O_WD1 = O_B2E + 128;                // 192
static const size_t O_WD2 = O_WD1 + 192;                // 8192
static const size_t O_P4  = O_WD2 + 8192;               // 8192*4
static const size_t O_S1D = O_P4  + (size_t)8192*4;     // 8192*256
static const size_t O_GS2 = O_S1D + (size_t)8192*256;   // 4096

static const size_t O_M1   = O_K1;            // 128*128
static const size_t O_M2   = O_K1 + 65536;    // 256*256

static const size_t OI_IDX  = 0;                          // 8192*16
static const size_t OI_S1I  = (size_t)8192*16;            // 8192*256

// ----------------------------------------------------------------------------
// f32x2 helpers
// ----------------------------------------------------------------------------
typedef unsigned long long ull;

__device__ __forceinline__ ull pk2(float lo, float hi) {
    ull r; asm("mov.b64 %0,{%1,%2};" : "=l"(r) : "f"(lo), "f"(hi)); return r;
}
__device__ __forceinline__ ull fma2(ull a, ull b, ull c) {
    ull d; asm("fma.rn.f32x2 %0,%1,%2,%3;" : "=l"(d) : "l"(a), "l"(b), "l"(c)); return d;
}
__device__ __forceinline__ void upk2(ull v, float& lo, float& hi) {
    asm("mov.b64 {%0,%1},%2;" : "=f"(lo), "=f"(hi) : "l"(v));
}

__device__ __forceinline__ unsigned tf32cvt(float f) {
    unsigned r; asm("cvt.rna.tf32.f32 %0,%1;" : "=r"(r) : "f"(f)); return r;
}

// bank-conflict-free smem swizzle for the tf32 GEMM (see R11 notes):
// compute loads vary k in bits 0-1, staging stores vary k in bits 2-3;
// SWZ permutes {0,8,16,24} under both -> 32 distinct banks on every access.
#define ASWZ(k) ((((k) ^ ((k) >> 2)) & 3) << 3)

// ----------------------------------------------------------------------------
// fused prologue: p4 prep, We diffs, b2eff.  grid 131, block 128.
// ----------------------------------------------------------------------------
__global__ void prologue_kernel(const float* __restrict__ p, float4* __restrict__ p4,
                                const float* __restrict__ We1, float* __restrict__ Wd1,
                                const float* __restrict__ We2, float* __restrict__ Wd2,
                                const float* __restrict__ bc1, const float* __restrict__ scv,
                                const float* __restrict__ bcv, float* __restrict__ b2e) {
    int b = blockIdx.x, t = threadIdx.x;
    if (b < 64) {
        int i = b * 128 + t;
        float x = p[3 * i], y = p[3 * i + 1], z = p[3 * i + 2];
        p4[i] = make_float4(x, y, z, x * x + y * y + z * z);
    } else if (b < 66) {
        int j = (b - 64) * 128 + t;
        if (j < 192) Wd1[j] = We1[j] - We1[192 + j];
    } else if (b < 130) {
        int j = (b - 66) * 128 + t;
        Wd2[j] = We2[j] - We2[8192 + j];
    } else {
        b2e[t] = fmaf(bc1[t], scv[t], bcv[t]);
    }
}

// ----------------------------------------------------------------------------
// M = scale * Wq @ Wk^T  (both [Din, D] row-major).  4 i's x 32 j's per block.
// ----------------------------------------------------------------------------
__global__ void abt_kernel(const float* __restrict__ Wq, const float* __restrict__ Wk,
                           float* __restrict__ M, int Din, int D, float scale) {
    int j = blockIdx.x * 32 + (threadIdx.x & 31);
    int i = blockIdx.y * 4 + (threadIdx.x >> 5);
    const float4* a = (const float4*)(Wq + (size_t)i * D);
    const float4* b = (const float4*)(Wk + (size_t)j * D);
    float s = 0.f;
    int n4 = D >> 2;
    for (int d = 0; d < n4; ++d) {
        float4 x = a[d], y = b[d];
        s = fmaf(x.x, y.x, fmaf(x.y, y.y, fmaf(x.z, y.z, fmaf(x.w, y.w, s))));
    }
    M[(size_t)i * Din + j] = s * scale;
}

// ----------------------------------------------------------------------------
// kNN with conservative precomputed threshold.
// ----------------------------------------------------------------------------
__device__ __forceinline__ void replace_rescan(float s, int j, float (&d)[KNN], int (&id)[KNN],
                                               float& wval, int& wpos) {
#pragma unroll
    for (int t = 0; t < KNN; ++t) if (t == wpos) { d[t] = s; id[t] = j; }
    wval = d[0]; wpos = 0;
#pragma unroll
    for (int t = 1; t < KNN; ++t) if (d[t] > wval) { wval = d[t]; wpos = t; }
}

// tau[q] = 16th-smallest of the 32 lane-mins over 64 strided candidates each.
__global__ void knn_tau_kernel(const float4* __restrict__ p4, float* __restrict__ tau) {
    int q = (blockIdx.x * blockDim.x + threadIdx.x) >> 5;
    int lane = threadIdx.x & 31;
    float4 qp = p4[q];
    float qx = -2.f * qp.x, qy = -2.f * qp.y, qz = -2.f * qp.z;
    float m0 = FLT_MAX, m1 = FLT_MAX;
#pragma unroll 8
    for (int t = 0; t < 64; t += 2) {
        float4 c0 = p4[t * 32 + lane];
        float4 c1 = p4[(t + 1) * 32 + lane];
        float s0 = fmaf(qx, c0.x, fmaf(qy, c0.y, fmaf(qz, c0.z, c0.w)));
        float s1 = fmaf(qx, c1.x, fmaf(qy, c1.y, fmaf(qz, c1.z, c1.w)));
        m0 = fminf(m0, s0);
        m1 = fminf(m1, s1);
    }
    float v = fminf(m0, m1), tv = 0.f;
#pragma unroll
    for (int r = 0; r < KNN; ++r) {
        float mn = v;
#pragma unroll
        for (int o = 16; o; o >>= 1) mn = fminf(mn, __shfl_xor_sync(0xffffffffu, mn, o));
        tv = mn;
        unsigned ball = __ballot_sync(0xffffffffu, v == mn);
        int src = __ffs(ball) - 1;
        if (lane == src) v = FLT_MAX;
    }
    if (lane == 0) tau[q] = tv;
}

// grid (NPTS/128, CHUNKS), block 128. One 512-candidate tile per chunk.
__global__ void knn_stage1_kernel(const float4* __restrict__ p4, const float* __restrict__ taub,
                                  float* __restrict__ s1d, int* __restrict__ s1i) {
    const int CH = NPTS / CHUNKS;  // 512
    int q  = blockIdx.x * blockDim.x + threadIdx.x;
    int c0 = blockIdx.y * CH;

    float4 qp = p4[q];
    float qx = -2.f * qp.x, qy = -2.f * qp.y, qz = -2.f * qp.z;
    float tau = taub[q];

    __shared__ float4 tile[512];
#pragma unroll
    for (int l = 0; l < 4; ++l) tile[threadIdx.x + l * 128] = p4[c0 + threadIdx.x + l * 128];
    __syncthreads();

    float d[KNN]; int id[KNN];
#pragma unroll
    for (int t = 0; t < KNN; ++t) { d[t] = FLT_MAX; id[t] = 0; }
    float wval = FLT_MAX; int wpos = 0;

#pragma unroll 4
    for (int i = 0; i < CH; ++i) {
        float4 c = tile[i];
        float s = fmaf(qx, c.x, fmaf(qy, c.y, fmaf(qz, c.z, c.w)));
        if (s <= tau && s < wval) {
            replace_rescan(s, c0 + i, d, id, wval, wpos);
        }
    }

    size_t o = ((size_t)q * CHUNKS + blockIdx.y) * KNN;
#pragma unroll
    for (int t = 0; t < KNN; ++t) { s1d[o + t] = d[t]; s1i[o + t] = id[t]; }
}

__global__ void knn_stage2_kernel(const float* __restrict__ s1d, const int* __restrict__ s1i,
                                  int* __restrict__ outidx) {
    int q = blockIdx.x * blockDim.x + threadIdx.x;
    size_t base = (size_t)q * (CHUNKS * KNN);
    float d[KNN]; int id[KNN];
#pragma unroll
    for (int t = 0; t < KNN; ++t) { d[t] = s1d[base + t]; id[t] = s1i[base + t]; }
    float wval = d[0]; int wpos = 0;
#pragma unroll
    for (int t = 1; t < KNN; ++t) if (d[t] > wval) { wval = d[t]; wpos = t; }
    for (int c = KNN; c < CHUNKS * KNN; ++c) {
        float s = s1d[base + c];
        if (s < wval) replace_rescan(s, s1i[base + c], d, id, wval, wpos);
    }
#pragma unroll
    for (int t = 0; t < KNN; ++t) outidx[q * KNN + t] = id[t];
}

// ----------------------------------------------------------------------------
// Tensor-core GEMM (tf32 mma.sync.m16n8k8): C[M,N] = A[M,K] @ B[K,N].
// Conflict-free XOR-swizzled smem (SP=128).
// MODE 0: store. MODE 3: acc + p@W3 rows (row ld = ldc).
// ----------------------------------------------------------------------------
#define SP 128

template <int MODE>
__global__ __launch_bounds__(256, 2)
void mma_gemm_kernel(const float* __restrict__ A, int lda,
                     const float* __restrict__ Bp0, const float* __restrict__ Bp1,
                     const float* __restrict__ Bp2, int ldb,
                     float* __restrict__ Cp0, float* __restrict__ Cp1,
                     float* __restrict__ Cp2, int ldc, int K,
                     const float4* __restrict__ p4r, int rstride,
                     const float* __restrict__ W3) {
    __shared__ __align__(16) unsigned As[2][16][SP];
    __shared__ __align__(16) unsigned Bs[2][16][SP];

    const float* B = (blockIdx.z == 0) ? Bp0 : (blockIdx.z == 1) ? Bp1 : Bp2;
    float*       C = (blockIdx.z == 0) ? Cp0 : (blockIdx.z == 1) ? Cp1 : Cp2;

    int tid = threadIdx.x;
    int bm = blockIdx.y * 128, bn = blockIdx.x * 128;

    int ar = tid >> 2, ac4 = tid & 3;
    int bk = tid >> 5, bc = tid & 31;
    const float* Ap = A + (size_t)(bm + ar) * lda + ac4 * 4;
    const float* Bq = B + (size_t)bk * ldb + bn + bc * 4;

    // per-thread store swizzles (constant across tiles)
    int sa0 = ASWZ(ac4 * 4 + 0), sa1w = ASWZ(ac4 * 4 + 1);
    int sa2 = ASWZ(ac4 * 4 + 2), sa3 = ASWZ(ac4 * 4 + 3);
    int sb0 = ASWZ(bk), sb1 = ASWZ(bk + 8);

    float4 pa0, pa1, pb0, pb1;
    pa0 = *(const float4*)Ap;
    pa1 = *(const float4*)(Ap + (size_t)64 * lda);
    pb0 = *(const float4*)Bq;
    pb1 = *(const float4*)(Bq + (size_t)8 * ldb);
    Ap += 16;
    Bq += (size_t)16 * ldb;

    {
        As[0][ac4 * 4 + 0][ar ^ sa0] = tf32cvt(pa0.x);
        As[0][ac4 * 4 + 1][ar ^ sa1w] = tf32cvt(pa0.y);
        As[0][ac4 * 4 + 2][ar ^ sa2] = tf32cvt(pa0.z);
        As[0][ac4 * 4 + 3][ar ^ sa3] = tf32cvt(pa0.w);
        As[0][ac4 * 4 + 0][(ar + 64) ^ sa0] = tf32cvt(pa1.x);
        As[0][ac4 * 4 + 1][(ar + 64) ^ sa1w] = tf32cvt(pa1.y);
        As[0][ac4 * 4 + 2][(ar + 64) ^ sa2] = tf32cvt(pa1.z);
        As[0][ac4 * 4 + 3][(ar + 64) ^ sa3] = tf32cvt(pa1.w);
        uint4 t0 = make_uint4(tf32cvt(pb0.x), tf32cvt(pb0.y), tf32cvt(pb0.z), tf32cvt(pb0.w));
        uint4 t1 = make_uint4(tf32cvt(pb1.x), tf32cvt(pb1.y), tf32cvt(pb1.z), tf32cvt(pb1.w));
        *(uint4*)&Bs[0][bk][(bc * 4) ^ sb0] = t0;
        *(uint4*)&Bs[0][bk + 8][(bc * 4) ^ sb1] = t1;
    }
    __syncthreads();

    int lane = tid & 31, wid = tid >> 5;
    int wm = (wid & 1) * 64;
    int wn = (wid >> 1) * 32;
    int grp = lane >> 2, qid = lane & 3;

    float acc[4][4][4];
#pragma unroll
    for (int tm = 0; tm < 4; ++tm)
#pragma unroll
        for (int tn = 0; tn < 4; ++tn)
#pragma unroll
            for (int c = 0; c < 4; ++c) acc[tm][tn][c] = 0.f;

    int ktiles = K >> 4;
    for (int t = 0; t < ktiles; ++t) {
        bool more = (t + 1 < ktiles);
        if (more) {
            pa0 = *(const float4*)Ap;
            pa1 = *(const float4*)(Ap + (size_t)64 * lda);
            pb0 = *(const float4*)Bq;
            pb1 = *(const float4*)(Bq + (size_t)8 * ldb);
            Ap += 16;
            Bq += (size_t)16 * ldb;
        }

        int cb = t & 1;
#pragma unroll
        for (int kh = 0; kh < 2; ++kh) {
            int k0 = kh * 8;
            int kq = k0 + qid, kq4 = k0 + qid + 4;
            int swa = ASWZ(kq), swb = ASWZ(kq4);
            unsigned af[4][4], bf[4][2];
#pragma unroll
            for (int tm = 0; tm < 4; ++tm) {
                int m0 = wm + tm * 16 + grp;
                af[tm][0] = As[cb][kq][m0 ^ swa];
                af[tm][1] = As[cb][kq][(m0 + 8) ^ swa];
                af[tm][2] = As[cb][kq4][m0 ^ swb];
                af[tm][3] = As[cb][kq4][(m0 + 8) ^ swb];
            }
#pragma unroll
            for (int tn = 0; tn < 4; ++tn) {
                int n0 = wn + tn * 8 + grp;
                bf[tn][0] = Bs[cb][kq][n0 ^ swa];
                bf[tn][1] = Bs[cb][kq4][n0 ^ swb];
            }
#pragma unroll
            for (int tm = 0; tm < 4; ++tm)
#pragma unroll
                for (int tn = 0; tn < 4; ++tn) {
                    asm volatile(
                        "mma.sync.aligned.m16n8k8.row.col.f32.tf32.tf32.f32 "
                        "{%0,%1,%2,%3},{%4,%5,%6,%7},{%8,%9},{%0,%1,%2,%3};"
                        : "+f"(acc[tm][tn][0]), "+f"(acc[tm][tn][1]),
                          "+f"(acc[tm][tn][2]), "+f"(acc[tm][tn][3])
                        : "r"(af[tm][0]), "r"(af[tm][1]), "r"(af[tm][2]), "r"(af[tm][3]),
                          "r"(bf[tn][0]), "r"(bf[tn][1]));
                }
        }

        if (more) {
            int nb = (t + 1) & 1;
            As[nb][ac4 * 4 + 0][ar ^ sa0] = tf32cvt(pa0.x);
            As[nb][ac4 * 4 + 1][ar ^ sa1w] = tf32cvt(pa0.y);
            As[nb][ac4 * 4 + 2][ar ^ sa2] = tf32cvt(pa0.z);
            As[nb][ac4 * 4 + 3][ar ^ sa3] = tf32cvt(pa0.w);
            As[nb][ac4 * 4 + 0][(ar + 64) ^ sa0] = tf32cvt(pa1.x);
            As[nb][ac4 * 4 + 1][(ar + 64) ^ sa1w] = tf32cvt(pa1.y);
            As[nb][ac4 * 4 + 2][(ar + 64) ^ sa2] = tf32cvt(pa1.z);
            As[nb][ac4 * 4 + 3][(ar + 64) ^ sa3] = tf32cvt(pa1.w);
            uint4 t0 = make_uint4(tf32cvt(pb0.x), tf32cvt(pb0.y), tf32cvt(pb0.z), tf32cvt(pb0.w));
            uint4 t1 = make_uint4(tf32cvt(pb1.x), tf32cvt(pb1.y), tf32cvt(pb1.z), tf32cvt(pb1.w));
            *(uint4*)&Bs[nb][bk][(bc * 4) ^ sb0] = t0;
            *(uint4*)&Bs[nb][bk + 8][(bc * 4) ^ sb1] = t1;
        }
        __syncthreads();
    }

#pragma unroll
    for (int tm = 0; tm < 4; ++tm) {
        int r0 = bm + wm + tm * 16 + grp;
        int r1 = r0 + 8;
        float4 p0, p1;
        if (MODE == 3) {
            p0 = p4r[(size_t)r0 * rstride];
            p1 = p4r[(size_t)r1 * rstride];
        }
#pragma unroll
        for (int tn = 0; tn < 4; ++tn) {
            int col = bn + wn + tn * 8 + 2 * qid;
            float c0 = acc[tm][tn][0], c1 = acc[tm][tn][1];
            float c2 = acc[tm][tn][2], c3 = acc[tm][tn][3];
            if (MODE == 3) {
                float wa0 = W3[col],           wa1 = W3[col + 1];
                float wb0 = W3[ldc + col],     wb1 = W3[ldc + col + 1];
                float wc0 = W3[2 * ldc + col], wc1 = W3[2 * ldc + col + 1];
                c0 += fmaf(p0.x, wa0, fmaf(p0.y, wb0, p0.z * wc0));
                c1 += fmaf(p0.x, wa1, fmaf(p0.y, wb1, p0.z * wc1));
                c2 += fmaf(p1.x, wa0, fmaf(p1.y, wb0, p1.z * wc0));
                c3 += fmaf(p1.x, wa1, fmaf(p1.y, wb1, p1.z * wc1));
            }
            *(float2*)&C[(size_t)r0 * ldc + col] = make_float2(c0, c1);
            *(float2*)&C[(size_t)r1 * ldc + col] = make_float2(c2, c3);
        }
    }
}

// ----------------------------------------------------------------------------
// f32x2 GEMM, 64x64 tiles.  MODE 0: store.  MODE 2: relu(acc*s+b).
// ----------------------------------------------------------------------------
template <int BM, int BN, int MODE>
__global__ __launch_bounds__(256, 2)
void gemm_kernel(const float* __restrict__ A, int lda,
                 const float* __restrict__ Bp0, int ldb,
                 float* __restrict__ Cp0, int ldc, int K,
                 const float* __restrict__ scv, const float* __restrict__ biv) {
    constexpr int TM = BM / 16;
    constexpr int TN = BN / 16;
    constexpr int RP = TM / 2;
    constexpr int NA = BM / 64;
    constexpr int NB = BN / 64;
    constexpr int F4R = BN / 4;
    constexpr int BROW = 256 / F4R;

    __shared__ __align__(16) float As[2][16][BM + 4];
    __shared__ __align__(16) float Bs[2][16][BN];

    const float* B = Bp0;
    float*       C = Cp0;

    int tid = threadIdx.x;
    int bm = blockIdx.y * BM, bn = blockIdx.x * BN;

    int ar = tid >> 2, ac4 = tid & 3;
    int bk = tid / F4R, bc = tid % F4R;

    const float* Ap = A + (size_t)(bm + ar) * lda + ac4 * 4;
    const float* Bq = B + (size_t)bk * ldb + bn + bc * 4;

    float4 pa[NA], pb[NB];
#pragma unroll
    for (int l = 0; l < NA; ++l) pa[l] = *(const float4*)(Ap + (size_t)(64 * l) * lda);
#pragma unroll
    for (int l = 0; l < NB; ++l) pb[l] = *(const float4*)(Bq + (size_t)(BROW * l) * ldb);
    Ap += 16;
    Bq += (size_t)16 * ldb;

#pragma unroll
    for (int l = 0; l < NA; ++l) {
        int r = ar + 64 * l;
        As[0][ac4 * 4 + 0][r] = pa[l].x;
        As[0][ac4 * 4 + 1][r] = pa[l].y;
        As[0][ac4 * 4 + 2][r] = pa[l].z;
        As[0][ac4 * 4 + 3][r] = pa[l].w;
    }
#pragma unroll
    for (int l = 0; l < NB; ++l)
        *(float4*)&Bs[0][bk + BROW * l][bc * 4] = pb[l];
    __syncthreads();

    int tr = (tid >> 4) * TM;
    int tc = (tid & 15) * TN;

    ull acc[RP][TN];
#pragma unroll
    for (int rp = 0; rp < RP; ++rp)
#pragma unroll
        for (int c = 0; c < TN; ++c) acc[rp][c] = 0ull;

    int ktiles = K >> 4;
    for (int t = 0; t < ktiles; ++t) {
        bool more = (t + 1 < ktiles);
        if (more) {
#pragma unroll
            for (int l = 0; l < NA; ++l) pa[l] = *(const float4*)(Ap + (size_t)(64 * l) * lda);
#pragma unroll
            for (int l = 0; l < NB; ++l) pb[l] = *(const float4*)(Bq + (size_t)(BROW * l) * ldb);
            Ap += 16;
            Bq += (size_t)16 * ldb;
        }

        int cb = t & 1;
#pragma unroll
        for (int k = 0; k < 16; ++k) {
            float4 av[TM / 4], bv[TN / 4];
#pragma unroll
            for (int v = 0; v < TM / 4; ++v) av[v] = *(const float4*)&As[cb][k][tr + 4 * v];
#pragma unroll
            for (int v = 0; v < TN / 4; ++v) bv[v] = *(const float4*)&Bs[cb][k][tc + 4 * v];
            ull apk[RP];
#pragma unroll
            for (int v = 0; v < TM / 4; ++v) {
                apk[2 * v + 0] = pk2(av[v].x, av[v].y);
                apk[2 * v + 1] = pk2(av[v].z, av[v].w);
            }
#pragma unroll
            for (int v = 0; v < TN / 4; ++v) {
                {
                    ull bb = pk2(bv[v].x, bv[v].x);
#pragma unroll
                    for (int rp = 0; rp < RP; ++rp) acc[rp][4 * v + 0] = fma2(apk[rp], bb, acc[rp][4 * v + 0]);
                }
                {
                    ull bb = pk2(bv[v].y, bv[v].y);
#pragma unroll
                    for (int rp = 0; rp < RP; ++rp) acc[rp][4 * v + 1] = fma2(apk[rp], bb, acc[rp][4 * v + 1]);
                }
                {
                    ull bb = pk2(bv[v].z, bv[v].z);
#pragma unroll
                    for (int rp = 0; rp < RP; ++rp) acc[rp][4 * v + 2] = fma2(apk[rp], bb, acc[rp][4 * v + 2]);
                }
                {
                    ull bb = pk2(bv[v].w, bv[v].w);
#pragma unroll
                    for (int rp = 0; rp < RP; ++rp) acc[rp][4 * v + 3] = fma2(apk[rp], bb, acc[rp][4 * v + 3]);
                }
            }
        }

        if (more) {
            int nb = (t + 1) & 1;
#pragma unroll
            for (int l = 0; l < NA; ++l) {
                int r = ar + 64 * l;
                As[nb][ac4 * 4 + 0][r] = pa[l].x;
                As[nb][ac4 * 4 + 1][r] = pa[l].y;
                As[nb][ac4 * 4 + 2][r] = pa[l].z;
                As[nb][ac4 * 4 + 3][r] = pa[l].w;
            }
#pragma unroll
            for (int l = 0; l < NB; ++l)
                *(float4*)&Bs[nb][bk + BROW * l][bc * 4] = pb[l];
        }
        __syncthreads();
    }

    float sc8[TN], bi8[TN];
    if (MODE == 2) {
#pragma unroll
        for (int c = 0; c < TN; ++c) { sc8[c] = scv[bn + tc + c]; bi8[c] = biv[bn + tc + c]; }
    }
#pragma unroll
    for (int rp = 0; rp < RP; ++rp) {
        int r0 = bm + tr + 2 * rp, r1 = r0 + 1;
        float o0[TN], o1[TN];
#pragma unroll
        for (int c = 0; c < TN; ++c) upk2(acc[rp][c], o0[c], o1[c]);
        if (MODE == 2) {
#pragma unroll
            for (int c = 0; c < TN; ++c) {
                o0[c] = fmaxf(fmaf(o0[c], sc8[c], bi8[c]), 0.f);
                o1[c] = fmaxf(fmaf(o1[c], sc8[c], bi8[c]), 0.f);
            }
        }
#pragma unroll
        for (int v = 0; v < TN / 4; ++v) {
            *(float4*)&C[(size_t)r0 * ldc + bn + tc + 4 * v] =
                make_float4(o0[4 * v], o0[4 * v + 1], o0[4 * v + 2], o0[4 * v + 3]);
            *(float4*)&C[(size_t)r1 * ldc + bn + tc + 4 * v] =
                make_float4(o1[4 * v], o1[4 * v + 1], o1[4 * v + 2], o1[4 * v + 3]);
        }
    }
}

// ----------------------------------------------------------------------------
// edge_conv1 fused (K=3, C=64). 4 points/block, 256 threads.
// ----------------------------------------------------------------------------
__global__ void edge1_kernel(const float4* __restrict__ p4,
                             const float* __restrict__ Wd, const float* __restrict__ Wb,
                             const int* __restrict__ idx,
                             const float* __restrict__ s, const float* __restrict__ b,
                             float* __restrict__ out) {
    __shared__ float4 pj[4][KNN];
    int g = threadIdx.x >> 6, c = threadIdx.x & 63;
    int i = blockIdx.x * 4 + g;
    if (c < KNN) pj[g][c] = p4[idx[i * KNN + c]];
    __syncthreads();
    float4 pi = p4[i];
    float w0 = Wd[c], w1 = Wd[64 + c], w2 = Wd[128 + c];
    float u0 = Wb[c], u1 = Wb[64 + c], u2 = Wb[128 + c];
    float a = fmaf(pi.x, w0, fmaf(pi.y, w1, pi.z * w2));
    float sc = s[c], bv = b[c];
    float m = 0.f;
#pragma unroll
    for (int k = 0; k < KNN; ++k) {
        float4 pp = pj[g][k];
        float e = fmaf(pp.x, u0, fmaf(pp.y, u1, fmaf(pp.z, u2, a)));
        m = fmaxf(m, fmaf(e, sc, bv));
    }
    out[(size_t)i * 64 + c] = m;
}

// ----------------------------------------------------------------------------
// edge_conv2 gather-max (C=128, float4): 4 points/block, 128 threads.
// ----------------------------------------------------------------------------
__global__ void gathermax_kernel(const float4* __restrict__ Aa, const float4* __restrict__ Bb,
                                 const int* __restrict__ idx,
                                 const float4* __restrict__ s, const float4* __restrict__ b,
                                 float4* __restrict__ out) {
    const int C4 = 32;
    __shared__ int js[4][KNN];
    int g = threadIdx.x >> 5, c = threadIdx.x & 31;
    int i = blockIdx.x * 4 + g;
    if (c < KNN) js[g][c] = idx[i * KNN + c];
    __syncthreads();
    float4 a = Aa[(size_t)i * C4 + c];
    float4 sc = s[c], bv = b[c];
    float4 m = make_float4(0.f, 0.f, 0.f, 0.f);
#pragma unroll
    for (int k = 0; k < KNN; ++k) {
        float4 bj = Bb[(size_t)js[g][k] * C4 + c];
        m.x = fmaxf(m.x, fmaf(a.x + bj.x, sc.x, bv.x));
        m.y = fmaxf(m.y, fmaf(a.y + bj.y, sc.y, bv.y));
        m.z = fmaxf(m.z, fmaf(a.z + bj.z, sc.z, bv.z));
        m.w = fmaxf(m.w, fmaf(a.w + bj.w, sc.w, bv.w));
    }
    out[(size_t)i * C4 + c] = m;
}

// ----------------------------------------------------------------------------
// graph attention with precomputed y = x @ (scale * Wq Wk^T)
// ----------------------------------------------------------------------------
template <int DIN, int D, int NP>
__global__ void attn_kernel(const float4* __restrict__ y, const float4* __restrict__ xin,
                            const float4* __restrict__ v, const int* __restrict__ idx,
                            const float4* __restrict__ s, const float4* __restrict__ b,
                            float4* __restrict__ out) {
    constexpr int D4 = D / 4, DIN4 = DIN / 4;
    int tid = threadIdx.x;
    int g = tid / D4, t = tid % D4;
    int i = blockIdx.x * NP + g;
    __shared__ float4 qs[NP][DIN4];
    __shared__ float lg[NP][KNN];
    __shared__ float aw[NP][KNN];
    __shared__ int js[NP][KNN];
    if (t < DIN4) qs[g][t] = y[(size_t)i * DIN4 + t];
    if (t < KNN) js[g][t] = idx[i * KNN + t];
    __syncthreads();

    constexpr int NW = D4 / 32;
    int w = t >> 5, lane = t & 31;
    for (int k = w; k < 8; k += NW) {
        const float4* k0 = xin + (size_t)js[g][k] * DIN4;
        const float4* k1 = xin + (size_t)js[g][k + 8] * DIN4;
        float s0 = 0.f, s1 = 0.f;
#pragma unroll
        for (int m = lane; m < DIN4; m += 32) {
            float4 a = qs[g][m];
            float4 c0 = k0[m], c1 = k1[m];
            s0 = fmaf(a.x, c0.x, fmaf(a.y, c0.y, fmaf(a.z, c0.z, fmaf(a.w, c0.w, s0))));
            s1 = fmaf(a.x, c1.x, fmaf(a.y, c1.y, fmaf(a.z, c1.z, fmaf(a.w, c1.w, s1))));
        }
#pragma unroll
        for (int o = 16; o; o >>= 1) {
            s0 += __shfl_xor_sync(0xffffffffu, s0, o);
            s1 += __shfl_xor_sync(0xffffffffu, s1, o);
        }
        if (lane == 0) {
            lg[g][k] = s0;
            lg[g][k + 8] = s1;
        }
    }
    __syncthreads();
    if (t < 32) {
        float l = (lane < KNN) ? lg[g][lane] : -FLT_MAX;
        float mx = l;
#pragma unroll
        for (int o = 16; o; o >>= 1) mx = fmaxf(mx, __shfl_xor_sync(0xffffffffu, mx, o));
        float e = (lane < KNN) ? expf(l - mx) : 0.f;
        float se = e;
#pragma unroll
        for (int o = 16; o; o >>= 1) se += __shfl_xor_sync(0xffffffffu, se, o);
        if (lane < KNN) aw[g][lane] = e / se;
    }
    __syncthreads();
    float4 yy = make_float4(0.f, 0.f, 0.f, 0.f);
#pragma unroll
    for (int k = 0; k < KNN; ++k) {
        float a = aw[g][k];
        float4 vv = v[(size_t)js[g][k] * D4 + t];
        yy.x = fmaf(a, vv.x, yy.x); yy.y = fmaf(a, vv.y, yy.y);
        yy.z = fmaf(a, vv.z, yy.z); yy.w = fmaf(a, vv.w, yy.w);
    }
    float4 sc = s[t], bv = b[t];
    float4 r;
    r.x = fmaxf(fmaf(yy.x, sc.x, bv.x), 0.f);
    r.y = fmaxf(fmaf(yy.y, sc.y, bv.y), 0.f);
    r.z = fmaxf(fmaf(yy.z, sc.z, bv.z), 0.f);
    r.w = fmaxf(fmaf(yy.w, sc.w, bv.w), 0.f);
    out[(size_t)i * D4 + t] = r;
}

// ----------------------------------------------------------------------------
// downsample gather-max with fused pm = p@W3 (float4): 2 pts/block, 256 thr.
// ----------------------------------------------------------------------------
__global__ void downgather_kernel(const float4* __restrict__ PX, const float4* __restrict__ p4,
                                  const float* __restrict__ W3, const int* __restrict__ idx,
                                  const float4* __restrict__ s, const float4* __restrict__ b,
                                  float4* __restrict__ out) {
    __shared__ int js[2][KNN];
    int g = threadIdx.x >> 7, c = threadIdx.x & 127;
    int i = blockIdx.x * 2 + g;
    if (c < KNN) js[g][c] = idx[(4 * i) * KNN + c];
    __syncthreads();
    float4 p = p4[4 * i];
    float4 wa = *(const float4*)&W3[4 * c];
    float4 wb = *(const float4*)&W3[512 + 4 * c];
    float4 wc = *(const float4*)&W3[1024 + 4 * c];
    float4 pm;
    pm.x = fmaf(p.x, wa.x, fmaf(p.y, wb.x, p.z * wc.x));
    pm.y = fmaf(p.x, wa.y, fmaf(p.y, wb.y, p.z * wc.y));
    pm.z = fmaf(p.x, wa.z, fmaf(p.y, wb.z, p.z * wc.z));
    pm.w = fmaf(p.x, wa.w, fmaf(p.y, wb.w, p.z * wc.w));
    float4 sc = s[c], bv = b[c];
    float4 m = make_float4(0.f, 0.f, 0.f, 0.f);
#pragma unroll
    for (int k = 0; k < KNN; ++k) {
        float4 px = PX[(size_t)js[g][k] * 128 + c];
        m.x = fmaxf(m.x, fmaf(px.x - pm.x, sc.x, bv.x));
        m.y = fmaxf(m.y, fmaf(px.y - pm.y, sc.y, bv.y));
        m.z = fmaxf(m.z, fmaf(px.z - pm.z, sc.z, bv.z));
        m.w = fmaxf(m.w, fmaf(px.w - pm.w, sc.w, bv.w));
    }
    out[(size_t)i * 128 + c] = m;
}

__global__ void colsum_part_kernel(const float* __restrict__ xd, float* __restrict__ gs2) {
    int c = blockIdx.x * blockDim.x + threadIdx.x;
    int g = blockIdx.y;
    float s = 0.f;
    for (int r = g * 256; r < (g + 1) * 256; ++r) s += xd[(size_t)r * 512 + c];
    gs2[g * 512 + c] = s;
}

__global__ void beff_kernel(const float* __restrict__ gs2, const float* __restrict__ Wu2,
                            const float* __restrict__ su2, const float* __restrict__ bu1,
                            const float* __restrict__ bu2, float* __restrict__ be) {
    __shared__ float gsum[512];
    int tid = threadIdx.x;
    for (int c = tid; c < 512; c += 256) {
        float s = 0.f;
#pragma unroll
        for (int g = 0; g < 8; ++g) s += gs2[g * 512 + c];
        gsum[c] = s;
    }
    __syncthreads();
    float acc = 0.f;
    for (int d = 0; d < 512; ++d) acc = fmaf(gsum[d], Wu2[(size_t)d * 256 + tid], acc);
    be[tid] = bu1[tid] + bu2[tid] + su2[tid] * (acc * (1.f / 2048.f));
}

__global__ void bias_relu_kernel(float* __restrict__ x, const float* __restrict__ s,
                                 const float* __restrict__ b) {
    int t = blockIdx.x * 256 + threadIdx.x;
    int c = t & 255;
    x[t] = fmaxf(fmaf(x[t], s[c], b[c]), 0.f);
}

__global__ void final_kernel(const float* __restrict__ h, const float* __restrict__ Wc2,
                             const float* __restrict__ bc2, float* __restrict__ out) {
    int t = blockIdx.x * blockDim.x + threadIdx.x;
    if (t >= NDOWN * 6) return;
    int i = t / 6, c = t % 6;
    float acc = bc2[c];
    for (int d = 0; d < 128; ++d) acc = fmaf(h[(size_t)i * 128 + d], Wc2[d * 6 + c], acc);
    out[t] = acc;
}

// ----------------------------------------------------------------------------
// launch (stream-parallel graph capture with event fork/join)
// ----------------------------------------------------------------------------
extern "C" void kernel_launch(void* const* d_in, const int* in_sizes, int n_in,
                              void* d_out, int out_size) {
    const float* points = (const float*)d_in[0];
    const float* We1 = (const float*)d_in[1];
    const float* se1 = (const float*)d_in[2];
    const float* be1 = (const float*)d_in[3];
    const float* We2 = (const float*)d_in[4];
    const float* se2 = (const float*)d_in[5];
    const float* be2 = (const float*)d_in[6];
    const float* Wq1 = (const float*)d_in[7];
    const float* Wk1 = (const float*)d_in[8];
    const float* Wv1 = (const float*)d_in[9];
    const float* sa1 = (const float*)d_in[10];
    const float* ba1 = (const float*)d_in[11];
    const float* Wq2 = (const float*)d_in[12];
    const float* Wk2 = (const float*)d_in[13];
    const float* Wv2 = (const float*)d_in[14];
    const float* sa2 = (const float*)d_in[15];
    const float* ba2 = (const float*)d_in[16];
    const float* Wtd = (const float*)d_in[17];
    const float* sd  = (const float*)d_in[18];
    const float* bd  = (const float*)d_in[19];
    const float* Wu1 = (const float*)d_in[20];
    const float* su1 = (const float*)d_in[21];
    const float* bu1 = (const float*)d_in[22];
    const float* Wu2 = (const float*)d_in[23];
    const float* su2 = (const float*)d_in[24];
    const float* bu2 = (const float*)d_in[25];
    const float* Wc1 = (const float*)d_in[26];
    const float* bc1 = (const float*)d_in[27];
    const float* scv = (const float*)d_in[28];
    const float* bcv = (const float*)d_in[29];
    const float* Wc2 = (const float*)d_in[30];
    const float* bc2 = (const float*)d_in[31];

    float* F = nullptr;
    int*   I = nullptr;
    cudaGetSymbolAddress((void**)&F, g_f);
    cudaGetSymbolAddress((void**)&I, g_i);

    float4* p4  = (float4*)(F + O_P4);
    float*  s1d = F + O_S1D;
    int*    s1i = I + OI_S1I;
    int*    idx = I + OI_IDX;

    // side stream + events (created per call; capture-safe)
    cudaStream_t st1;
    cudaStreamCreateWithFlags(&st1, cudaStreamNonBlocking);
    cudaEvent_t ev0, ev1, ev2, ev3, ev4, ev5, ev6;
    cudaEventCreateWithFlags(&ev0, cudaEventDisableTiming);
    cudaEventCreateWithFlags(&ev1, cudaEventDisableTiming);
    cudaEventCreateWithFlags(&ev2, cudaEventDisableTiming);
    cudaEventCreateWithFlags(&ev3, cudaEventDisableTiming);
    cudaEventCreateWithFlags(&ev4, cudaEventDisableTiming);
    cudaEventCreateWithFlags(&ev5, cudaEventDisableTiming);
    cudaEventCreateWithFlags(&ev6, cudaEventDisableTiming);

    // --- fused prologue ---
    prologue_kernel<<<131, 128>>>(points, p4, We1, F + O_WD1, We2, F + O_WD2,
                                  bc1, scv, bcv, F + O_B2E);

    // --- fork: M1/M2 precompute on st1, kNN on main ---
    cudaEventRecord(ev0, 0);
    cudaStreamWaitEvent(st1, ev0, 0);
    abt_kernel<<<dim3(4, 32), 128, 0, st1>>>(Wq1, Wk1, F + O_M1, 128, 256, 1.f / sqrtf(256.f));
    abt_kernel<<<dim3(8, 64), 128, 0, st1>>>(Wq2, Wk2, F + O_M2, 256, 512, 1.f / sqrtf(512.f));

    // kNN: conservative threshold, then sparse chunked scan, then merge
    knn_tau_kernel<<<2048, 128>>>(p4, F + O_TAU);
    knn_stage1_kernel<<<dim3(NPTS / 128, CHUNKS), 128>>>(p4, F + O_TAU, s1d, s1i);
    knn_stage2_kernel<<<NPTS / 128, 128>>>(s1d, s1i, idx);

    // --- edge_conv 1 ---
    edge1_kernel<<<NPTS / 4, 256>>>(p4, F + O_WD1, We1 + 192, idx, se1, be1, F + O_X1);

    // --- edge_conv 2 (tf32, batched halves) ---
    mma_gemm_kernel<0><<<dim3(1, 64, 2), 256>>>(
        F + O_X1, 64, F + O_WD2, We2 + 8192, nullptr, 128,
        F + O_A2, F + O_B2, nullptr, 128, 64, nullptr, 0, nullptr);
    gathermax_kernel<<<NPTS / 4, 128>>>((const float4*)(F + O_A2), (const float4*)(F + O_B2), idx,
                                        (const float4*)se2, (const float4*)be2,
                                        (float4*)(F + O_X2));

    // --- attn1: y1 on st1 (needs M1 - in st1 order), v1 on main, join ---
    cudaEventRecord(ev1, 0);
    cudaStreamWaitEvent(st1, ev1, 0);
    mma_gemm_kernel<0><<<dim3(1, 64, 1), 256, 0, st1>>>(
        F + O_X2, 128, F + O_M1, nullptr, nullptr, 128,
        F + O_Q1, nullptr, nullptr, 128, 128, nullptr, 0, nullptr);
    cudaEventRecord(ev2, st1);
    mma_gemm_kernel<0><<<dim3(2, 64, 1), 256>>>(
        F + O_X2, 128, Wv1, nullptr, nullptr, 256,
        F + O_V1, nullptr, nullptr, 256, 128, nullptr, 0, nullptr);
    cudaStreamWaitEvent(0, ev2, 0);
    attn_kernel<128, 256, 4><<<NPTS / 4, 256>>>(
        (const float4*)(F + O_Q1), (const float4*)(F + O_X2), (const float4*)(F + O_V1), idx,
        (const float4*)sa1, (const float4*)ba1, (float4*)(F + O_X3));

    // --- attn2: y2 on st1, v2 on main, join ---
    cudaEventRecord(ev3, 0);
    cudaStreamWaitEvent(st1, ev3, 0);
    mma_gemm_kernel<0><<<dim3(2, 64, 1), 256, 0, st1>>>(
        F + O_X3, 256, F + O_M2, nullptr, nullptr, 256,
        F + O_Q2, nullptr, nullptr, 256, 256, nullptr, 0, nullptr);
    cudaEventRecord(ev4, st1);
    mma_gemm_kernel<0><<<dim3(4, 64, 1), 256>>>(
        F + O_X3, 256, Wv2, nullptr, nullptr, 512,
        F + O_V2, nullptr, nullptr, 512, 256, nullptr, 0, nullptr);
    cudaStreamWaitEvent(0, ev4, 0);
    attn_kernel<256, 512, 2><<<NPTS / 2, 256>>>(
        (const float4*)(F + O_Q2), (const float4*)(F + O_X3), (const float4*)(F + O_V2), idx,
        (const float4*)sa2, (const float4*)ba2, (float4*)(F + O_X4));

    // --- downsample: PX = x4@Wtd[3:] + p@Wtd[0:3]; gather-max with fused pm ---
    mma_gemm_kernel<3><<<dim3(4, 64, 1), 256>>>(
        F + O_X4, 512, Wtd + 3 * 512, nullptr, nullptr, 512,
        F + O_PX, nullptr, nullptr, 512, 512, p4, 1, Wtd);
    downgather_kernel<<<NDOWN / 2, 256>>>((const float4*)(F + O_PX), p4, Wtd, idx,
                                          (const float4*)sd, (const float4*)bd,
                                          (float4*)(F + O_XD));

    // --- fork: Wu1 raw gemm on st1 || colsum+beff on main; join; bias_relu ---
    cudaEventRecord(ev5, 0);
    cudaStreamWaitEvent(st1, ev5, 0);
    gemm_kernel<64, 64, 0><<<dim3(4, 32), 256, 0, st1>>>(
        F + O_XD, 512, Wu1, 256, F + O_XU, 256, 512, nullptr, nullptr);
    cudaEventRecord(ev6, st1);
    colsum_part_kernel<<<dim3(4, 8), 128>>>(F + O_XD, F + O_GS2);
    beff_kernel<<<1, 256>>>(F + O_GS2, Wu2, su2, bu1, bu2, F + O_BE);
    cudaStreamWaitEvent(0, ev6, 0);
    bias_relu_kernel<<<NDOWN, 256>>>(F + O_XU, su1, F + O_BE);

    // --- h = relu((xu@Wc1)*sc + (bc1*sc+bc)) ---
    gemm_kernel<64, 64, 2><<<dim3(2, 32), 256>>>(
        F + O_XU, 256, Wc1, 128, F + O_H, 128, 256, scv, F + O_B2E);

    // --- out = h@Wc2 + bc2 ---
    final_kernel<<<96, 128>>>(F + O_H, Wc2, bc2, (float*)d_out);
}